// round 2
// baseline (speedup 1.0000x reference)
#include <cuda_runtime.h>
#include <cstdint>
#include <cstddef>

// Problem constants (match reference)
#define NROWS 50000
#define MROWS 20000
#define HIDC  256
#define OUTC  64

// ---------------------------------------------------------------------------
// Static device scratch (allocation-free rule: __device__ globals)
// ---------------------------------------------------------------------------
__device__ __align__(16) float g_xw0[(size_t)NROWS * HIDC];   // x @ W0
__device__ __align__(16) float g_yw0[(size_t)MROWS * HIDC];   // y @ W0
__device__ __align__(16) float g_sa [(size_t)NROWS * HIDC];   // spmm(HHT, .)  (reused layer1)
__device__ __align__(16) float g_sb [(size_t)NROWS * HIDC];   // spmm(H,   .)
__device__ __align__(16) float g_sc [(size_t)MROWS * HIDC];   // spmm(HT,  .)
__device__ __align__(16) float g_sd [(size_t)MROWS * HIDC];   // spmm(HTH, .)
__device__ __align__(16) float g_x1 [(size_t)NROWS * HIDC];
__device__ __align__(16) float g_y1 [(size_t)MROWS * HIDC];
__device__ __align__(16) float g_xw1[(size_t)NROWS * OUTC];   // x1 @ W1
__device__ __align__(16) float g_yw1[(size_t)MROWS * OUTC];   // y1 @ W1

__device__ __forceinline__ float leaky(float v) {
    return v >= 0.0f ? v : 0.2f * v;
}

__device__ __forceinline__ void red_add_v4(float* p, float a, float b, float c, float d) {
#if defined(__CUDA_ARCH__) && (__CUDA_ARCH__ >= 900)
    asm volatile("red.global.add.v4.f32 [%0], {%1, %2, %3, %4};"
                 :: "l"(p), "f"(a), "f"(b), "f"(c), "f"(d)
                 : "memory");
#else
    atomicAdd(p + 0, a);
    atomicAdd(p + 1, b);
    atomicAdd(p + 2, c);
    atomicAdd(p + 3, d);
#endif
}

// ---------------------------------------------------------------------------
// Tiled fp32 GEMM: C[Mr,Nc] = A[Mr,K] @ B[K,Nc].
// BM=64, BN=64, BK=16, 256 threads, 4x4 micro-tile per thread.
// K and Nc are multiples of 16/64 here; only Mr needs guarding.
// ---------------------------------------------------------------------------
__global__ __launch_bounds__(256)
void gemm_kernel(const float* __restrict__ A, const float* __restrict__ B,
                 float* __restrict__ C, int Mr, int K, int Nc)
{
    constexpr int BM = 64, BN = 64, BK = 16;
    __shared__ float As[BK][BM];   // transposed A tile
    __shared__ float Bs[BK][BN];

    const int tid = threadIdx.x;
    const int tx  = tid & 15;      // 0..15 -> 4 output cols each
    const int ty  = tid >> 4;      // 0..15 -> 4 output rows each
    const int row0 = blockIdx.y * BM;
    const int col0 = blockIdx.x * BN;

    float acc[4][4] = {};

    for (int k0 = 0; k0 < K; k0 += BK) {
        // A tile: 64 rows x 16 k, one float4 per thread, stored transposed
        {
            const int r  = tid >> 2;              // 0..63
            const int kc = (tid & 3) * 4;         // 0,4,8,12
            float4 v = make_float4(0.f, 0.f, 0.f, 0.f);
            if (row0 + r < Mr)
                v = *(const float4*)(A + (size_t)(row0 + r) * K + k0 + kc);
            As[kc + 0][r] = v.x; As[kc + 1][r] = v.y;
            As[kc + 2][r] = v.z; As[kc + 3][r] = v.w;
        }
        // B tile: 16 k x 64 cols, one float4 per thread
        {
            const int r = tid >> 4;               // 0..15
            const int c = (tid & 15) * 4;         // 0..60
            *(float4*)&Bs[r][c] =
                *(const float4*)(B + (size_t)(k0 + r) * Nc + col0 + c);
        }
        __syncthreads();

        #pragma unroll
        for (int k = 0; k < BK; ++k) {
            const float4 a4 = *(const float4*)&As[k][ty * 4];
            const float4 b4 = *(const float4*)&Bs[k][tx * 4];
            acc[0][0] += a4.x * b4.x; acc[0][1] += a4.x * b4.y;
            acc[0][2] += a4.x * b4.z; acc[0][3] += a4.x * b4.w;
            acc[1][0] += a4.y * b4.x; acc[1][1] += a4.y * b4.y;
            acc[1][2] += a4.y * b4.z; acc[1][3] += a4.y * b4.w;
            acc[2][0] += a4.z * b4.x; acc[2][1] += a4.z * b4.y;
            acc[2][2] += a4.z * b4.z; acc[2][3] += a4.z * b4.w;
            acc[3][0] += a4.w * b4.x; acc[3][1] += a4.w * b4.y;
            acc[3][2] += a4.w * b4.z; acc[3][3] += a4.w * b4.w;
        }
        __syncthreads();
    }

    #pragma unroll
    for (int i = 0; i < 4; ++i) {
        const int r = row0 + ty * 4 + i;
        if (r < Mr) {
            float4 o = make_float4(acc[i][0], acc[i][1], acc[i][2], acc[i][3]);
            *(float4*)(C + (size_t)r * Nc + col0 + tx * 4) = o;
        }
    }
}

// ---------------------------------------------------------------------------
// COO SpMM via vectorized global reductions.
// dst[r, :] += v * src[c, :]   for every nnz (r, c, v).
// K/4 threads cooperate per edge; each thread issues one red.global.add.v4.f32
// (no return value, spread addresses -> high L2 reduction throughput).
// Edge metadata is loaded by one lane per warp-subgroup and broadcast.
// Grid-stride over edges to keep the grid bounded.
// ---------------------------------------------------------------------------
template<int K>
__global__ __launch_bounds__(256)
void spmm_atomic_kernel(const int* __restrict__ rows, const int* __restrict__ cols,
                        const float* __restrict__ vals, int nnz,
                        const float* __restrict__ src, float* __restrict__ dst)
{
    constexpr int TPE = K / 4;       // threads per edge (64 for K=256, 16 for K=64)
    constexpr int EPB = 256 / TPE;   // edges per block
    const int tid   = threadIdx.x;
    const int lane  = tid % TPE;
    const int eslot = tid / TPE;                 // edge slot within block
    const int lane32 = tid & 31;
    // metadata broadcast group: min(TPE,32) threads share one edge within a warp
    constexpr int BC = (TPE < 32) ? TPE : 32;

    for (int e0 = blockIdx.x * EPB; e0 < nnz; e0 += gridDim.x * EPB) {
        const int e = e0 + eslot;
        if (e >= nnz) break;

        int r, c; float v;
        if ((lane32 % BC) == 0) {
            r = __ldg(rows + e);
            c = __ldg(cols + e);
            v = __ldg(vals + e);
        }
        const unsigned srcln = (lane32 / BC) * BC;
        r = __shfl_sync(0xffffffffu, r, srcln);
        c = __shfl_sync(0xffffffffu, c, srcln);
        v = __shfl_sync(0xffffffffu, v, srcln);

        const float4 s = __ldg((const float4*)(src + (size_t)c * K) + lane);
        float* p = dst + (size_t)r * K + (size_t)lane * 4;
        red_add_v4(p, v * s.x, v * s.y, v * s.z, v * s.w);
    }
}

// ---------------------------------------------------------------------------
// out[i] = leaky(a[i]) + leaky(b[i]), float4-vectorized
// ---------------------------------------------------------------------------
__global__ __launch_bounds__(256)
void combine_leaky_kernel(const float4* __restrict__ a, const float4* __restrict__ b,
                          float4* __restrict__ out, int n4)
{
    const int i = blockIdx.x * blockDim.x + threadIdx.x;
    if (i >= n4) return;
    const float4 av = a[i];
    const float4 bv = b[i];
    float4 o;
    o.x = leaky(av.x) + leaky(bv.x);
    o.y = leaky(av.y) + leaky(bv.y);
    o.z = leaky(av.z) + leaky(bv.z);
    o.w = leaky(av.w) + leaky(bv.w);
    out[i] = o;
}

static inline int spmm_grid(int nnz, int epb) {
    long long g = ((long long)nnz + epb - 1) / epb;
    if (g > 65535) g = 65535;   // grid-stride covers the rest
    return (int)g;
}

// ---------------------------------------------------------------------------
// Launch
// ---------------------------------------------------------------------------
extern "C" void kernel_launch(void* const* d_in, const int* in_sizes, int n_in,
                              void* d_out, int out_size)
{
    const float* x   = (const float*)d_in[0];
    const float* y   = (const float*)d_in[1];
    const float* W0  = (const float*)d_in[2];
    const float* W1  = (const float*)d_in[3];
    const int*   hht_r = (const int*)d_in[4];
    const int*   hht_c = (const int*)d_in[5];
    const float* hht_v = (const float*)d_in[6];
    const int*   h_r   = (const int*)d_in[7];
    const int*   h_c   = (const int*)d_in[8];
    const float* h_v   = (const float*)d_in[9];
    const int*   ht_r  = (const int*)d_in[10];
    const int*   ht_c  = (const int*)d_in[11];
    const float* ht_v  = (const float*)d_in[12];
    const int*   hth_r = (const int*)d_in[13];
    const int*   hth_c = (const int*)d_in[14];
    const float* hth_v = (const float*)d_in[15];

    const int nnz_hht = in_sizes[4];
    const int nnz_h   = in_sizes[7];
    const int nnz_ht  = in_sizes[10];
    const int nnz_hth = in_sizes[13];

    float *xw0, *yw0, *sa, *sb, *sc, *sd, *x1, *y1, *xw1, *yw1;
    cudaGetSymbolAddress((void**)&xw0, g_xw0);
    cudaGetSymbolAddress((void**)&yw0, g_yw0);
    cudaGetSymbolAddress((void**)&sa,  g_sa);
    cudaGetSymbolAddress((void**)&sb,  g_sb);
    cudaGetSymbolAddress((void**)&sc,  g_sc);
    cudaGetSymbolAddress((void**)&sd,  g_sd);
    cudaGetSymbolAddress((void**)&x1,  g_x1);
    cudaGetSymbolAddress((void**)&y1,  g_y1);
    cudaGetSymbolAddress((void**)&xw1, g_xw1);
    cudaGetSymbolAddress((void**)&yw1, g_yw1);

    float* out = (float*)d_out;

    // ---- Layer 0 dense: xW0 [N,256], yW0 [M,256] ----
    {
        dim3 gx((HIDC + 63) / 64, (NROWS + 63) / 64);
        gemm_kernel<<<gx, 256>>>(x, W0, xw0, NROWS, HIDC, HIDC);
        dim3 gy((HIDC + 63) / 64, (MROWS + 63) / 64);
        gemm_kernel<<<gy, 256>>>(y, W0, yw0, MROWS, HIDC, HIDC);
    }

    // ---- Layer 0 sparse: 4 SpMMs (K=256) ----
    cudaMemsetAsync(sa, 0, (size_t)NROWS * HIDC * sizeof(float), 0);
    cudaMemsetAsync(sb, 0, (size_t)NROWS * HIDC * sizeof(float), 0);
    cudaMemsetAsync(sc, 0, (size_t)MROWS * HIDC * sizeof(float), 0);
    cudaMemsetAsync(sd, 0, (size_t)MROWS * HIDC * sizeof(float), 0);
    {
        constexpr int EPB = 256 / (HIDC / 4);  // 4 edges / block
        spmm_atomic_kernel<HIDC><<<spmm_grid(nnz_hht, EPB), 256>>>(hht_r, hht_c, hht_v, nnz_hht, xw0, sa);
        spmm_atomic_kernel<HIDC><<<spmm_grid(nnz_h,   EPB), 256>>>(h_r,   h_c,   h_v,   nnz_h,   yw0, sb);
        spmm_atomic_kernel<HIDC><<<spmm_grid(nnz_ht,  EPB), 256>>>(ht_r,  ht_c,  ht_v,  nnz_ht,  xw0, sc);
        spmm_atomic_kernel<HIDC><<<spmm_grid(nnz_hth, EPB), 256>>>(hth_r, hth_c, hth_v, nnz_hth, yw0, sd);
    }

    // ---- x1 = leaky(sa) + leaky(sb); y1 = leaky(sc) + leaky(sd) ----
    {
        int n4x = NROWS * HIDC / 4;
        combine_leaky_kernel<<<(n4x + 255) / 256, 256>>>((const float4*)sa, (const float4*)sb, (float4*)x1, n4x);
        int n4y = MROWS * HIDC / 4;
        combine_leaky_kernel<<<(n4y + 255) / 256, 256>>>((const float4*)sc, (const float4*)sd, (float4*)y1, n4y);
    }

    // ---- Layer 1 dense: x1W1 [N,64], y1W1 [M,64] ----
    {
        dim3 gx((OUTC + 63) / 64, (NROWS + 63) / 64);
        gemm_kernel<<<gx, 256>>>(x1, W1, xw1, NROWS, HIDC, OUTC);
        dim3 gy((OUTC + 63) / 64, (MROWS + 63) / 64);
        gemm_kernel<<<gy, 256>>>(y1, W1, yw1, MROWS, HIDC, OUTC);
    }

    // ---- Layer 1 sparse: 4 SpMMs (K=64), reuse sa..sd scratch ----
    cudaMemsetAsync(sa, 0, (size_t)NROWS * OUTC * sizeof(float), 0);
    cudaMemsetAsync(sb, 0, (size_t)NROWS * OUTC * sizeof(float), 0);
    cudaMemsetAsync(sc, 0, (size_t)MROWS * OUTC * sizeof(float), 0);
    cudaMemsetAsync(sd, 0, (size_t)MROWS * OUTC * sizeof(float), 0);
    {
        constexpr int EPB = 256 / (OUTC / 4);  // 16 edges / block
        spmm_atomic_kernel<OUTC><<<spmm_grid(nnz_hht, EPB), 256>>>(hht_r, hht_c, hht_v, nnz_hht, xw1, sa);
        spmm_atomic_kernel<OUTC><<<spmm_grid(nnz_h,   EPB), 256>>>(h_r,   h_c,   h_v,   nnz_h,   yw1, sb);
        spmm_atomic_kernel<OUTC><<<spmm_grid(nnz_ht,  EPB), 256>>>(ht_r,  ht_c,  ht_v,  nnz_ht,  xw1, sc);
        spmm_atomic_kernel<OUTC><<<spmm_grid(nnz_hth, EPB), 256>>>(hth_r, hth_c, hth_v, nnz_hth, yw1, sd);
    }

    // ---- Output: x_out = leaky(sa)+leaky(sb), y_out = leaky(sc)+leaky(sd) ----
    {
        int n4x = NROWS * OUTC / 4;
        combine_leaky_kernel<<<(n4x + 255) / 256, 256>>>((const float4*)sa, (const float4*)sb, (float4*)out, n4x);
        int n4y = MROWS * OUTC / 4;
        combine_leaky_kernel<<<(n4y + 255) / 256, 256>>>((const float4*)sc, (const float4*)sd,
                                                         (float4*)(out + (size_t)NROWS * OUTC), n4y);
    }
}

// round 4
// speedup vs baseline: 1.0046x; 1.0046x over previous
#include <cuda_runtime.h>
#include <cstdint>
#include <cstddef>

// Problem constants (match reference)
#define NROWS 50000
#define MROWS 20000
#define HIDC  256
#define OUTC  64

// ---------------------------------------------------------------------------
// Static device scratch (allocation-free rule: __device__ globals)
// ---------------------------------------------------------------------------
__device__ __align__(16) float g_xw0[(size_t)NROWS * HIDC];   // x @ W0
__device__ __align__(16) float g_yw0[(size_t)MROWS * HIDC];   // y @ W0
__device__ __align__(16) float g_sa [(size_t)NROWS * HIDC];   // spmm(HHT, .)  (reused layer1)
__device__ __align__(16) float g_sb [(size_t)NROWS * HIDC];   // spmm(H,   .)
__device__ __align__(16) float g_sc [(size_t)MROWS * HIDC];   // spmm(HT,  .)
__device__ __align__(16) float g_sd [(size_t)MROWS * HIDC];   // spmm(HTH, .)
__device__ __align__(16) float g_xw1[(size_t)NROWS * OUTC];   // leaky-combined(sa,sb) @ W1
__device__ __align__(16) float g_yw1[(size_t)MROWS * OUTC];   // leaky-combined(sc,sd) @ W1

__device__ __forceinline__ float leaky(float v) {
    return v >= 0.0f ? v : 0.2f * v;
}

__device__ __forceinline__ void red_add_v4(float* p, float a, float b, float c, float d) {
#if defined(__CUDA_ARCH__) && (__CUDA_ARCH__ >= 900)
    asm volatile("red.global.add.v4.f32 [%0], {%1, %2, %3, %4};"
                 :: "l"(p), "f"(a), "f"(b), "f"(c), "f"(d)
                 : "memory");
#else
    atomicAdd(p + 0, a);
    atomicAdd(p + 1, b);
    atomicAdd(p + 2, c);
    atomicAdd(p + 3, d);
#endif
}

// ---------------------------------------------------------------------------
// Tiled fp32 GEMM: C[Mr,Nc] = A_eff[Mr,K] @ B[K,Nc]
// BM=128, BK=16, 256 threads, TM=8 x TN micro-tile per thread.
//   BN=128, TN=8 : layer-0 (Nc=256)
//   BN=64,  TN=4 : layer-1 (Nc=64)
// FUSE: A_eff[i] = leaky(A[i]) + leaky(A2[i])   (mid-layer combine fused in;
// valid because each A tile is read exactly once per column tile).
// ---------------------------------------------------------------------------
template<int BN, int TN, bool FUSE>
__global__ __launch_bounds__(256)
void gemm128_kernel(const float* __restrict__ A, const float* __restrict__ A2,
                    const float* __restrict__ B, float* __restrict__ C,
                    int Mr, int K, int Nc)
{
    constexpr int BM = 128, BK = 16, TM = 8;
    constexpr int NT4 = BN / 4;               // float4 per B-tile row
    constexpr int BSLOTS = BK * NT4;          // float4 slots in B tile

    __shared__ float As[BK][BM];              // transposed A tile
    __shared__ float Bs[BK][BN];

    const int tid  = threadIdx.x;
    const int tx   = tid & 15;                // 16 col-groups
    const int ty   = tid >> 4;                // 16 row-groups
    const int row0 = blockIdx.y * BM;
    const int col0 = blockIdx.x * BN;

    float acc[TM][TN] = {};

    for (int k0 = 0; k0 < K; k0 += BK) {
        // ---- A tile: 128 rows x 16 k  (512 float4 slots, 2 per thread) ----
        #pragma unroll
        for (int t = 0; t < 2; ++t) {
            const int li = tid + t * 256;     // 0..511
            const int r  = li >> 2;           // 0..127
            const int kc = (li & 3) * 4;      // 0,4,8,12
            float4 v = make_float4(0.f, 0.f, 0.f, 0.f);
            if (row0 + r < Mr) {
                const size_t off = (size_t)(row0 + r) * K + k0 + kc;
                v = *(const float4*)(A + off);
                if (FUSE) {
                    const float4 w = *(const float4*)(A2 + off);
                    v.x = leaky(v.x) + leaky(w.x);
                    v.y = leaky(v.y) + leaky(w.y);
                    v.z = leaky(v.z) + leaky(w.z);
                    v.w = leaky(v.w) + leaky(w.w);
                }
            }
            As[kc + 0][r] = v.x; As[kc + 1][r] = v.y;
            As[kc + 2][r] = v.z; As[kc + 3][r] = v.w;
        }
        // ---- B tile: 16 k x BN cols ----
        #pragma unroll
        for (int t = 0; t < BSLOTS / 256; ++t) {
            const int li = tid + t * 256;
            const int r  = li / NT4;
            const int c  = (li % NT4) * 4;
            *(float4*)&Bs[r][c] =
                *(const float4*)(B + (size_t)(k0 + r) * Nc + col0 + c);
        }
        __syncthreads();

        #pragma unroll
        for (int k = 0; k < BK; ++k) {
            float a[TM], b[TN];
            *(float4*)&a[0] = *(const float4*)&As[k][ty * TM];
            *(float4*)&a[4] = *(const float4*)&As[k][ty * TM + 4];
            #pragma unroll
            for (int j = 0; j < TN; j += 4)
                *(float4*)&b[j] = *(const float4*)&Bs[k][tx * TN + j];
            #pragma unroll
            for (int i = 0; i < TM; ++i)
                #pragma unroll
                for (int j = 0; j < TN; ++j)
                    acc[i][j] += a[i] * b[j];
        }
        __syncthreads();
    }

    #pragma unroll
    for (int i = 0; i < TM; ++i) {
        const int r = row0 + ty * TM + i;
        if (r < Mr) {
            #pragma unroll
            for (int j = 0; j < TN; j += 4) {
                float4 o = make_float4(acc[i][j], acc[i][j+1], acc[i][j+2], acc[i][j+3]);
                *(float4*)(C + (size_t)r * Nc + col0 + tx * TN + j) = o;
            }
        }
    }
}

// ---------------------------------------------------------------------------
// COO SpMM via vectorized global reductions.
// dst[r, :] += v * src[c, :]   for every nnz (r, c, v).
// K/4 threads cooperate per edge; each thread issues one red.global.add.v4.f32.
// Edge metadata loaded once per broadcast group and shuffled.
// ---------------------------------------------------------------------------
template<int K>
__global__ __launch_bounds__(256)
void spmm_atomic_kernel(const int* __restrict__ rows, const int* __restrict__ cols,
                        const float* __restrict__ vals, int nnz,
                        const float* __restrict__ src, float* __restrict__ dst)
{
    constexpr int TPE = K / 4;       // threads per edge (64 for K=256, 16 for K=64)
    constexpr int EPB = 256 / TPE;   // edges per block
    const int tid    = threadIdx.x;
    const int lane   = tid % TPE;
    const int eslot  = tid / TPE;
    const int lane32 = tid & 31;
    constexpr int BC = (TPE < 32) ? TPE : 32;

    for (int e0 = blockIdx.x * EPB; e0 < nnz; e0 += gridDim.x * EPB) {
        const int e = e0 + eslot;
        if (e >= nnz) break;

        int r, c; float v;
        if ((lane32 % BC) == 0) {
            r = __ldg(rows + e);
            c = __ldg(cols + e);
            v = __ldg(vals + e);
        }
        const unsigned srcln = (lane32 / BC) * BC;
        r = __shfl_sync(0xffffffffu, r, srcln);
        c = __shfl_sync(0xffffffffu, c, srcln);
        v = __shfl_sync(0xffffffffu, v, srcln);

        const float4 s = __ldg((const float4*)(src + (size_t)c * K) + lane);
        float* p = dst + (size_t)r * K + (size_t)lane * 4;
        red_add_v4(p, v * s.x, v * s.y, v * s.z, v * s.w);
    }
}

// ---------------------------------------------------------------------------
// out[i] = leaky(a[i]) + leaky(b[i]), float4-vectorized  (final outputs only)
// ---------------------------------------------------------------------------
__global__ __launch_bounds__(256)
void combine_leaky_kernel(const float4* __restrict__ a, const float4* __restrict__ b,
                          float4* __restrict__ out, int n4)
{
    const int i = blockIdx.x * blockDim.x + threadIdx.x;
    if (i >= n4) return;
    const float4 av = a[i];
    const float4 bv = b[i];
    float4 o;
    o.x = leaky(av.x) + leaky(bv.x);
    o.y = leaky(av.y) + leaky(bv.y);
    o.z = leaky(av.z) + leaky(bv.z);
    o.w = leaky(av.w) + leaky(bv.w);
    out[i] = o;
}

static inline int spmm_grid(int nnz, int epb) {
    long long g = ((long long)nnz + epb - 1) / epb;
    if (g > 65535) g = 65535;   // grid-stride covers the rest
    return (int)g;
}

// ---------------------------------------------------------------------------
// Launch
// ---------------------------------------------------------------------------
extern "C" void kernel_launch(void* const* d_in, const int* in_sizes, int n_in,
                              void* d_out, int out_size)
{
    const float* x   = (const float*)d_in[0];
    const float* y   = (const float*)d_in[1];
    const float* W0  = (const float*)d_in[2];
    const float* W1  = (const float*)d_in[3];
    const int*   hht_r = (const int*)d_in[4];
    const int*   hht_c = (const int*)d_in[5];
    const float* hht_v = (const float*)d_in[6];
    const int*   h_r   = (const int*)d_in[7];
    const int*   h_c   = (const int*)d_in[8];
    const float* h_v   = (const float*)d_in[9];
    const int*   ht_r  = (const int*)d_in[10];
    const int*   ht_c  = (const int*)d_in[11];
    const float* ht_v  = (const float*)d_in[12];
    const int*   hth_r = (const int*)d_in[13];
    const int*   hth_c = (const int*)d_in[14];
    const float* hth_v = (const float*)d_in[15];

    const int nnz_hht = in_sizes[4];
    const int nnz_h   = in_sizes[7];
    const int nnz_ht  = in_sizes[10];
    const int nnz_hth = in_sizes[13];

    float *xw0, *yw0, *sa, *sb, *sc, *sd, *xw1, *yw1;
    cudaGetSymbolAddress((void**)&xw0, g_xw0);
    cudaGetSymbolAddress((void**)&yw0, g_yw0);
    cudaGetSymbolAddress((void**)&sa,  g_sa);
    cudaGetSymbolAddress((void**)&sb,  g_sb);
    cudaGetSymbolAddress((void**)&sc,  g_sc);
    cudaGetSymbolAddress((void**)&sd,  g_sd);
    cudaGetSymbolAddress((void**)&xw1, g_xw1);
    cudaGetSymbolAddress((void**)&yw1, g_yw1);

    float* out = (float*)d_out;

    // ---- Layer 0 dense: xW0 [N,256], yW0 [M,256] ----
    {
        dim3 gx(HIDC / 128, (NROWS + 127) / 128);
        gemm128_kernel<128, 8, false><<<gx, 256>>>(x, nullptr, W0, xw0, NROWS, HIDC, HIDC);
        dim3 gy(HIDC / 128, (MROWS + 127) / 128);
        gemm128_kernel<128, 8, false><<<gy, 256>>>(y, nullptr, W0, yw0, MROWS, HIDC, HIDC);
    }

    // ---- Layer 0 sparse: 4 SpMMs (K=256) ----
    cudaMemsetAsync(sa, 0, (size_t)NROWS * HIDC * sizeof(float), 0);
    cudaMemsetAsync(sb, 0, (size_t)NROWS * HIDC * sizeof(float), 0);
    cudaMemsetAsync(sc, 0, (size_t)MROWS * HIDC * sizeof(float), 0);
    cudaMemsetAsync(sd, 0, (size_t)MROWS * HIDC * sizeof(float), 0);
    {
        constexpr int EPB = 256 / (HIDC / 4);  // 4 edges / block
        spmm_atomic_kernel<HIDC><<<spmm_grid(nnz_hht, EPB), 256>>>(hht_r, hht_c, hht_v, nnz_hht, xw0, sa);
        spmm_atomic_kernel<HIDC><<<spmm_grid(nnz_h,   EPB), 256>>>(h_r,   h_c,   h_v,   nnz_h,   yw0, sb);
        spmm_atomic_kernel<HIDC><<<spmm_grid(nnz_ht,  EPB), 256>>>(ht_r,  ht_c,  ht_v,  nnz_ht,  xw0, sc);
        spmm_atomic_kernel<HIDC><<<spmm_grid(nnz_hth, EPB), 256>>>(hth_r, hth_c, hth_v, nnz_hth, yw0, sd);
    }

    // ---- Layer 1 dense (combine fused into A-load):
    //      xw1 = (leaky(sa)+leaky(sb)) @ W1,  yw1 = (leaky(sc)+leaky(sd)) @ W1 ----
    {
        dim3 gx(OUTC / 64, (NROWS + 127) / 128);
        gemm128_kernel<64, 4, true><<<gx, 256>>>(sa, sb, W1, xw1, NROWS, HIDC, OUTC);
        dim3 gy(OUTC / 64, (MROWS + 127) / 128);
        gemm128_kernel<64, 4, true><<<gy, 256>>>(sc, sd, W1, yw1, MROWS, HIDC, OUTC);
    }

    // ---- Layer 1 sparse: 4 SpMMs (K=64), reuse sa..sd scratch ----
    cudaMemsetAsync(sa, 0, (size_t)NROWS * OUTC * sizeof(float), 0);
    cudaMemsetAsync(sb, 0, (size_t)NROWS * OUTC * sizeof(float), 0);
    cudaMemsetAsync(sc, 0, (size_t)MROWS * OUTC * sizeof(float), 0);
    cudaMemsetAsync(sd, 0, (size_t)MROWS * OUTC * sizeof(float), 0);
    {
        constexpr int EPB = 256 / (OUTC / 4);  // 16 edges / block
        spmm_atomic_kernel<OUTC><<<spmm_grid(nnz_hht, EPB), 256>>>(hht_r, hht_c, hht_v, nnz_hht, xw1, sa);
        spmm_atomic_kernel<OUTC><<<spmm_grid(nnz_h,   EPB), 256>>>(h_r,   h_c,   h_v,   nnz_h,   yw1, sb);
        spmm_atomic_kernel<OUTC><<<spmm_grid(nnz_ht,  EPB), 256>>>(ht_r,  ht_c,  ht_v,  nnz_ht,  xw1, sc);
        spmm_atomic_kernel<OUTC><<<spmm_grid(nnz_hth, EPB), 256>>>(hth_r, hth_c, hth_v, nnz_hth, yw1, sd);
    }

    // ---- Output: x_out = leaky(sa)+leaky(sb), y_out = leaky(sc)+leaky(sd) ----
    {
        int n4x = NROWS * OUTC / 4;
        combine_leaky_kernel<<<(n4x + 255) / 256, 256>>>((const float4*)sa, (const float4*)sb, (float4*)out, n4x);
        int n4y = MROWS * OUTC / 4;
        combine_leaky_kernel<<<(n4y + 255) / 256, 256>>>((const float4*)sc, (const float4*)sd,
                                                         (float4*)(out + (size_t)NROWS * OUTC), n4y);
    }
}

// round 6
// speedup vs baseline: 1.0330x; 1.0283x over previous
#include <cuda_runtime.h>
#include <cstdint>
#include <cstddef>

// Problem constants (match reference)
#define NROWS 50000
#define MROWS 20000
#define HIDC  256
#define OUTC  64

// ---------------------------------------------------------------------------
// Static device scratch (allocation-free rule: __device__ globals)
// ---------------------------------------------------------------------------
__device__ __align__(16) float g_xw0[(size_t)NROWS * HIDC];   // x @ W0
__device__ __align__(16) float g_yw0[(size_t)MROWS * HIDC];   // y @ W0
__device__ __align__(16) float g_sa [(size_t)NROWS * HIDC];   // spmm(HHT, .)  (reused layer1)
__device__ __align__(16) float g_sb [(size_t)NROWS * HIDC];   // spmm(H,   .)
__device__ __align__(16) float g_sc [(size_t)MROWS * HIDC];   // spmm(HT,  .)
__device__ __align__(16) float g_sd [(size_t)MROWS * HIDC];   // spmm(HTH, .)
__device__ __align__(16) float g_xw1[(size_t)NROWS * OUTC];   // leaky-combined(sa,sb) @ W1
__device__ __align__(16) float g_yw1[(size_t)MROWS * OUTC];   // leaky-combined(sc,sd) @ W1

__device__ __forceinline__ float leaky(float v) {
    return v >= 0.0f ? v : 0.2f * v;
}

__device__ __forceinline__ void red_add_v4(float* p, float a, float b, float c, float d) {
#if defined(__CUDA_ARCH__) && (__CUDA_ARCH__ >= 900)
    asm volatile("red.global.add.v4.f32 [%0], {%1, %2, %3, %4};"
                 :: "l"(p), "f"(a), "f"(b), "f"(c), "f"(d)
                 : "memory");
#else
    atomicAdd(p + 0, a);
    atomicAdd(p + 1, b);
    atomicAdd(p + 2, c);
    atomicAdd(p + 3, d);
#endif
}

// ---- packed fp32x2 helpers (Blackwell FFMA2 path; 2x FFMA issue rate) ----
__device__ __forceinline__ unsigned long long pack_dup_f32(float x) {
#if defined(__CUDA_ARCH__) && (__CUDA_ARCH__ >= 1000)
    unsigned long long r;
    asm("mov.b64 %0, {%1, %1};" : "=l"(r) : "r"(__float_as_uint(x)));
    return r;
#else
    union { unsigned long long u; float f[2]; } t;
    t.f[0] = x; t.f[1] = x;
    return t.u;
#endif
}

__device__ __forceinline__ void ffma2(unsigned long long& acc,
                                      unsigned long long a, unsigned long long b) {
#if defined(__CUDA_ARCH__) && (__CUDA_ARCH__ >= 1000)
    asm("fma.rn.f32x2 %0, %1, %2, %0;" : "+l"(acc) : "l"(a), "l"(b));
#else
    union U { unsigned long long u; float f[2]; };
    U ua, ub, uc; ua.u = a; ub.u = b; uc.u = acc;
    uc.f[0] = fmaf(ua.f[0], ub.f[0], uc.f[0]);
    uc.f[1] = fmaf(ua.f[1], ub.f[1], uc.f[1]);
    acc = uc.u;
#endif
}

// ---------------------------------------------------------------------------
// Tiled fp32 GEMM with packed f32x2 accumulation:
// C[Mr,Nc] = A_eff[Mr,K] @ B[K,Nc]
// BM=128, BK=16, 256 threads, TM=8 x TN micro-tile per thread.
//   BN=128, TN=8 : layer-0 (Nc=256)
//   BN=64,  TN=4 : layer-1 (Nc=64)
// Inner product runs on fma.rn.f32x2 (FFMA2): acc pairs cover columns
// (2j, 2j+1); b pairs load directly from contiguous smem as u64; a values
// are lane-duplicated with one mov.b64 each. Full fp32 precision.
// FUSE: A_eff[i] = leaky(A[i]) + leaky(A2[i])  (mid-layer combine fused in).
// ---------------------------------------------------------------------------
template<int BN, int TN, bool FUSE>
__global__ __launch_bounds__(256)
void gemm128_kernel(const float* __restrict__ A, const float* __restrict__ A2,
                    const float* __restrict__ B, float* __restrict__ C,
                    int Mr, int K, int Nc)
{
    constexpr int BM = 128, BK = 16, TM = 8;
    constexpr int TNP = TN / 2;               // packed pairs per thread
    constexpr int NT4 = BN / 4;               // float4 per B-tile row
    constexpr int BSLOTS = BK * NT4;          // float4 slots in B tile

    __shared__ float As[BK][BM];              // transposed A tile
    __shared__ float Bs[BK][BN];

    const int tid  = threadIdx.x;
    const int tx   = tid & 15;                // 16 col-groups
    const int ty   = tid >> 4;                // 16 row-groups
    const int row0 = blockIdx.y * BM;
    const int col0 = blockIdx.x * BN;

    unsigned long long acc2[TM][TNP] = {};    // (0ull == two +0.0f)

    for (int k0 = 0; k0 < K; k0 += BK) {
        // ---- A tile: 128 rows x 16 k  (512 float4 slots, 2 per thread) ----
        #pragma unroll
        for (int t = 0; t < 2; ++t) {
            const int li = tid + t * 256;     // 0..511
            const int r  = li >> 2;           // 0..127
            const int kc = (li & 3) * 4;      // 0,4,8,12
            float4 v = make_float4(0.f, 0.f, 0.f, 0.f);
            if (row0 + r < Mr) {
                const size_t off = (size_t)(row0 + r) * K + k0 + kc;
                v = *(const float4*)(A + off);
                if (FUSE) {
                    const float4 w = *(const float4*)(A2 + off);
                    v.x = leaky(v.x) + leaky(w.x);
                    v.y = leaky(v.y) + leaky(w.y);
                    v.z = leaky(v.z) + leaky(w.z);
                    v.w = leaky(v.w) + leaky(w.w);
                }
            }
            As[kc + 0][r] = v.x; As[kc + 1][r] = v.y;
            As[kc + 2][r] = v.z; As[kc + 3][r] = v.w;
        }
        // ---- B tile: 16 k x BN cols ----
        #pragma unroll
        for (int t = 0; t < BSLOTS / 256; ++t) {
            const int li = tid + t * 256;
            const int r  = li / NT4;
            const int c  = (li % NT4) * 4;
            *(float4*)&Bs[r][c] =
                *(const float4*)(B + (size_t)(k0 + r) * Nc + col0 + c);
        }
        __syncthreads();

        #pragma unroll
        for (int k = 0; k < BK; ++k) {
            float a[TM];
            *(float4*)&a[0] = *(const float4*)&As[k][ty * TM];
            *(float4*)&a[4] = *(const float4*)&As[k][ty * TM + 4];

            unsigned long long a2[TM];
            #pragma unroll
            for (int i = 0; i < TM; ++i) a2[i] = pack_dup_f32(a[i]);

            unsigned long long b2[TNP];
            #pragma unroll
            for (int j = 0; j < TNP; j += 2) {
                const ulonglong2 t = *(const ulonglong2*)&Bs[k][tx * TN + j * 2];
                b2[j]     = t.x;
                b2[j + 1] = t.y;
            }

            #pragma unroll
            for (int i = 0; i < TM; ++i)
                #pragma unroll
                for (int j = 0; j < TNP; ++j)
                    ffma2(acc2[i][j], a2[i], b2[j]);
        }
        __syncthreads();
    }

    #pragma unroll
    for (int i = 0; i < TM; ++i) {
        const int r = row0 + ty * TM + i;
        if (r < Mr) {
            #pragma unroll
            for (int j = 0; j < TNP; j += 2) {
                ulonglong2 o;
                o.x = acc2[i][j];
                o.y = acc2[i][j + 1];
                *(ulonglong2*)(C + (size_t)r * Nc + col0 + tx * TN + j * 2) = o;
            }
        }
    }
}

// ---------------------------------------------------------------------------
// COO SpMM via vectorized global reductions.
// dst[r, :] += v * src[c, :]   for every nnz (r, c, v).
// K/4 threads cooperate per edge; each thread issues one red.global.add.v4.f32.
// Edge metadata loaded once per broadcast group and shuffled.
// ---------------------------------------------------------------------------
template<int K>
__global__ __launch_bounds__(256)
void spmm_atomic_kernel(const int* __restrict__ rows, const int* __restrict__ cols,
                        const float* __restrict__ vals, int nnz,
                        const float* __restrict__ src, float* __restrict__ dst)
{
    constexpr int TPE = K / 4;       // threads per edge (64 for K=256, 16 for K=64)
    constexpr int EPB = 256 / TPE;   // edges per block
    const int tid    = threadIdx.x;
    const int lane   = tid % TPE;
    const int eslot  = tid / TPE;
    const int lane32 = tid & 31;
    constexpr int BC = (TPE < 32) ? TPE : 32;

    for (int e0 = blockIdx.x * EPB; e0 < nnz; e0 += gridDim.x * EPB) {
        const int e = e0 + eslot;
        if (e >= nnz) break;

        int r, c; float v;
        if ((lane32 % BC) == 0) {
            r = __ldg(rows + e);
            c = __ldg(cols + e);
            v = __ldg(vals + e);
        }
        const unsigned srcln = (lane32 / BC) * BC;
        r = __shfl_sync(0xffffffffu, r, srcln);
        c = __shfl_sync(0xffffffffu, c, srcln);
        v = __shfl_sync(0xffffffffu, v, srcln);

        const float4 s = __ldg((const float4*)(src + (size_t)c * K) + lane);
        float* p = dst + (size_t)r * K + (size_t)lane * 4;
        red_add_v4(p, v * s.x, v * s.y, v * s.z, v * s.w);
    }
}

// ---------------------------------------------------------------------------
// out[i] = leaky(a[i]) + leaky(b[i]), float4-vectorized  (final outputs only)
// ---------------------------------------------------------------------------
__global__ __launch_bounds__(256)
void combine_leaky_kernel(const float4* __restrict__ a, const float4* __restrict__ b,
                          float4* __restrict__ out, int n4)
{
    const int i = blockIdx.x * blockDim.x + threadIdx.x;
    if (i >= n4) return;
    const float4 av = a[i];
    const float4 bv = b[i];
    float4 o;
    o.x = leaky(av.x) + leaky(bv.x);
    o.y = leaky(av.y) + leaky(bv.y);
    o.z = leaky(av.z) + leaky(bv.z);
    o.w = leaky(av.w) + leaky(bv.w);
    out[i] = o;
}

static inline int spmm_grid(int nnz, int epb) {
    long long g = ((long long)nnz + epb - 1) / epb;
    if (g > 65535) g = 65535;   // grid-stride covers the rest
    return (int)g;
}

// ---------------------------------------------------------------------------
// Launch
// ---------------------------------------------------------------------------
extern "C" void kernel_launch(void* const* d_in, const int* in_sizes, int n_in,
                              void* d_out, int out_size)
{
    const float* x   = (const float*)d_in[0];
    const float* y   = (const float*)d_in[1];
    const float* W0  = (const float*)d_in[2];
    const float* W1  = (const float*)d_in[3];
    const int*   hht_r = (const int*)d_in[4];
    const int*   hht_c = (const int*)d_in[5];
    const float* hht_v = (const float*)d_in[6];
    const int*   h_r   = (const int*)d_in[7];
    const int*   h_c   = (const int*)d_in[8];
    const float* h_v   = (const float*)d_in[9];
    const int*   ht_r  = (const int*)d_in[10];
    const int*   ht_c  = (const int*)d_in[11];
    const float* ht_v  = (const float*)d_in[12];
    const int*   hth_r = (const int*)d_in[13];
    const int*   hth_c = (const int*)d_in[14];
    const float* hth_v = (const float*)d_in[15];

    const int nnz_hht = in_sizes[4];
    const int nnz_h   = in_sizes[7];
    const int nnz_ht  = in_sizes[10];
    const int nnz_hth = in_sizes[13];

    float *xw0, *yw0, *sa, *sb, *sc, *sd, *xw1, *yw1;
    cudaGetSymbolAddress((void**)&xw0, g_xw0);
    cudaGetSymbolAddress((void**)&yw0, g_yw0);
    cudaGetSymbolAddress((void**)&sa,  g_sa);
    cudaGetSymbolAddress((void**)&sb,  g_sb);
    cudaGetSymbolAddress((void**)&sc,  g_sc);
    cudaGetSymbolAddress((void**)&sd,  g_sd);
    cudaGetSymbolAddress((void**)&xw1, g_xw1);
    cudaGetSymbolAddress((void**)&yw1, g_yw1);

    float* out = (float*)d_out;

    // ---- Layer 0 dense: xW0 [N,256], yW0 [M,256] ----
    {
        dim3 gx(HIDC / 128, (NROWS + 127) / 128);
        gemm128_kernel<128, 8, false><<<gx, 256>>>(x, nullptr, W0, xw0, NROWS, HIDC, HIDC);
        dim3 gy(HIDC / 128, (MROWS + 127) / 128);
        gemm128_kernel<128, 8, false><<<gy, 256>>>(y, nullptr, W0, yw0, MROWS, HIDC, HIDC);
    }

    // ---- Layer 0 sparse: 4 SpMMs (K=256) ----
    cudaMemsetAsync(sa, 0, (size_t)NROWS * HIDC * sizeof(float), 0);
    cudaMemsetAsync(sb, 0, (size_t)NROWS * HIDC * sizeof(float), 0);
    cudaMemsetAsync(sc, 0, (size_t)MROWS * HIDC * sizeof(float), 0);
    cudaMemsetAsync(sd, 0, (size_t)MROWS * HIDC * sizeof(float), 0);
    {
        constexpr int EPB = 256 / (HIDC / 4);  // 4 edges / block
        spmm_atomic_kernel<HIDC><<<spmm_grid(nnz_hht, EPB), 256>>>(hht_r, hht_c, hht_v, nnz_hht, xw0, sa);
        spmm_atomic_kernel<HIDC><<<spmm_grid(nnz_h,   EPB), 256>>>(h_r,   h_c,   h_v,   nnz_h,   yw0, sb);
        spmm_atomic_kernel<HIDC><<<spmm_grid(nnz_ht,  EPB), 256>>>(ht_r,  ht_c,  ht_v,  nnz_ht,  xw0, sc);
        spmm_atomic_kernel<HIDC><<<spmm_grid(nnz_hth, EPB), 256>>>(hth_r, hth_c, hth_v, nnz_hth, yw0, sd);
    }

    // ---- Layer 1 dense (combine fused into A-load):
    //      xw1 = (leaky(sa)+leaky(sb)) @ W1,  yw1 = (leaky(sc)+leaky(sd)) @ W1 ----
    {
        dim3 gx(OUTC / 64, (NROWS + 127) / 128);
        gemm128_kernel<64, 4, true><<<gx, 256>>>(sa, sb, W1, xw1, NROWS, HIDC, OUTC);
        dim3 gy(OUTC / 64, (MROWS + 127) / 128);
        gemm128_kernel<64, 4, true><<<gy, 256>>>(sc, sd, W1, yw1, MROWS, HIDC, OUTC);
    }

    // ---- Layer 1 sparse: 4 SpMMs (K=64), reuse sa..sd scratch ----
    cudaMemsetAsync(sa, 0, (size_t)NROWS * OUTC * sizeof(float), 0);
    cudaMemsetAsync(sb, 0, (size_t)NROWS * OUTC * sizeof(float), 0);
    cudaMemsetAsync(sc, 0, (size_t)MROWS * OUTC * sizeof(float), 0);
    cudaMemsetAsync(sd, 0, (size_t)MROWS * OUTC * sizeof(float), 0);
    {
        constexpr int EPB = 256 / (OUTC / 4);  // 16 edges / block
        spmm_atomic_kernel<OUTC><<<spmm_grid(nnz_hht, EPB), 256>>>(hht_r, hht_c, hht_v, nnz_hht, xw1, sa);
        spmm_atomic_kernel<OUTC><<<spmm_grid(nnz_h,   EPB), 256>>>(h_r,   h_c,   h_v,   nnz_h,   yw1, sb);
        spmm_atomic_kernel<OUTC><<<spmm_grid(nnz_ht,  EPB), 256>>>(ht_r,  ht_c,  ht_v,  nnz_ht,  xw1, sc);
        spmm_atomic_kernel<OUTC><<<spmm_grid(nnz_hth, EPB), 256>>>(hth_r, hth_c, hth_v, nnz_hth, yw1, sd);
    }

    // ---- Output: x_out = leaky(sa)+leaky(sb), y_out = leaky(sc)+leaky(sd) ----
    {
        int n4x = NROWS * OUTC / 4;
        combine_leaky_kernel<<<(n4x + 255) / 256, 256>>>((const float4*)sa, (const float4*)sb, (float4*)out, n4x);
        int n4y = MROWS * OUTC / 4;
        combine_leaky_kernel<<<(n4y + 255) / 256, 256>>>((const float4*)sc, (const float4*)sd,
                                                         (float4*)(out + (size_t)NROWS * OUTC), n4y);
    }
}

// round 7
// speedup vs baseline: 1.7425x; 1.6869x over previous
#include <cuda_runtime.h>
#include <cstdint>
#include <cstddef>

// Problem constants (match reference)
#define NROWS 50000
#define MROWS 20000
#define HIDC  256
#define OUTC  64
#define NNZ_HHT 1600000
#define NNZ_H   1000000
#define NNZ_HT  1000000
#define NNZ_HTH  640000

// ---------------------------------------------------------------------------
// Static device scratch (allocation-free rule: __device__ globals)
// ---------------------------------------------------------------------------
__device__ __align__(16) float g_xw0[(size_t)NROWS * HIDC];
__device__ __align__(16) float g_yw0[(size_t)MROWS * HIDC];
__device__ __align__(16) float g_sa [(size_t)NROWS * HIDC];
__device__ __align__(16) float g_sb [(size_t)NROWS * HIDC];
__device__ __align__(16) float g_sc [(size_t)MROWS * HIDC];
__device__ __align__(16) float g_sd [(size_t)MROWS * HIDC];
__device__ __align__(16) float g_xw1[(size_t)NROWS * OUTC];
__device__ __align__(16) float g_yw1[(size_t)MROWS * OUTC];

// CSR structures (built on device each launch; deterministic up to fp order)
__device__ int   g_cnt_hht[NROWS],  g_rp_hht[NROWS + 1],  g_cur_hht[NROWS];
__device__ int   g_cnt_h  [NROWS],  g_rp_h  [NROWS + 1],  g_cur_h  [NROWS];
__device__ int   g_cnt_ht [MROWS],  g_rp_ht [MROWS + 1],  g_cur_ht [MROWS];
__device__ int   g_cnt_hth[MROWS],  g_rp_hth[MROWS + 1],  g_cur_hth[MROWS];
__device__ int   g_aux_hht[64], g_aux_h[64], g_aux_ht[64], g_aux_hth[64];
__device__ int   g_pc_hht[NNZ_HHT];  __device__ float g_pv_hht[NNZ_HHT];
__device__ int   g_pc_h  [NNZ_H];    __device__ float g_pv_h  [NNZ_H];
__device__ int   g_pc_ht [NNZ_HT];   __device__ float g_pv_ht [NNZ_HT];
__device__ int   g_pc_hth[NNZ_HTH];  __device__ float g_pv_hth[NNZ_HTH];

__device__ __forceinline__ float leaky(float v) {
    return v >= 0.0f ? v : 0.2f * v;
}

// ---- packed fp32x2 helpers (Blackwell FFMA2 path) ----
__device__ __forceinline__ unsigned long long pack_dup_f32(float x) {
#if defined(__CUDA_ARCH__) && (__CUDA_ARCH__ >= 1000)
    unsigned long long r;
    asm("mov.b64 %0, {%1, %1};" : "=l"(r) : "r"(__float_as_uint(x)));
    return r;
#else
    union { unsigned long long u; float f[2]; } t;
    t.f[0] = x; t.f[1] = x;
    return t.u;
#endif
}

__device__ __forceinline__ void ffma2(unsigned long long& acc,
                                      unsigned long long a, unsigned long long b) {
#if defined(__CUDA_ARCH__) && (__CUDA_ARCH__ >= 1000)
    asm("fma.rn.f32x2 %0, %1, %2, %0;" : "+l"(acc) : "l"(a), "l"(b));
#else
    union U { unsigned long long u; float f[2]; };
    U ua, ub, uc; ua.u = a; ub.u = b; uc.u = acc;
    uc.f[0] = fmaf(ua.f[0], ub.f[0], uc.f[0]);
    uc.f[1] = fmaf(ua.f[1], ub.f[1], uc.f[1]);
    acc = uc.u;
#endif
}

// ===========================================================================
// CSR build kernels
// ===========================================================================
__global__ __launch_bounds__(256)
void zero_counts_kernel()
{
    const int i = blockIdx.x * blockDim.x + threadIdx.x;
    if (i < NROWS) { g_cnt_hht[i] = 0; g_cnt_h[i] = 0; }
    if (i < MROWS) { g_cnt_ht[i]  = 0; g_cnt_hth[i] = 0; }
}

__global__ __launch_bounds__(256)
void hist_kernel(const int* __restrict__ rows, int nnz, int* __restrict__ cnt)
{
    for (int e = blockIdx.x * blockDim.x + threadIdx.x; e < nnz;
         e += gridDim.x * blockDim.x)
        atomicAdd(cnt + rows[e], 1);
}

// pass 1: per-block exclusive scan of counts -> rowptr partial; aux[b] = block sum
__global__ __launch_bounds__(1024)
void scan1_kernel(const int* __restrict__ cnt, int* __restrict__ rp,
                  int* __restrict__ aux, int n)
{
    __shared__ int s[1024];
    const int tid = threadIdx.x;
    const int i = blockIdx.x * 1024 + tid;
    const int v = (i < n) ? cnt[i] : 0;
    s[tid] = v;
    __syncthreads();
    for (int off = 1; off < 1024; off <<= 1) {
        int t = (tid >= off) ? s[tid - off] : 0;
        __syncthreads();
        s[tid] += t;
        __syncthreads();
    }
    if (i < n) rp[i] = s[tid] - v;              // exclusive within block
    if (tid == 1023) aux[blockIdx.x] = s[1023]; // block total
}

// pass 2: exclusive scan of aux (<=64 entries), single block of 64 threads
__global__ __launch_bounds__(64)
void scan2_kernel(int* __restrict__ aux, int naux)
{
    __shared__ int s[64];
    const int tid = threadIdx.x;
    const int v = (tid < naux) ? aux[tid] : 0;
    s[tid] = v;
    __syncthreads();
    for (int off = 1; off < 64; off <<= 1) {
        int t = (tid >= off) ? s[tid - off] : 0;
        __syncthreads();
        s[tid] += t;
        __syncthreads();
    }
    if (tid < naux) aux[tid] = s[tid] - v;      // exclusive
}

// pass 3: add block offsets; copy rowptr into cursor; write rp[n]
__global__ __launch_bounds__(1024)
void scan3_kernel(const int* __restrict__ cnt, int* __restrict__ rp,
                  int* __restrict__ cur, const int* __restrict__ aux, int n)
{
    const int tid = threadIdx.x;
    const int i = blockIdx.x * 1024 + tid;
    if (i < n) {
        const int r = rp[i] + aux[blockIdx.x];
        rp[i] = r;
        cur[i] = r;
        if (i == n - 1) rp[n] = r + cnt[i];
    }
}

__global__ __launch_bounds__(256)
void scatter_kernel(const int* __restrict__ rows, const int* __restrict__ cols,
                    const float* __restrict__ vals, int nnz,
                    int* __restrict__ cur,
                    int* __restrict__ pc, float* __restrict__ pv)
{
    for (int e = blockIdx.x * blockDim.x + threadIdx.x; e < nnz;
         e += gridDim.x * blockDim.x) {
        const int r = rows[e];
        const int pos = atomicAdd(cur + r, 1);
        pc[pos] = cols[e];
        pv[pos] = vals[e];
    }
}

// ===========================================================================
// CSR SpMM, K=256: one warp per row, register accumulation, single store.
// 8 warps/block -> 8 rows/block. nrows divisible by 8 here.
// ===========================================================================
__global__ __launch_bounds__(256)
void spmm_csr256_kernel(const int* __restrict__ rp,
                        const int* __restrict__ pc, const float* __restrict__ pv,
                        const float* __restrict__ src, float* __restrict__ dst,
                        int nrows)
{
    const int row  = blockIdx.x * 8 + (threadIdx.x >> 5);
    const int lane = threadIdx.x & 31;
    if (row >= nrows) return;

    const int s0 = __ldg(rp + row);
    const int s1 = __ldg(rp + row + 1);

    float4 a0 = make_float4(0.f, 0.f, 0.f, 0.f);
    float4 a1 = make_float4(0.f, 0.f, 0.f, 0.f);

    for (int j0 = s0; j0 < s1; j0 += 32) {
        int   cc = 0; float vv = 0.f;
        if (j0 + lane < s1) {
            cc = __ldg(pc + j0 + lane);
            vv = __ldg(pv + j0 + lane);
        }
        const int cnt = min(32, s1 - j0);
        for (int t = 0; t < cnt; ++t) {
            const int   ct = __shfl_sync(0xffffffffu, cc, t);
            const float vt = __shfl_sync(0xffffffffu, vv, t);
            const float4* sp = (const float4*)(src + (size_t)ct * HIDC);
            const float4 x0 = __ldg(sp + lane);
            const float4 x1 = __ldg(sp + 32 + lane);
            a0.x += vt * x0.x; a0.y += vt * x0.y; a0.z += vt * x0.z; a0.w += vt * x0.w;
            a1.x += vt * x1.x; a1.y += vt * x1.y; a1.z += vt * x1.z; a1.w += vt * x1.w;
        }
    }

    float4* dp = (float4*)(dst + (size_t)row * HIDC);
    dp[lane]      = a0;
    dp[32 + lane] = a1;
}

// ===========================================================================
// CSR SpMM, K=64: 16 lanes per row (2 rows per warp), group-scoped shuffles.
// 16 rows/block. nrows divisible by 16 here.
// ===========================================================================
__global__ __launch_bounds__(256)
void spmm_csr64_kernel(const int* __restrict__ rp,
                       const int* __restrict__ pc, const float* __restrict__ pv,
                       const float* __restrict__ src, float* __restrict__ dst,
                       int nrows)
{
    const int lane32 = threadIdx.x & 31;
    const int lane16 = threadIdx.x & 15;
    const int row    = blockIdx.x * 16 + (threadIdx.x >> 4);
    if (row >= nrows) return;

    const unsigned gmask = 0xFFFFu << (lane32 & 16);

    const int s0 = __ldg(rp + row);
    const int s1 = __ldg(rp + row + 1);

    float4 a = make_float4(0.f, 0.f, 0.f, 0.f);

    for (int j0 = s0; j0 < s1; j0 += 16) {
        int   cc = 0; float vv = 0.f;
        if (j0 + lane16 < s1) {
            cc = __ldg(pc + j0 + lane16);
            vv = __ldg(pv + j0 + lane16);
        }
        const int cnt = min(16, s1 - j0);
        for (int t = 0; t < cnt; ++t) {
            const int   ct = __shfl_sync(gmask, cc, t, 16);
            const float vt = __shfl_sync(gmask, vv, t, 16);
            const float4 x = __ldg((const float4*)(src + (size_t)ct * OUTC) + lane16);
            a.x += vt * x.x; a.y += vt * x.y; a.z += vt * x.z; a.w += vt * x.w;
        }
    }

    *((float4*)(dst + (size_t)row * OUTC) + lane16) = a;
}

// ===========================================================================
// Tiled fp32 GEMM with packed f32x2 accumulation (unchanged from R6).
// ===========================================================================
template<int BN, int TN, bool FUSE>
__global__ __launch_bounds__(256)
void gemm128_kernel(const float* __restrict__ A, const float* __restrict__ A2,
                    const float* __restrict__ B, float* __restrict__ C,
                    int Mr, int K, int Nc)
{
    constexpr int BM = 128, BK = 16, TM = 8;
    constexpr int TNP = TN / 2;
    constexpr int NT4 = BN / 4;
    constexpr int BSLOTS = BK * NT4;

    __shared__ float As[BK][BM];
    __shared__ float Bs[BK][BN];

    const int tid  = threadIdx.x;
    const int tx   = tid & 15;
    const int ty   = tid >> 4;
    const int row0 = blockIdx.y * BM;
    const int col0 = blockIdx.x * BN;

    unsigned long long acc2[TM][TNP] = {};

    for (int k0 = 0; k0 < K; k0 += BK) {
        #pragma unroll
        for (int t = 0; t < 2; ++t) {
            const int li = tid + t * 256;
            const int r  = li >> 2;
            const int kc = (li & 3) * 4;
            float4 v = make_float4(0.f, 0.f, 0.f, 0.f);
            if (row0 + r < Mr) {
                const size_t off = (size_t)(row0 + r) * K + k0 + kc;
                v = *(const float4*)(A + off);
                if (FUSE) {
                    const float4 w = *(const float4*)(A2 + off);
                    v.x = leaky(v.x) + leaky(w.x);
                    v.y = leaky(v.y) + leaky(w.y);
                    v.z = leaky(v.z) + leaky(w.z);
                    v.w = leaky(v.w) + leaky(w.w);
                }
            }
            As[kc + 0][r] = v.x; As[kc + 1][r] = v.y;
            As[kc + 2][r] = v.z; As[kc + 3][r] = v.w;
        }
        #pragma unroll
        for (int t = 0; t < BSLOTS / 256; ++t) {
            const int li = tid + t * 256;
            const int r  = li / NT4;
            const int c  = (li % NT4) * 4;
            *(float4*)&Bs[r][c] =
                *(const float4*)(B + (size_t)(k0 + r) * Nc + col0 + c);
        }
        __syncthreads();

        #pragma unroll
        for (int k = 0; k < BK; ++k) {
            float a[TM];
            *(float4*)&a[0] = *(const float4*)&As[k][ty * TM];
            *(float4*)&a[4] = *(const float4*)&As[k][ty * TM + 4];

            unsigned long long a2[TM];
            #pragma unroll
            for (int i = 0; i < TM; ++i) a2[i] = pack_dup_f32(a[i]);

            unsigned long long b2[TNP];
            #pragma unroll
            for (int j = 0; j < TNP; j += 2) {
                const ulonglong2 t2 = *(const ulonglong2*)&Bs[k][tx * TN + j * 2];
                b2[j]     = t2.x;
                b2[j + 1] = t2.y;
            }

            #pragma unroll
            for (int i = 0; i < TM; ++i)
                #pragma unroll
                for (int j = 0; j < TNP; ++j)
                    ffma2(acc2[i][j], a2[i], b2[j]);
        }
        __syncthreads();
    }

    #pragma unroll
    for (int i = 0; i < TM; ++i) {
        const int r = row0 + ty * TM + i;
        if (r < Mr) {
            #pragma unroll
            for (int j = 0; j < TNP; j += 2) {
                ulonglong2 o;
                o.x = acc2[i][j];
                o.y = acc2[i][j + 1];
                *(ulonglong2*)(C + (size_t)r * Nc + col0 + tx * TN + j * 2) = o;
            }
        }
    }
}

// ---------------------------------------------------------------------------
// out[i] = leaky(a[i]) + leaky(b[i]), float4-vectorized  (final outputs only)
// ---------------------------------------------------------------------------
__global__ __launch_bounds__(256)
void combine_leaky_kernel(const float4* __restrict__ a, const float4* __restrict__ b,
                          float4* __restrict__ out, int n4)
{
    const int i = blockIdx.x * blockDim.x + threadIdx.x;
    if (i >= n4) return;
    const float4 av = a[i];
    const float4 bv = b[i];
    float4 o;
    o.x = leaky(av.x) + leaky(bv.x);
    o.y = leaky(av.y) + leaky(bv.y);
    o.z = leaky(av.z) + leaky(bv.z);
    o.w = leaky(av.w) + leaky(bv.w);
    out[i] = o;
}

static inline int cap_grid(long long g) { return (int)(g > 65535 ? 65535 : g); }

// ---------------------------------------------------------------------------
// Launch
// ---------------------------------------------------------------------------
extern "C" void kernel_launch(void* const* d_in, const int* in_sizes, int n_in,
                              void* d_out, int out_size)
{
    const float* x   = (const float*)d_in[0];
    const float* y   = (const float*)d_in[1];
    const float* W0  = (const float*)d_in[2];
    const float* W1  = (const float*)d_in[3];
    const int*   hht_r = (const int*)d_in[4];
    const int*   hht_c = (const int*)d_in[5];
    const float* hht_v = (const float*)d_in[6];
    const int*   h_r   = (const int*)d_in[7];
    const int*   h_c   = (const int*)d_in[8];
    const float* h_v   = (const float*)d_in[9];
    const int*   ht_r  = (const int*)d_in[10];
    const int*   ht_c  = (const int*)d_in[11];
    const float* ht_v  = (const float*)d_in[12];
    const int*   hth_r = (const int*)d_in[13];
    const int*   hth_c = (const int*)d_in[14];
    const float* hth_v = (const float*)d_in[15];

    const int nnz_hht = in_sizes[4];
    const int nnz_h   = in_sizes[7];
    const int nnz_ht  = in_sizes[10];
    const int nnz_hth = in_sizes[13];

    float *xw0, *yw0, *sa, *sb, *sc, *sd, *xw1, *yw1;
    cudaGetSymbolAddress((void**)&xw0, g_xw0);
    cudaGetSymbolAddress((void**)&yw0, g_yw0);
    cudaGetSymbolAddress((void**)&sa,  g_sa);
    cudaGetSymbolAddress((void**)&sb,  g_sb);
    cudaGetSymbolAddress((void**)&sc,  g_sc);
    cudaGetSymbolAddress((void**)&sd,  g_sd);
    cudaGetSymbolAddress((void**)&xw1, g_xw1);
    cudaGetSymbolAddress((void**)&yw1, g_yw1);

    int *cnt_hht, *rp_hht, *cur_hht, *aux_hht, *pc_hht; float* pv_hht;
    int *cnt_h,   *rp_h,   *cur_h,   *aux_h,   *pc_h;   float* pv_h;
    int *cnt_ht,  *rp_ht,  *cur_ht,  *aux_ht,  *pc_ht;  float* pv_ht;
    int *cnt_hth, *rp_hth, *cur_hth, *aux_hth, *pc_hth; float* pv_hth;
    cudaGetSymbolAddress((void**)&cnt_hht, g_cnt_hht);
    cudaGetSymbolAddress((void**)&rp_hht,  g_rp_hht);
    cudaGetSymbolAddress((void**)&cur_hht, g_cur_hht);
    cudaGetSymbolAddress((void**)&aux_hht, g_aux_hht);
    cudaGetSymbolAddress((void**)&pc_hht,  g_pc_hht);
    cudaGetSymbolAddress((void**)&pv_hht,  g_pv_hht);
    cudaGetSymbolAddress((void**)&cnt_h,   g_cnt_h);
    cudaGetSymbolAddress((void**)&rp_h,    g_rp_h);
    cudaGetSymbolAddress((void**)&cur_h,   g_cur_h);
    cudaGetSymbolAddress((void**)&aux_h,   g_aux_h);
    cudaGetSymbolAddress((void**)&pc_h,    g_pc_h);
    cudaGetSymbolAddress((void**)&pv_h,    g_pv_h);
    cudaGetSymbolAddress((void**)&cnt_ht,  g_cnt_ht);
    cudaGetSymbolAddress((void**)&rp_ht,   g_rp_ht);
    cudaGetSymbolAddress((void**)&cur_ht,  g_cur_ht);
    cudaGetSymbolAddress((void**)&aux_ht,  g_aux_ht);
    cudaGetSymbolAddress((void**)&pc_ht,   g_pc_ht);
    cudaGetSymbolAddress((void**)&pv_ht,   g_pv_ht);
    cudaGetSymbolAddress((void**)&cnt_hth, g_cnt_hth);
    cudaGetSymbolAddress((void**)&rp_hth,  g_rp_hth);
    cudaGetSymbolAddress((void**)&cur_hth, g_cur_hth);
    cudaGetSymbolAddress((void**)&aux_hth, g_aux_hth);
    cudaGetSymbolAddress((void**)&pc_hth,  g_pc_hth);
    cudaGetSymbolAddress((void**)&pv_hth,  g_pv_hth);

    float* out = (float*)d_out;

    const int NB1024_N = (NROWS + 1023) / 1024;   // 49
    const int NB1024_M = (MROWS + 1023) / 1024;   // 20

    // ---- Layer 0 dense (runs while nothing depends on CSR yet) ----
    {
        dim3 gx(HIDC / 128, (NROWS + 127) / 128);
        gemm128_kernel<128, 8, false><<<gx, 256>>>(x, nullptr, W0, xw0, NROWS, HIDC, HIDC);
        dim3 gy(HIDC / 128, (MROWS + 127) / 128);
        gemm128_kernel<128, 8, false><<<gy, 256>>>(y, nullptr, W0, yw0, MROWS, HIDC, HIDC);
    }

    // ---- Build CSR for all four matrices (reused by both layers) ----
    zero_counts_kernel<<<(NROWS + 255) / 256, 256>>>();
    hist_kernel<<<cap_grid((nnz_hht + 255) / 256), 256>>>(hht_r, nnz_hht, cnt_hht);
    hist_kernel<<<cap_grid((nnz_h   + 255) / 256), 256>>>(h_r,   nnz_h,   cnt_h);
    hist_kernel<<<cap_grid((nnz_ht  + 255) / 256), 256>>>(ht_r,  nnz_ht,  cnt_ht);
    hist_kernel<<<cap_grid((nnz_hth + 255) / 256), 256>>>(hth_r, nnz_hth, cnt_hth);

    scan1_kernel<<<NB1024_N, 1024>>>(cnt_hht, rp_hht, aux_hht, NROWS);
    scan1_kernel<<<NB1024_N, 1024>>>(cnt_h,   rp_h,   aux_h,   NROWS);
    scan1_kernel<<<NB1024_M, 1024>>>(cnt_ht,  rp_ht,  aux_ht,  MROWS);
    scan1_kernel<<<NB1024_M, 1024>>>(cnt_hth, rp_hth, aux_hth, MROWS);

    scan2_kernel<<<1, 64>>>(aux_hht, NB1024_N);
    scan2_kernel<<<1, 64>>>(aux_h,   NB1024_N);
    scan2_kernel<<<1, 64>>>(aux_ht,  NB1024_M);
    scan2_kernel<<<1, 64>>>(aux_hth, NB1024_M);

    scan3_kernel<<<NB1024_N, 1024>>>(cnt_hht, rp_hht, cur_hht, aux_hht, NROWS);
    scan3_kernel<<<NB1024_N, 1024>>>(cnt_h,   rp_h,   cur_h,   aux_h,   NROWS);
    scan3_kernel<<<NB1024_M, 1024>>>(cnt_ht,  rp_ht,  cur_ht,  aux_ht,  MROWS);
    scan3_kernel<<<NB1024_M, 1024>>>(cnt_hth, rp_hth, cur_hth, aux_hth, MROWS);

    scatter_kernel<<<cap_grid((nnz_hht + 255) / 256), 256>>>(hht_r, hht_c, hht_v, nnz_hht, cur_hht, pc_hht, pv_hht);
    scatter_kernel<<<cap_grid((nnz_h   + 255) / 256), 256>>>(h_r,   h_c,   h_v,   nnz_h,   cur_h,   pc_h,   pv_h);
    scatter_kernel<<<cap_grid((nnz_ht  + 255) / 256), 256>>>(ht_r,  ht_c,  ht_v,  nnz_ht,  cur_ht,  pc_ht,  pv_ht);
    scatter_kernel<<<cap_grid((nnz_hth + 255) / 256), 256>>>(hth_r, hth_c, hth_v, nnz_hth, cur_hth, pc_hth, pv_hth);

    // ---- Layer 0 sparse: CSR SpMM, K=256 (no memsets needed) ----
    spmm_csr256_kernel<<<NROWS / 8, 256>>>(rp_hht, pc_hht, pv_hht, xw0, sa, NROWS);
    spmm_csr256_kernel<<<NROWS / 8, 256>>>(rp_h,   pc_h,   pv_h,   yw0, sb, NROWS);
    spmm_csr256_kernel<<<MROWS / 8, 256>>>(rp_ht,  pc_ht,  pv_ht,  xw0, sc, MROWS);
    spmm_csr256_kernel<<<MROWS / 8, 256>>>(rp_hth, pc_hth, pv_hth, yw0, sd, MROWS);

    // ---- Layer 1 dense (mid-layer combine fused into A-load) ----
    {
        dim3 gx(OUTC / 64, (NROWS + 127) / 128);
        gemm128_kernel<64, 4, true><<<gx, 256>>>(sa, sb, W1, xw1, NROWS, HIDC, OUTC);
        dim3 gy(OUTC / 64, (MROWS + 127) / 128);
        gemm128_kernel<64, 4, true><<<gy, 256>>>(sc, sd, W1, yw1, MROWS, HIDC, OUTC);
    }

    // ---- Layer 1 sparse: CSR SpMM, K=64, reuse sa..sd ----
    spmm_csr64_kernel<<<NROWS / 16, 256>>>(rp_hht, pc_hht, pv_hht, xw1, sa, NROWS);
    spmm_csr64_kernel<<<NROWS / 16, 256>>>(rp_h,   pc_h,   pv_h,   yw1, sb, NROWS);
    spmm_csr64_kernel<<<MROWS / 16, 256>>>(rp_ht,  pc_ht,  pv_ht,  xw1, sc, MROWS);
    spmm_csr64_kernel<<<MROWS / 16, 256>>>(rp_hth, pc_hth, pv_hth, yw1, sd, MROWS);

    // ---- Output: x_out = leaky(sa)+leaky(sb), y_out = leaky(sc)+leaky(sd) ----
    {
        int n4x = NROWS * OUTC / 4;
        combine_leaky_kernel<<<(n4x + 255) / 256, 256>>>((const float4*)sa, (const float4*)sb, (float4*)out, n4x);
        int n4y = MROWS * OUTC / 4;
        combine_leaky_kernel<<<(n4y + 255) / 256, 256>>>((const float4*)sc, (const float4*)sd,
                                                         (float4*)(out + (size_t)NROWS * OUTC), n4y);
    }
}

// round 8
// speedup vs baseline: 1.8350x; 1.0531x over previous
#include <cuda_runtime.h>
#include <cstdint>
#include <cstddef>

// Problem constants (match reference)
#define NROWS 50000
#define MROWS 20000
#define HIDC  256
#define OUTC  64
#define NNZ_HHT 1600000
#define NNZ_H   1000000
#define NNZ_HT  1000000
#define NNZ_HTH  640000

#define NB_N 49   // ceil(NROWS/1024)
#define NB_M 20   // ceil(MROWS/1024)

// ---------------------------------------------------------------------------
// Static device scratch (allocation-free rule: __device__ globals)
// ---------------------------------------------------------------------------
__device__ __align__(16) float g_xw0[(size_t)NROWS * HIDC];   // x @ W0
__device__ __align__(16) float g_yw0[(size_t)MROWS * HIDC];   // y @ W0
__device__ __align__(16) float g_x1 [(size_t)NROWS * HIDC];   // leaky(hht_l)+leaky(h_l)
__device__ __align__(16) float g_y1 [(size_t)MROWS * HIDC];   // leaky(ht_l)+leaky(hth_l)
__device__ __align__(16) float g_xw1[(size_t)NROWS * OUTC];   // x1 @ W1
__device__ __align__(16) float g_yw1[(size_t)MROWS * OUTC];   // y1 @ W1

// CSR structures (built on device each launch)
__device__ int  g_cnt_hht[NROWS],  g_rp_hht[NROWS + 1],  g_cur_hht[NROWS];
__device__ int  g_cnt_h  [NROWS],  g_rp_h  [NROWS + 1],  g_cur_h  [NROWS];
__device__ int  g_cnt_ht [MROWS],  g_rp_ht [MROWS + 1],  g_cur_ht [MROWS];
__device__ int  g_cnt_hth[MROWS],  g_rp_hth[MROWS + 1],  g_cur_hth[MROWS];
__device__ int  g_aux_hht[64], g_aux_h[64], g_aux_ht[64], g_aux_hth[64];
// packed (col, float_as_int(val)) per edge
__device__ int2 g_pe_hht[NNZ_HHT];
__device__ int2 g_pe_h  [NNZ_H];
__device__ int2 g_pe_ht [NNZ_HT];
__device__ int2 g_pe_hth[NNZ_HTH];

__device__ __forceinline__ float leaky(float v) {
    return v >= 0.0f ? v : 0.2f * v;
}
__device__ __forceinline__ float4 leaky4(float4 v) {
    return make_float4(leaky(v.x), leaky(v.y), leaky(v.z), leaky(v.w));
}

// ---- packed fp32x2 helpers (Blackwell FFMA2 path) ----
__device__ __forceinline__ unsigned long long pack_dup_f32(float x) {
#if defined(__CUDA_ARCH__) && (__CUDA_ARCH__ >= 1000)
    unsigned long long r;
    asm("mov.b64 %0, {%1, %1};" : "=l"(r) : "r"(__float_as_uint(x)));
    return r;
#else
    union { unsigned long long u; float f[2]; } t;
    t.f[0] = x; t.f[1] = x;
    return t.u;
#endif
}

__device__ __forceinline__ void ffma2(unsigned long long& acc,
                                      unsigned long long a, unsigned long long b) {
#if defined(__CUDA_ARCH__) && (__CUDA_ARCH__ >= 1000)
    asm("fma.rn.f32x2 %0, %1, %2, %0;" : "+l"(acc) : "l"(a), "l"(b));
#else
    union U { unsigned long long u; float f[2]; };
    U ua, ub, uc; ua.u = a; ub.u = b; uc.u = acc;
    uc.f[0] = fmaf(ua.f[0], ub.f[0], uc.f[0]);
    uc.f[1] = fmaf(ua.f[1], ub.f[1], uc.f[1]);
    acc = uc.u;
#endif
}

// ===========================================================================
// CSR build kernels
// ===========================================================================
__global__ __launch_bounds__(256)
void zero_counts_kernel()
{
    const int i = blockIdx.x * blockDim.x + threadIdx.x;
    if (i < NROWS) { g_cnt_hht[i] = 0; g_cnt_h[i] = 0; }
    if (i < MROWS) { g_cnt_ht[i]  = 0; g_cnt_hth[i] = 0; }
}

__global__ __launch_bounds__(256)
void hist_kernel(const int* __restrict__ rows, int nnz, int* __restrict__ cnt)
{
    for (int e = blockIdx.x * blockDim.x + threadIdx.x; e < nnz;
         e += gridDim.x * blockDim.x)
        atomicAdd(cnt + rows[e], 1);
}

// pass 1: per-block exclusive scan of counts; aux[b] = block sum
__global__ __launch_bounds__(1024)
void scan1_kernel(const int* __restrict__ cnt, int* __restrict__ rp,
                  int* __restrict__ aux, int n)
{
    __shared__ int s[1024];
    const int tid = threadIdx.x;
    const int i = blockIdx.x * 1024 + tid;
    const int v = (i < n) ? cnt[i] : 0;
    s[tid] = v;
    __syncthreads();
    for (int off = 1; off < 1024; off <<= 1) {
        int t = (tid >= off) ? s[tid - off] : 0;
        __syncthreads();
        s[tid] += t;
        __syncthreads();
    }
    if (i < n) rp[i] = s[tid] - v;
    if (tid == 1023) aux[blockIdx.x] = s[1023];
}

// pass 2 (all four aux arrays in one launch, block per array)
__global__ __launch_bounds__(64)
void scan2_all_kernel()
{
    int* aux; int naux;
    switch (blockIdx.x) {
        case 0:  aux = g_aux_hht; naux = NB_N; break;
        case 1:  aux = g_aux_h;   naux = NB_N; break;
        case 2:  aux = g_aux_ht;  naux = NB_M; break;
        default: aux = g_aux_hth; naux = NB_M; break;
    }
    __shared__ int s[64];
    const int tid = threadIdx.x;
    const int v = (tid < naux) ? aux[tid] : 0;
    s[tid] = v;
    __syncthreads();
    for (int off = 1; off < 64; off <<= 1) {
        int t = (tid >= off) ? s[tid - off] : 0;
        __syncthreads();
        s[tid] += t;
        __syncthreads();
    }
    if (tid < naux) aux[tid] = s[tid] - v;
}

// pass 3: add block offsets; copy rowptr into cursor; write rp[n]
__global__ __launch_bounds__(1024)
void scan3_kernel(const int* __restrict__ cnt, int* __restrict__ rp,
                  int* __restrict__ cur, const int* __restrict__ aux, int n)
{
    const int tid = threadIdx.x;
    const int i = blockIdx.x * 1024 + tid;
    if (i < n) {
        const int r = rp[i] + aux[blockIdx.x];
        rp[i] = r;
        cur[i] = r;
        if (i == n - 1) rp[n] = r + cnt[i];
    }
}

__global__ __launch_bounds__(256)
void scatter_kernel(const int* __restrict__ rows, const int* __restrict__ cols,
                    const float* __restrict__ vals, int nnz,
                    int* __restrict__ cur, int2* __restrict__ pe)
{
    for (int e = blockIdx.x * blockDim.x + threadIdx.x; e < nnz;
         e += gridDim.x * blockDim.x) {
        const int r = rows[e];
        const int pos = atomicAdd(cur + r, 1);
        pe[pos] = make_int2(cols[e], __float_as_int(vals[e]));
    }
}

// ===========================================================================
// Merged CSR SpMM, K=256: one warp per destination row, TWO matrices
// (same row space, different sources); writes leaky(sumA)+leaky(sumB).
// 8 warps/block. nrows divisible by 8.
// ===========================================================================
__global__ __launch_bounds__(256)
void spmm2_csr256_kernel(const int* __restrict__ rpA, const int2* __restrict__ peA,
                         const float* __restrict__ srcA,
                         const int* __restrict__ rpB, const int2* __restrict__ peB,
                         const float* __restrict__ srcB,
                         float* __restrict__ dst, int nrows)
{
    const int row  = blockIdx.x * 8 + (threadIdx.x >> 5);
    const int lane = threadIdx.x & 31;
    if (row >= nrows) return;

    float4 a0 = make_float4(0.f, 0.f, 0.f, 0.f);
    float4 a1 = make_float4(0.f, 0.f, 0.f, 0.f);
    {
        const int s0 = __ldg(rpA + row);
        const int s1 = __ldg(rpA + row + 1);
        for (int j0 = s0; j0 < s1; j0 += 32) {
            int2 e = make_int2(0, 0);
            if (j0 + lane < s1) e = __ldg(peA + j0 + lane);
            const int cnt = min(32, s1 - j0);
            for (int t = 0; t < cnt; ++t) {
                const int   ct = __shfl_sync(0xffffffffu, e.x, t);
                const float vt = __int_as_float(__shfl_sync(0xffffffffu, e.y, t));
                const float4* sp = (const float4*)(srcA + (size_t)ct * HIDC);
                const float4 x0 = __ldg(sp + lane);
                const float4 x1 = __ldg(sp + 32 + lane);
                a0.x += vt * x0.x; a0.y += vt * x0.y; a0.z += vt * x0.z; a0.w += vt * x0.w;
                a1.x += vt * x1.x; a1.y += vt * x1.y; a1.z += vt * x1.z; a1.w += vt * x1.w;
            }
        }
    }

    float4 b0 = make_float4(0.f, 0.f, 0.f, 0.f);
    float4 b1 = make_float4(0.f, 0.f, 0.f, 0.f);
    {
        const int s0 = __ldg(rpB + row);
        const int s1 = __ldg(rpB + row + 1);
        for (int j0 = s0; j0 < s1; j0 += 32) {
            int2 e = make_int2(0, 0);
            if (j0 + lane < s1) e = __ldg(peB + j0 + lane);
            const int cnt = min(32, s1 - j0);
            for (int t = 0; t < cnt; ++t) {
                const int   ct = __shfl_sync(0xffffffffu, e.x, t);
                const float vt = __int_as_float(__shfl_sync(0xffffffffu, e.y, t));
                const float4* sp = (const float4*)(srcB + (size_t)ct * HIDC);
                const float4 x0 = __ldg(sp + lane);
                const float4 x1 = __ldg(sp + 32 + lane);
                b0.x += vt * x0.x; b0.y += vt * x0.y; b0.z += vt * x0.z; b0.w += vt * x0.w;
                b1.x += vt * x1.x; b1.y += vt * x1.y; b1.z += vt * x1.z; b1.w += vt * x1.w;
            }
        }
    }

    const float4 la0 = leaky4(a0), la1 = leaky4(a1);
    const float4 lb0 = leaky4(b0), lb1 = leaky4(b1);
    float4* dp = (float4*)(dst + (size_t)row * HIDC);
    dp[lane]      = make_float4(la0.x + lb0.x, la0.y + lb0.y, la0.z + lb0.z, la0.w + lb0.w);
    dp[32 + lane] = make_float4(la1.x + lb1.x, la1.y + lb1.y, la1.z + lb1.z, la1.w + lb1.w);
}

// ===========================================================================
// Merged CSR SpMM, K=64: 16 lanes per row; writes leaky(sumA)+leaky(sumB).
// 16 rows/block. nrows divisible by 16.
// ===========================================================================
__global__ __launch_bounds__(256)
void spmm2_csr64_kernel(const int* __restrict__ rpA, const int2* __restrict__ peA,
                        const float* __restrict__ srcA,
                        const int* __restrict__ rpB, const int2* __restrict__ peB,
                        const float* __restrict__ srcB,
                        float* __restrict__ dst, int nrows)
{
    const int lane32 = threadIdx.x & 31;
    const int lane16 = threadIdx.x & 15;
    const int row    = blockIdx.x * 16 + (threadIdx.x >> 4);
    if (row >= nrows) return;

    const unsigned gmask = 0xFFFFu << (lane32 & 16);

    float4 a = make_float4(0.f, 0.f, 0.f, 0.f);
    {
        const int s0 = __ldg(rpA + row);
        const int s1 = __ldg(rpA + row + 1);
        for (int j0 = s0; j0 < s1; j0 += 16) {
            int2 e = make_int2(0, 0);
            if (j0 + lane16 < s1) e = __ldg(peA + j0 + lane16);
            const int cnt = min(16, s1 - j0);
            for (int t = 0; t < cnt; ++t) {
                const int   ct = __shfl_sync(gmask, e.x, t, 16);
                const float vt = __int_as_float(__shfl_sync(gmask, e.y, t, 16));
                const float4 x = __ldg((const float4*)(srcA + (size_t)ct * OUTC) + lane16);
                a.x += vt * x.x; a.y += vt * x.y; a.z += vt * x.z; a.w += vt * x.w;
            }
        }
    }

    float4 b = make_float4(0.f, 0.f, 0.f, 0.f);
    {
        const int s0 = __ldg(rpB + row);
        const int s1 = __ldg(rpB + row + 1);
        for (int j0 = s0; j0 < s1; j0 += 16) {
            int2 e = make_int2(0, 0);
            if (j0 + lane16 < s1) e = __ldg(peB + j0 + lane16);
            const int cnt = min(16, s1 - j0);
            for (int t = 0; t < cnt; ++t) {
                const int   ct = __shfl_sync(gmask, e.x, t, 16);
                const float vt = __int_as_float(__shfl_sync(gmask, e.y, t, 16));
                const float4 x = __ldg((const float4*)(srcB + (size_t)ct * OUTC) + lane16);
                b.x += vt * x.x; b.y += vt * x.y; b.z += vt * x.z; b.w += vt * x.w;
            }
        }
    }

    const float4 la = leaky4(a), lb = leaky4(b);
    *((float4*)(dst + (size_t)row * OUTC) + lane16) =
        make_float4(la.x + lb.x, la.y + lb.y, la.z + lb.z, la.w + lb.w);
}

// ===========================================================================
// Tiled fp32 GEMM with packed f32x2 accumulation (FFMA2).
// ===========================================================================
template<int BN, int TN>
__global__ __launch_bounds__(256)
void gemm128_kernel(const float* __restrict__ A, const float* __restrict__ B,
                    float* __restrict__ C, int Mr, int K, int Nc)
{
    constexpr int BM = 128, BK = 16, TM = 8;
    constexpr int TNP = TN / 2;
    constexpr int NT4 = BN / 4;
    constexpr int BSLOTS = BK * NT4;

    __shared__ float As[BK][BM];
    __shared__ float Bs[BK][BN];

    const int tid  = threadIdx.x;
    const int tx   = tid & 15;
    const int ty   = tid >> 4;
    const int row0 = blockIdx.y * BM;
    const int col0 = blockIdx.x * BN;

    unsigned long long acc2[TM][TNP] = {};

    for (int k0 = 0; k0 < K; k0 += BK) {
        #pragma unroll
        for (int t = 0; t < 2; ++t) {
            const int li = tid + t * 256;
            const int r  = li >> 2;
            const int kc = (li & 3) * 4;
            float4 v = make_float4(0.f, 0.f, 0.f, 0.f);
            if (row0 + r < Mr)
                v = *(const float4*)(A + (size_t)(row0 + r) * K + k0 + kc);
            As[kc + 0][r] = v.x; As[kc + 1][r] = v.y;
            As[kc + 2][r] = v.z; As[kc + 3][r] = v.w;
        }
        #pragma unroll
        for (int t = 0; t < BSLOTS / 256; ++t) {
            const int li = tid + t * 256;
            const int r  = li / NT4;
            const int c  = (li % NT4) * 4;
            *(float4*)&Bs[r][c] =
                *(const float4*)(B + (size_t)(k0 + r) * Nc + col0 + c);
        }
        __syncthreads();

        #pragma unroll
        for (int k = 0; k < BK; ++k) {
            float a[TM];
            *(float4*)&a[0] = *(const float4*)&As[k][ty * TM];
            *(float4*)&a[4] = *(const float4*)&As[k][ty * TM + 4];

            unsigned long long a2[TM];
            #pragma unroll
            for (int i = 0; i < TM; ++i) a2[i] = pack_dup_f32(a[i]);

            unsigned long long b2[TNP];
            #pragma unroll
            for (int j = 0; j < TNP; j += 2) {
                const ulonglong2 t2 = *(const ulonglong2*)&Bs[k][tx * TN + j * 2];
                b2[j]     = t2.x;
                b2[j + 1] = t2.y;
            }

            #pragma unroll
            for (int i = 0; i < TM; ++i)
                #pragma unroll
                for (int j = 0; j < TNP; ++j)
                    ffma2(acc2[i][j], a2[i], b2[j]);
        }
        __syncthreads();
    }

    #pragma unroll
    for (int i = 0; i < TM; ++i) {
        const int r = row0 + ty * TM + i;
        if (r < Mr) {
            #pragma unroll
            for (int j = 0; j < TNP; j += 2) {
                ulonglong2 o;
                o.x = acc2[i][j];
                o.y = acc2[i][j + 1];
                *(ulonglong2*)(C + (size_t)r * Nc + col0 + tx * TN + j * 2) = o;
            }
        }
    }
}

static inline int cap_grid(long long g) { return (int)(g > 65535 ? 65535 : g); }

// ---------------------------------------------------------------------------
// Launch
// ---------------------------------------------------------------------------
extern "C" void kernel_launch(void* const* d_in, const int* in_sizes, int n_in,
                              void* d_out, int out_size)
{
    const float* x   = (const float*)d_in[0];
    const float* y   = (const float*)d_in[1];
    const float* W0  = (const float*)d_in[2];
    const float* W1  = (const float*)d_in[3];
    const int*   hht_r = (const int*)d_in[4];
    const int*   hht_c = (const int*)d_in[5];
    const float* hht_v = (const float*)d_in[6];
    const int*   h_r   = (const int*)d_in[7];
    const int*   h_c   = (const int*)d_in[8];
    const float* h_v   = (const float*)d_in[9];
    const int*   ht_r  = (const int*)d_in[10];
    const int*   ht_c  = (const int*)d_in[11];
    const float* ht_v  = (const float*)d_in[12];
    const int*   hth_r = (const int*)d_in[13];
    const int*   hth_c = (const int*)d_in[14];
    const float* hth_v = (const float*)d_in[15];

    const int nnz_hht = in_sizes[4];
    const int nnz_h   = in_sizes[7];
    const int nnz_ht  = in_sizes[10];
    const int nnz_hth = in_sizes[13];

    float *xw0, *yw0, *x1, *y1, *xw1, *yw1;
    cudaGetSymbolAddress((void**)&xw0, g_xw0);
    cudaGetSymbolAddress((void**)&yw0, g_yw0);
    cudaGetSymbolAddress((void**)&x1,  g_x1);
    cudaGetSymbolAddress((void**)&y1,  g_y1);
    cudaGetSymbolAddress((void**)&xw1, g_xw1);
    cudaGetSymbolAddress((void**)&yw1, g_yw1);

    int *cnt_hht, *rp_hht, *cur_hht, *aux_hht; int2* pe_hht;
    int *cnt_h,   *rp_h,   *cur_h,   *aux_h;   int2* pe_h;
    int *cnt_ht,  *rp_ht,  *cur_ht,  *aux_ht;  int2* pe_ht;
    int *cnt_hth, *rp_hth, *cur_hth, *aux_hth; int2* pe_hth;
    cudaGetSymbolAddress((void**)&cnt_hht, g_cnt_hht);
    cudaGetSymbolAddress((void**)&rp_hht,  g_rp_hht);
    cudaGetSymbolAddress((void**)&cur_hht, g_cur_hht);
    cudaGetSymbolAddress((void**)&aux_hht, g_aux_hht);
    cudaGetSymbolAddress((void**)&pe_hht,  g_pe_hht);
    cudaGetSymbolAddress((void**)&cnt_h,   g_cnt_h);
    cudaGetSymbolAddress((void**)&rp_h,    g_rp_h);
    cudaGetSymbolAddress((void**)&cur_h,   g_cur_h);
    cudaGetSymbolAddress((void**)&aux_h,   g_aux_h);
    cudaGetSymbolAddress((void**)&pe_h,    g_pe_h);
    cudaGetSymbolAddress((void**)&cnt_ht,  g_cnt_ht);
    cudaGetSymbolAddress((void**)&rp_ht,   g_rp_ht);
    cudaGetSymbolAddress((void**)&cur_ht,  g_cur_ht);
    cudaGetSymbolAddress((void**)&aux_ht,  g_aux_ht);
    cudaGetSymbolAddress((void**)&pe_ht,   g_pe_ht);
    cudaGetSymbolAddress((void**)&cnt_hth, g_cnt_hth);
    cudaGetSymbolAddress((void**)&rp_hth,  g_rp_hth);
    cudaGetSymbolAddress((void**)&cur_hth, g_cur_hth);
    cudaGetSymbolAddress((void**)&aux_hth, g_aux_hth);
    cudaGetSymbolAddress((void**)&pe_hth,  g_pe_hth);

    float* out = (float*)d_out;

    // ---- Layer 0 dense: xW0 [N,256], yW0 [M,256] ----
    {
        dim3 gx(HIDC / 128, (NROWS + 127) / 128);
        gemm128_kernel<128, 8><<<gx, 256>>>(x, W0, xw0, NROWS, HIDC, HIDC);
        dim3 gy(HIDC / 128, (MROWS + 127) / 128);
        gemm128_kernel<128, 8><<<gy, 256>>>(y, W0, yw0, MROWS, HIDC, HIDC);
    }

    // ---- Build CSR for all four matrices (reused by both layers) ----
    zero_counts_kernel<<<(NROWS + 255) / 256, 256>>>();
    hist_kernel<<<cap_grid((nnz_hht + 255) / 256), 256>>>(hht_r, nnz_hht, cnt_hht);
    hist_kernel<<<cap_grid((nnz_h   + 255) / 256), 256>>>(h_r,   nnz_h,   cnt_h);
    hist_kernel<<<cap_grid((nnz_ht  + 255) / 256), 256>>>(ht_r,  nnz_ht,  cnt_ht);
    hist_kernel<<<cap_grid((nnz_hth + 255) / 256), 256>>>(hth_r, nnz_hth, cnt_hth);

    scan1_kernel<<<NB_N, 1024>>>(cnt_hht, rp_hht, aux_hht, NROWS);
    scan1_kernel<<<NB_N, 1024>>>(cnt_h,   rp_h,   aux_h,   NROWS);
    scan1_kernel<<<NB_M, 1024>>>(cnt_ht,  rp_ht,  aux_ht,  MROWS);
    scan1_kernel<<<NB_M, 1024>>>(cnt_hth, rp_hth, aux_hth, MROWS);

    scan2_all_kernel<<<4, 64>>>();

    scan3_kernel<<<NB_N, 1024>>>(cnt_hht, rp_hht, cur_hht, aux_hht, NROWS);
    scan3_kernel<<<NB_N, 1024>>>(cnt_h,   rp_h,   cur_h,   aux_h,   NROWS);
    scan3_kernel<<<NB_M, 1024>>>(cnt_ht,  rp_ht,  cur_ht,  aux_ht,  MROWS);
    scan3_kernel<<<NB_M, 1024>>>(cnt_hth, rp_hth, cur_hth, aux_hth, MROWS);

    scatter_kernel<<<cap_grid((nnz_hht + 255) / 256), 256>>>(hht_r, hht_c, hht_v, nnz_hht, cur_hht, pe_hht);
    scatter_kernel<<<cap_grid((nnz_h   + 255) / 256), 256>>>(h_r,   h_c,   h_v,   nnz_h,   cur_h,   pe_h);
    scatter_kernel<<<cap_grid((nnz_ht  + 255) / 256), 256>>>(ht_r,  ht_c,  ht_v,  nnz_ht,  cur_ht,  pe_ht);
    scatter_kernel<<<cap_grid((nnz_hth + 255) / 256), 256>>>(hth_r, hth_c, hth_v, nnz_hth, cur_hth, pe_hth);

    // ---- Layer 0 sparse (merged pairs, combine fused into store):
    //      x1 = leaky(spmm(hht, xw0)) + leaky(spmm(h, yw0))
    //      y1 = leaky(spmm(ht,  xw0)) + leaky(spmm(hth, yw0)) ----
    spmm2_csr256_kernel<<<NROWS / 8, 256>>>(rp_hht, pe_hht, xw0, rp_h,   pe_h,   yw0, x1, NROWS);
    spmm2_csr256_kernel<<<MROWS / 8, 256>>>(rp_ht,  pe_ht,  xw0, rp_hth, pe_hth, yw0, y1, MROWS);

    // ---- Layer 1 dense: xw1 = x1 @ W1, yw1 = y1 @ W1 ----
    {
        dim3 gx(OUTC / 64, (NROWS + 127) / 128);
        gemm128_kernel<64, 4><<<gx, 256>>>(x1, W1, xw1, NROWS, HIDC, OUTC);
        dim3 gy(OUTC / 64, (MROWS + 127) / 128);
        gemm128_kernel<64, 4><<<gy, 256>>>(y1, W1, yw1, MROWS, HIDC, OUTC);
    }

    // ---- Layer 1 sparse (merged pairs), writes final output directly ----
    spmm2_csr64_kernel<<<NROWS / 16, 256>>>(rp_hht, pe_hht, xw1, rp_h,   pe_h,   yw1,
                                            out, NROWS);
    spmm2_csr64_kernel<<<MROWS / 16, 256>>>(rp_ht,  pe_ht,  xw1, rp_hth, pe_hth, yw1,
                                            out + (size_t)NROWS * OUTC, MROWS);
}

// round 10
// speedup vs baseline: 1.9106x; 1.0412x over previous
#include <cuda_runtime.h>
#include <cstdint>
#include <cstddef>

// Problem constants (match reference)
#define NROWS 50000
#define MROWS 20000
#define HIDC  256
#define OUTC  64
#define NNZ_HHT 1600000
#define NNZ_H   1000000
#define NNZ_HT  1000000
#define NNZ_HTH  640000

#define NB_N 49   // ceil(NROWS/1024)
#define NB_M 20   // ceil(MROWS/1024)

// ---------------------------------------------------------------------------
// Static device scratch (allocation-free rule: __device__ globals)
// ---------------------------------------------------------------------------
__device__ __align__(16) float g_xw0[(size_t)NROWS * HIDC];   // x @ W0
__device__ __align__(16) float g_yw0[(size_t)MROWS * HIDC];   // y @ W0
__device__ __align__(16) float g_x1 [(size_t)NROWS * HIDC];   // leaky(hht_l)+leaky(h_l)
__device__ __align__(16) float g_y1 [(size_t)MROWS * HIDC];   // leaky(ht_l)+leaky(hth_l)
__device__ __align__(16) float g_xw1[(size_t)NROWS * OUTC];   // x1 @ W1
__device__ __align__(16) float g_yw1[(size_t)MROWS * OUTC];   // y1 @ W1

// CSR structures (built on device each launch)
__device__ int  g_cnt_hht[NROWS],  g_rp_hht[NROWS + 1],  g_cur_hht[NROWS];
__device__ int  g_cnt_h  [NROWS],  g_rp_h  [NROWS + 1],  g_cur_h  [NROWS];
__device__ int  g_cnt_ht [MROWS],  g_rp_ht [MROWS + 1],  g_cur_ht [MROWS];
__device__ int  g_cnt_hth[MROWS],  g_rp_hth[MROWS + 1],  g_cur_hth[MROWS];
__device__ int  g_aux_hht[64], g_aux_h[64], g_aux_ht[64], g_aux_hth[64];
// packed (col, float_as_int(val)) per edge
__device__ int2 g_pe_hht[NNZ_HHT];
__device__ int2 g_pe_h  [NNZ_H];
__device__ int2 g_pe_ht [NNZ_HT];
__device__ int2 g_pe_hth[NNZ_HTH];

__device__ __forceinline__ float leaky(float v) {
    return v >= 0.0f ? v : 0.2f * v;
}
__device__ __forceinline__ float4 leaky4(float4 v) {
    return make_float4(leaky(v.x), leaky(v.y), leaky(v.z), leaky(v.w));
}

// ---- packed fp32x2 helpers (Blackwell FFMA2 path) ----
__device__ __forceinline__ unsigned long long pack_dup_f32(float x) {
#if defined(__CUDA_ARCH__) && (__CUDA_ARCH__ >= 1000)
    unsigned long long r;
    asm("mov.b64 %0, {%1, %1};" : "=l"(r) : "r"(__float_as_uint(x)));
    return r;
#else
    union { unsigned long long u; float f[2]; } t;
    t.f[0] = x; t.f[1] = x;
    return t.u;
#endif
}

__device__ __forceinline__ void ffma2(unsigned long long& acc,
                                      unsigned long long a, unsigned long long b) {
#if defined(__CUDA_ARCH__) && (__CUDA_ARCH__ >= 1000)
    asm("fma.rn.f32x2 %0, %1, %2, %0;" : "+l"(acc) : "l"(a), "l"(b));
#else
    union U { unsigned long long u; float f[2]; };
    U ua, ub, uc; ua.u = a; ub.u = b; uc.u = acc;
    uc.f[0] = fmaf(ua.f[0], ub.f[0], uc.f[0]);
    uc.f[1] = fmaf(ua.f[1], ub.f[1], uc.f[1]);
    acc = uc.u;
#endif
}

// ===========================================================================
// CSR build kernels (fused across all four matrices)
// ===========================================================================
__global__ __launch_bounds__(256)
void zero_counts_kernel()
{
    const int i = blockIdx.x * blockDim.x + threadIdx.x;
    if (i < NROWS) { g_cnt_hht[i] = 0; g_cnt_h[i] = 0; }
    if (i < MROWS) { g_cnt_ht[i]  = 0; g_cnt_hth[i] = 0; }
}

__global__ __launch_bounds__(256)
void hist_all_kernel(const int* __restrict__ r0, int n0,
                     const int* __restrict__ r1, int n1,
                     const int* __restrict__ r2, int n2,
                     const int* __restrict__ r3, int n3)
{
    const int total = n0 + n1 + n2 + n3;
    for (int e = blockIdx.x * blockDim.x + threadIdx.x; e < total;
         e += gridDim.x * blockDim.x) {
        if (e < n0)                atomicAdd(g_cnt_hht + __ldcs(r0 + e), 1);
        else if (e < n0 + n1)      atomicAdd(g_cnt_h   + __ldcs(r1 + e - n0), 1);
        else if (e < n0 + n1 + n2) atomicAdd(g_cnt_ht  + __ldcs(r2 + e - n0 - n1), 1);
        else                       atomicAdd(g_cnt_hth + __ldcs(r3 + e - n0 - n1 - n2), 1);
    }
}

// pass 1: per-block exclusive scan of counts; aux[b] = block sum.
// Blocks [0,NB_N) hht, [NB_N,2NB_N) h, then NB_M each for ht, hth.
__global__ __launch_bounds__(1024)
void scan1_all_kernel()
{
    const int b = blockIdx.x;
    const int* cnt; int* rp; int* aux; int n; int lb;
    if (b < NB_N)              { cnt = g_cnt_hht; rp = g_rp_hht; aux = g_aux_hht; n = NROWS; lb = b; }
    else if (b < 2 * NB_N)     { cnt = g_cnt_h;   rp = g_rp_h;   aux = g_aux_h;   n = NROWS; lb = b - NB_N; }
    else if (b < 2*NB_N+NB_M)  { cnt = g_cnt_ht;  rp = g_rp_ht;  aux = g_aux_ht;  n = MROWS; lb = b - 2*NB_N; }
    else                       { cnt = g_cnt_hth; rp = g_rp_hth; aux = g_aux_hth; n = MROWS; lb = b - 2*NB_N - NB_M; }

    __shared__ int s[1024];
    const int tid = threadIdx.x;
    const int i = lb * 1024 + tid;
    const int v = (i < n) ? cnt[i] : 0;
    s[tid] = v;
    __syncthreads();
    for (int off = 1; off < 1024; off <<= 1) {
        int t = (tid >= off) ? s[tid - off] : 0;
        __syncthreads();
        s[tid] += t;
        __syncthreads();
    }
    if (i < n) rp[i] = s[tid] - v;
    if (tid == 1023) aux[lb] = s[1023];
}

// pass 2 (all four aux arrays, block per array)
__global__ __launch_bounds__(64)
void scan2_all_kernel()
{
    int* aux; int naux;
    switch (blockIdx.x) {
        case 0:  aux = g_aux_hht; naux = NB_N; break;
        case 1:  aux = g_aux_h;   naux = NB_N; break;
        case 2:  aux = g_aux_ht;  naux = NB_M; break;
        default: aux = g_aux_hth; naux = NB_M; break;
    }
    __shared__ int s[64];
    const int tid = threadIdx.x;
    const int v = (tid < naux) ? aux[tid] : 0;
    s[tid] = v;
    __syncthreads();
    for (int off = 1; off < 64; off <<= 1) {
        int t = (tid >= off) ? s[tid - off] : 0;
        __syncthreads();
        s[tid] += t;
        __syncthreads();
    }
    if (tid < naux) aux[tid] = s[tid] - v;
}

// pass 3: add block offsets; copy into cursor; thread 0 writes rp[n] = nnz.
__global__ __launch_bounds__(1024)
void scan3_all_kernel(int n0, int n1, int n2, int n3)
{
    const int b = blockIdx.x;
    int* rp; int* cur; const int* aux; int n; int lb; int nnz;
    if (b < NB_N)              { rp = g_rp_hht; cur = g_cur_hht; aux = g_aux_hht; n = NROWS; lb = b;                  nnz = n0; }
    else if (b < 2 * NB_N)     { rp = g_rp_h;   cur = g_cur_h;   aux = g_aux_h;   n = NROWS; lb = b - NB_N;           nnz = n1; }
    else if (b < 2*NB_N+NB_M)  { rp = g_rp_ht;  cur = g_cur_ht;  aux = g_aux_ht;  n = MROWS; lb = b - 2*NB_N;         nnz = n2; }
    else                       { rp = g_rp_hth; cur = g_cur_hth; aux = g_aux_hth; n = MROWS; lb = b - 2*NB_N - NB_M;  nnz = n3; }

    const int tid = threadIdx.x;
    const int i = lb * 1024 + tid;
    if (i < n) {
        const int r = rp[i] + aux[lb];
        rp[i] = r;
        cur[i] = r;
    }
    if (lb == 0 && tid == 0) rp[n] = nnz;
}

__global__ __launch_bounds__(256)
void scatter_all_kernel(const int* __restrict__ r0, const int* __restrict__ c0,
                        const float* __restrict__ v0, int n0,
                        const int* __restrict__ r1, const int* __restrict__ c1,
                        const float* __restrict__ v1, int n1,
                        const int* __restrict__ r2, const int* __restrict__ c2,
                        const float* __restrict__ v2, int n2,
                        const int* __restrict__ r3, const int* __restrict__ c3,
                        const float* __restrict__ v3, int n3)
{
    const int total = n0 + n1 + n2 + n3;
    for (int e = blockIdx.x * blockDim.x + threadIdx.x; e < total;
         e += gridDim.x * blockDim.x) {
        const int* rows; const int* cols; const float* vals;
        int* cur; int2* pe; int el;
        if (e < n0)                { rows = r0; cols = c0; vals = v0; cur = g_cur_hht; pe = g_pe_hht; el = e; }
        else if (e < n0 + n1)      { rows = r1; cols = c1; vals = v1; cur = g_cur_h;   pe = g_pe_h;   el = e - n0; }
        else if (e < n0 + n1 + n2) { rows = r2; cols = c2; vals = v2; cur = g_cur_ht;  pe = g_pe_ht;  el = e - n0 - n1; }
        else                       { rows = r3; cols = c3; vals = v3; cur = g_cur_hth; pe = g_pe_hth; el = e - n0 - n1 - n2; }
        const int r = __ldcs(rows + el);
        const int pos = atomicAdd(cur + r, 1);
        __stcs(pe + pos, make_int2(__ldcs(cols + el), __float_as_int(__ldcs(vals + el))));
    }
}

// ===========================================================================
// Merged CSR SpMM, K=256: one warp per destination row, TWO matrices
// (same row space, different sources); writes leaky(sumA)+leaky(sumB).
// Edge reads are evict-first (one-pass); output stores streaming.
// ===========================================================================
__global__ __launch_bounds__(256)
void spmm2_csr256_kernel(const int* __restrict__ rpA, const int2* __restrict__ peA,
                         const float* __restrict__ srcA,
                         const int* __restrict__ rpB, const int2* __restrict__ peB,
                         const float* __restrict__ srcB,
                         float* __restrict__ dst, int nrows)
{
    const int row  = blockIdx.x * 8 + (threadIdx.x >> 5);
    const int lane = threadIdx.x & 31;
    if (row >= nrows) return;

    float4 a0 = make_float4(0.f, 0.f, 0.f, 0.f);
    float4 a1 = make_float4(0.f, 0.f, 0.f, 0.f);
    {
        const int s0 = __ldg(rpA + row);
        const int s1 = __ldg(rpA + row + 1);
        for (int j0 = s0; j0 < s1; j0 += 32) {
            int2 e = make_int2(0, 0);
            if (j0 + lane < s1) e = __ldcs(peA + j0 + lane);
            const int cnt = min(32, s1 - j0);
            for (int t = 0; t < cnt; ++t) {
                const int   ct = __shfl_sync(0xffffffffu, e.x, t);
                const float vt = __int_as_float(__shfl_sync(0xffffffffu, e.y, t));
                const float4* sp = (const float4*)(srcA + (size_t)ct * HIDC);
                const float4 x0 = __ldg(sp + lane);
                const float4 x1 = __ldg(sp + 32 + lane);
                a0.x += vt * x0.x; a0.y += vt * x0.y; a0.z += vt * x0.z; a0.w += vt * x0.w;
                a1.x += vt * x1.x; a1.y += vt * x1.y; a1.z += vt * x1.z; a1.w += vt * x1.w;
            }
        }
    }

    float4 b0 = make_float4(0.f, 0.f, 0.f, 0.f);
    float4 b1 = make_float4(0.f, 0.f, 0.f, 0.f);
    {
        const int s0 = __ldg(rpB + row);
        const int s1 = __ldg(rpB + row + 1);
        for (int j0 = s0; j0 < s1; j0 += 32) {
            int2 e = make_int2(0, 0);
            if (j0 + lane < s1) e = __ldcs(peB + j0 + lane);
            const int cnt = min(32, s1 - j0);
            for (int t = 0; t < cnt; ++t) {
                const int   ct = __shfl_sync(0xffffffffu, e.x, t);
                const float vt = __int_as_float(__shfl_sync(0xffffffffu, e.y, t));
                const float4* sp = (const float4*)(srcB + (size_t)ct * HIDC);
                const float4 x0 = __ldg(sp + lane);
                const float4 x1 = __ldg(sp + 32 + lane);
                b0.x += vt * x0.x; b0.y += vt * x0.y; b0.z += vt * x0.z; b0.w += vt * x0.w;
                b1.x += vt * x1.x; b1.y += vt * x1.y; b1.z += vt * x1.z; b1.w += vt * x1.w;
            }
        }
    }

    const float4 la0 = leaky4(a0), la1 = leaky4(a1);
    const float4 lb0 = leaky4(b0), lb1 = leaky4(b1);
    float4* dp = (float4*)(dst + (size_t)row * HIDC);
    __stcs(dp + lane,      make_float4(la0.x + lb0.x, la0.y + lb0.y, la0.z + lb0.z, la0.w + lb0.w));
    __stcs(dp + 32 + lane, make_float4(la1.x + lb1.x, la1.y + lb1.y, la1.z + lb1.z, la1.w + lb1.w));
}

// ===========================================================================
// Merged CSR SpMM, K=64: 16 lanes per row; writes leaky(sumA)+leaky(sumB).
// ===========================================================================
__global__ __launch_bounds__(256)
void spmm2_csr64_kernel(const int* __restrict__ rpA, const int2* __restrict__ peA,
                        const float* __restrict__ srcA,
                        const int* __restrict__ rpB, const int2* __restrict__ peB,
                        const float* __restrict__ srcB,
                        float* __restrict__ dst, int nrows)
{
    const int lane32 = threadIdx.x & 31;
    const int lane16 = threadIdx.x & 15;
    const int row    = blockIdx.x * 16 + (threadIdx.x >> 4);
    if (row >= nrows) return;

    const unsigned gmask = 0xFFFFu << (lane32 & 16);

    float4 a = make_float4(0.f, 0.f, 0.f, 0.f);
    {
        const int s0 = __ldg(rpA + row);
        const int s1 = __ldg(rpA + row + 1);
        for (int j0 = s0; j0 < s1; j0 += 16) {
            int2 e = make_int2(0, 0);
            if (j0 + lane16 < s1) e = __ldcs(peA + j0 + lane16);
            const int cnt = min(16, s1 - j0);
            for (int t = 0; t < cnt; ++t) {
                const int   ct = __shfl_sync(gmask, e.x, t, 16);
                const float vt = __int_as_float(__shfl_sync(gmask, e.y, t, 16));
                const float4 x = __ldg((const float4*)(srcA + (size_t)ct * OUTC) + lane16);
                a.x += vt * x.x; a.y += vt * x.y; a.z += vt * x.z; a.w += vt * x.w;
            }
        }
    }

    float4 b = make_float4(0.f, 0.f, 0.f, 0.f);
    {
        const int s0 = __ldg(rpB + row);
        const int s1 = __ldg(rpB + row + 1);
        for (int j0 = s0; j0 < s1; j0 += 16) {
            int2 e = make_int2(0, 0);
            if (j0 + lane16 < s1) e = __ldcs(peB + j0 + lane16);
            const int cnt = min(16, s1 - j0);
            for (int t = 0; t < cnt; ++t) {
                const int   ct = __shfl_sync(gmask, e.x, t, 16);
                const float vt = __int_as_float(__shfl_sync(gmask, e.y, t, 16));
                const float4 x = __ldg((const float4*)(srcB + (size_t)ct * OUTC) + lane16);
                b.x += vt * x.x; b.y += vt * x.y; b.z += vt * x.z; b.w += vt * x.w;
            }
        }
    }

    const float4 la = leaky4(a), lb = leaky4(b);
    __stcs((float4*)(dst + (size_t)row * OUTC) + lane16,
           make_float4(la.x + lb.x, la.y + lb.y, la.z + lb.z, la.w + lb.w));
}

// ===========================================================================
// Tiled fp32 GEMM with packed f32x2 accumulation (FFMA2).
// ===========================================================================
template<int BN, int TN>
__global__ __launch_bounds__(256)
void gemm128_kernel(const float* __restrict__ A, const float* __restrict__ B,
                    float* __restrict__ C, int Mr, int K, int Nc)
{
    constexpr int BM = 128, BK = 16, TM = 8;
    constexpr int TNP = TN / 2;
    constexpr int NT4 = BN / 4;
    constexpr int BSLOTS = BK * NT4;

    __shared__ float As[BK][BM];
    __shared__ float Bs[BK][BN];

    const int tid  = threadIdx.x;
    const int tx   = tid & 15;
    const int ty   = tid >> 4;
    const int row0 = blockIdx.y * BM;
    const int col0 = blockIdx.x * BN;

    unsigned long long acc2[TM][TNP] = {};

    for (int k0 = 0; k0 < K; k0 += BK) {
        #pragma unroll
        for (int t = 0; t < 2; ++t) {
            const int li = tid + t * 256;
            const int r  = li >> 2;
            const int kc = (li & 3) * 4;
            float4 v = make_float4(0.f, 0.f, 0.f, 0.f);
            if (row0 + r < Mr)
                v = *(const float4*)(A + (size_t)(row0 + r) * K + k0 + kc);
            As[kc + 0][r] = v.x; As[kc + 1][r] = v.y;
            As[kc + 2][r] = v.z; As[kc + 3][r] = v.w;
        }
        #pragma unroll
        for (int t = 0; t < BSLOTS / 256; ++t) {
            const int li = tid + t * 256;
            const int r  = li / NT4;
            const int c  = (li % NT4) * 4;
            *(float4*)&Bs[r][c] =
                *(const float4*)(B + (size_t)(k0 + r) * Nc + col0 + c);
        }
        __syncthreads();

        #pragma unroll
        for (int k = 0; k < BK; ++k) {
            float a[TM];
            *(float4*)&a[0] = *(const float4*)&As[k][ty * TM];
            *(float4*)&a[4] = *(const float4*)&As[k][ty * TM + 4];

            unsigned long long a2[TM];
            #pragma unroll
            for (int i = 0; i < TM; ++i) a2[i] = pack_dup_f32(a[i]);

            unsigned long long b2[TNP];
            #pragma unroll
            for (int j = 0; j < TNP; j += 2) {
                const ulonglong2 t2 = *(const ulonglong2*)&Bs[k][tx * TN + j * 2];
                b2[j]     = t2.x;
                b2[j + 1] = t2.y;
            }

            #pragma unroll
            for (int i = 0; i < TM; ++i)
                #pragma unroll
                for (int j = 0; j < TNP; ++j)
                    ffma2(acc2[i][j], a2[i], b2[j]);
        }
        __syncthreads();
    }

    #pragma unroll
    for (int i = 0; i < TM; ++i) {
        const int r = row0 + ty * TM + i;
        if (r < Mr) {
            #pragma unroll
            for (int j = 0; j < TNP; j += 2) {
                ulonglong2 o;
                o.x = acc2[i][j];
                o.y = acc2[i][j + 1];
                *(ulonglong2*)(C + (size_t)r * Nc + col0 + tx * TN + j * 2) = o;
            }
        }
    }
}

static inline int cap_grid(long long g) { return (int)(g > 65535 ? 65535 : g); }

// ---------------------------------------------------------------------------
// Launch
// ---------------------------------------------------------------------------
extern "C" void kernel_launch(void* const* d_in, const int* in_sizes, int n_in,
                              void* d_out, int out_size)
{
    const float* x   = (const float*)d_in[0];
    const float* y   = (const float*)d_in[1];
    const float* W0  = (const float*)d_in[2];
    const float* W1  = (const float*)d_in[3];
    const int*   hht_r = (const int*)d_in[4];
    const int*   hht_c = (const int*)d_in[5];
    const float* hht_v = (const float*)d_in[6];
    const int*   h_r   = (const int*)d_in[7];
    const int*   h_c   = (const int*)d_in[8];
    const float* h_v   = (const float*)d_in[9];
    const int*   ht_r  = (const int*)d_in[10];
    const int*   ht_c  = (const int*)d_in[11];
    const float* ht_v  = (const float*)d_in[12];
    const int*   hth_r = (const int*)d_in[13];
    const int*   hth_c = (const int*)d_in[14];
    const float* hth_v = (const float*)d_in[15];

    const int nnz_hht = in_sizes[4];
    const int nnz_h   = in_sizes[7];
    const int nnz_ht  = in_sizes[10];
    const int nnz_hth = in_sizes[13];
    const long long total_nnz = (long long)nnz_hht + nnz_h + nnz_ht + nnz_hth;

    float *xw0, *yw0, *x1, *y1, *xw1, *yw1;
    cudaGetSymbolAddress((void**)&xw0, g_xw0);
    cudaGetSymbolAddress((void**)&yw0, g_yw0);
    cudaGetSymbolAddress((void**)&x1,  g_x1);
    cudaGetSymbolAddress((void**)&y1,  g_y1);
    cudaGetSymbolAddress((void**)&xw1, g_xw1);
    cudaGetSymbolAddress((void**)&yw1, g_yw1);

    int *rp_hht, *rp_h, *rp_ht, *rp_hth;
    int2 *pe_hht, *pe_h, *pe_ht, *pe_hth;
    cudaGetSymbolAddress((void**)&rp_hht, g_rp_hht);
    cudaGetSymbolAddress((void**)&rp_h,   g_rp_h);
    cudaGetSymbolAddress((void**)&rp_ht,  g_rp_ht);
    cudaGetSymbolAddress((void**)&rp_hth, g_rp_hth);
    cudaGetSymbolAddress((void**)&pe_hht, g_pe_hht);
    cudaGetSymbolAddress((void**)&pe_h,   g_pe_h);
    cudaGetSymbolAddress((void**)&pe_ht,  g_pe_ht);
    cudaGetSymbolAddress((void**)&pe_hth, g_pe_hth);

    float* out = (float*)d_out;

    const int SCAN_BLOCKS = 2 * NB_N + 2 * NB_M;   // 138

    // ---- Build CSR (launch indices 0..5; -s 5 captures scatter_all) ----
    zero_counts_kernel<<<(NROWS + 255) / 256, 256>>>();
    hist_all_kernel<<<cap_grid((total_nnz + 255) / 256), 256>>>(
        hht_r, nnz_hht, h_r, nnz_h, ht_r, nnz_ht, hth_r, nnz_hth);
    scan1_all_kernel<<<SCAN_BLOCKS, 1024>>>();
    scan2_all_kernel<<<4, 64>>>();
    scan3_all_kernel<<<SCAN_BLOCKS, 1024>>>(nnz_hht, nnz_h, nnz_ht, nnz_hth);
    scatter_all_kernel<<<cap_grid((total_nnz + 255) / 256), 256>>>(
        hht_r, hht_c, hht_v, nnz_hht,
        h_r,   h_c,   h_v,   nnz_h,
        ht_r,  ht_c,  ht_v,  nnz_ht,
        hth_r, hth_c, hth_v, nnz_hth);

    // ---- Layer 0 dense: xW0 [N,256], yW0 [M,256] ----
    {
        dim3 gx(HIDC / 128, (NROWS + 127) / 128);
        gemm128_kernel<128, 8><<<gx, 256>>>(x, W0, xw0, NROWS, HIDC, HIDC);
        dim3 gy(HIDC / 128, (MROWS + 127) / 128);
        gemm128_kernel<128, 8><<<gy, 256>>>(y, W0, yw0, MROWS, HIDC, HIDC);
    }

    // ---- Layer 0 sparse (merged pairs, combine fused into store) ----
    spmm2_csr256_kernel<<<NROWS / 8, 256>>>(rp_hht, pe_hht, xw0, rp_h,   pe_h,   yw0, x1, NROWS);
    spmm2_csr256_kernel<<<MROWS / 8, 256>>>(rp_ht,  pe_ht,  xw0, rp_hth, pe_hth, yw0, y1, MROWS);

    // ---- Layer 1 dense: xw1 = x1 @ W1, yw1 = y1 @ W1 ----
    {
        dim3 gx(OUTC / 64, (NROWS + 127) / 128);
        gemm128_kernel<64, 4><<<gx, 256>>>(x1, W1, xw1, NROWS, HIDC, OUTC);
        dim3 gy(OUTC / 64, (MROWS + 127) / 128);
        gemm128_kernel<64, 4><<<gy, 256>>>(y1, W1, yw1, MROWS, HIDC, OUTC);
    }

    // ---- Layer 1 sparse (merged pairs), writes final output directly ----
    spmm2_csr64_kernel<<<NROWS / 16, 256>>>(rp_hht, pe_hht, xw1, rp_h,   pe_h,   yw1,
                                            out, NROWS);
    spmm2_csr64_kernel<<<MROWS / 16, 256>>>(rp_ht,  pe_ht,  xw1, rp_hth, pe_hth, yw1,
                                            out + (size_t)NROWS * OUTC, MROWS);
}

// round 11
// speedup vs baseline: 2.0910x; 1.0944x over previous
#include <cuda_runtime.h>
#include <cstdint>
#include <cstddef>

// Problem constants (match reference)
#define NROWS 50000
#define MROWS 20000
#define HIDC  256
#define OUTC  64
#define NNZ_HHT 1600000
#define NNZ_H   1000000
#define NNZ_HT  1000000
#define NNZ_HTH  640000

#define NB_N 49   // ceil(NROWS/1024)
#define NB_M 20   // ceil(MROWS/1024)

// block partitioning for fused kernels
#define GX_BLOCKS   782    // (HIDC/128) * ceil(NROWS/128) = 2*391
#define HIST_BLOCKS 1024
#define GY_BLOCKS   314    // 2*157
#define SCAT_BLOCKS 1024
#define K6_INTERLEAVE (GY_BLOCKS * 4)          // 1256
#define K6_BLOCKS  (K6_INTERLEAVE + (SCAT_BLOCKS - (K6_INTERLEAVE - GY_BLOCKS)))  // 1338

// ---------------------------------------------------------------------------
// Static device scratch (allocation-free rule: __device__ globals)
// ---------------------------------------------------------------------------
__device__ __align__(16) float g_xw0[(size_t)NROWS * HIDC];   // x @ W0
__device__ __align__(16) float g_yw0[(size_t)MROWS * HIDC];   // y @ W0
__device__ __align__(16) float g_x1 [(size_t)NROWS * HIDC];   // leaky(hht_l)+leaky(h_l)
__device__ __align__(16) float g_y1 [(size_t)MROWS * HIDC];   // leaky(ht_l)+leaky(hth_l)
__device__ __align__(16) float g_xw1[(size_t)NROWS * OUTC];   // x1 @ W1
__device__ __align__(16) float g_yw1[(size_t)MROWS * OUTC];   // y1 @ W1

// CSR structures (built on device each launch)
__device__ int  g_cnt_hht[NROWS],  g_rp_hht[NROWS + 1],  g_cur_hht[NROWS];
__device__ int  g_cnt_h  [NROWS],  g_rp_h  [NROWS + 1],  g_cur_h  [NROWS];
__device__ int  g_cnt_ht [MROWS],  g_rp_ht [MROWS + 1],  g_cur_ht [MROWS];
__device__ int  g_cnt_hth[MROWS],  g_rp_hth[MROWS + 1],  g_cur_hth[MROWS];
__device__ int  g_aux_hht[64], g_aux_h[64], g_aux_ht[64], g_aux_hth[64];
// packed (col, float_as_int(val)) per edge
__device__ int2 g_pe_hht[NNZ_HHT];
__device__ int2 g_pe_h  [NNZ_H];
__device__ int2 g_pe_ht [NNZ_HT];
__device__ int2 g_pe_hth[NNZ_HTH];

__device__ __forceinline__ float leaky(float v) {
    return v >= 0.0f ? v : 0.2f * v;
}
__device__ __forceinline__ float4 leaky4(float4 v) {
    return make_float4(leaky(v.x), leaky(v.y), leaky(v.z), leaky(v.w));
}

// ---- packed fp32x2 helpers (Blackwell FFMA2 path) ----
__device__ __forceinline__ unsigned long long pack_dup_f32(float x) {
#if defined(__CUDA_ARCH__) && (__CUDA_ARCH__ >= 1000)
    unsigned long long r;
    asm("mov.b64 %0, {%1, %1};" : "=l"(r) : "r"(__float_as_uint(x)));
    return r;
#else
    union { unsigned long long u; float f[2]; } t;
    t.f[0] = x; t.f[1] = x;
    return t.u;
#endif
}

__device__ __forceinline__ void ffma2(unsigned long long& acc,
                                      unsigned long long a, unsigned long long b) {
#if defined(__CUDA_ARCH__) && (__CUDA_ARCH__ >= 1000)
    asm("fma.rn.f32x2 %0, %1, %2, %0;" : "+l"(acc) : "l"(a), "l"(b));
#else
    union U { unsigned long long u; float f[2]; };
    U ua, ub, uc; ua.u = a; ub.u = b; uc.u = acc;
    uc.f[0] = fmaf(ua.f[0], ub.f[0], uc.f[0]);
    uc.f[1] = fmaf(ua.f[1], ub.f[1], uc.f[1]);
    acc = uc.u;
#endif
}

// ===========================================================================
// GEMM body (device function): C tile (bx, by) of C[Mr,Nc] = A[Mr,K] @ B[K,Nc]
// BM=128, BK=16, 256 threads, TM=8 x TN micro-tile, FFMA2 inner product.
// ===========================================================================
template<int BN, int TN>
__device__ __forceinline__
void gemm_body(const float* __restrict__ A, const float* __restrict__ B,
               float* __restrict__ C, int Mr, int K, int Nc, int bx, int by)
{
    constexpr int BM = 128, BK = 16, TM = 8;
    constexpr int TNP = TN / 2;
    constexpr int NT4 = BN / 4;
    constexpr int BSLOTS = BK * NT4;

    __shared__ float As[BK][BM];
    __shared__ float Bs[BK][BN];

    const int tid  = threadIdx.x;
    const int tx   = tid & 15;
    const int ty   = tid >> 4;
    const int row0 = by * BM;
    const int col0 = bx * BN;

    unsigned long long acc2[TM][TNP] = {};

    for (int k0 = 0; k0 < K; k0 += BK) {
        #pragma unroll
        for (int t = 0; t < 2; ++t) {
            const int li = tid + t * 256;
            const int r  = li >> 2;
            const int kc = (li & 3) * 4;
            float4 v = make_float4(0.f, 0.f, 0.f, 0.f);
            if (row0 + r < Mr)
                v = *(const float4*)(A + (size_t)(row0 + r) * K + k0 + kc);
            As[kc + 0][r] = v.x; As[kc + 1][r] = v.y;
            As[kc + 2][r] = v.z; As[kc + 3][r] = v.w;
        }
        #pragma unroll
        for (int t = 0; t < BSLOTS / 256; ++t) {
            const int li = tid + t * 256;
            const int r  = li / NT4;
            const int c  = (li % NT4) * 4;
            *(float4*)&Bs[r][c] =
                *(const float4*)(B + (size_t)(k0 + r) * Nc + col0 + c);
        }
        __syncthreads();

        #pragma unroll
        for (int k = 0; k < BK; ++k) {
            float a[TM];
            *(float4*)&a[0] = *(const float4*)&As[k][ty * TM];
            *(float4*)&a[4] = *(const float4*)&As[k][ty * TM + 4];

            unsigned long long a2[TM];
            #pragma unroll
            for (int i = 0; i < TM; ++i) a2[i] = pack_dup_f32(a[i]);

            unsigned long long b2[TNP];
            #pragma unroll
            for (int j = 0; j < TNP; j += 2) {
                const ulonglong2 t2 = *(const ulonglong2*)&Bs[k][tx * TN + j * 2];
                b2[j]     = t2.x;
                b2[j + 1] = t2.y;
            }

            #pragma unroll
            for (int i = 0; i < TM; ++i)
                #pragma unroll
                for (int j = 0; j < TNP; ++j)
                    ffma2(acc2[i][j], a2[i], b2[j]);
        }
        __syncthreads();
    }

    #pragma unroll
    for (int i = 0; i < TM; ++i) {
        const int r = row0 + ty * TM + i;
        if (r < Mr) {
            #pragma unroll
            for (int j = 0; j < TNP; j += 2) {
                ulonglong2 o;
                o.x = acc2[i][j];
                o.y = acc2[i][j + 1];
                *(ulonglong2*)(C + (size_t)r * Nc + col0 + tx * TN + j * 2) = o;
            }
        }
    }
}

// ===========================================================================
// CSR build kernels
// ===========================================================================
__global__ __launch_bounds__(256)
void zero_counts_kernel()
{
    const int i = blockIdx.x * blockDim.x + threadIdx.x;
    if (i < NROWS) { g_cnt_hht[i] = 0; g_cnt_h[i] = 0; }
    if (i < MROWS) { g_cnt_ht[i]  = 0; g_cnt_hth[i] = 0; }
}

// K2: blocks [0, GX_BLOCKS) compute x@W0; remaining blocks run the histogram.
__global__ __launch_bounds__(256)
void fused_gemmx_hist_kernel(const float* __restrict__ x, const float* __restrict__ W0,
                             float* __restrict__ xw0,
                             const int* __restrict__ r0, int n0,
                             const int* __restrict__ r1, int n1,
                             const int* __restrict__ r2, int n2,
                             const int* __restrict__ r3, int n3)
{
    const int b = blockIdx.x;
    if (b < GX_BLOCKS) {
        gemm_body<128, 8>(x, W0, xw0, NROWS, HIDC, HIDC, b & 1, b >> 1);
    } else {
        const int hb = b - GX_BLOCKS;
        const int total = n0 + n1 + n2 + n3;
        const int stride = HIST_BLOCKS * 256;
        for (int e = hb * 256 + threadIdx.x; e < total; e += stride) {
            if (e < n0)                atomicAdd(g_cnt_hht + __ldcs(r0 + e), 1);
            else if (e < n0 + n1)      atomicAdd(g_cnt_h   + __ldcs(r1 + e - n0), 1);
            else if (e < n0 + n1 + n2) atomicAdd(g_cnt_ht  + __ldcs(r2 + e - n0 - n1), 1);
            else                       atomicAdd(g_cnt_hth + __ldcs(r3 + e - n0 - n1 - n2), 1);
        }
    }
}

// pass 1: per-block exclusive scan of counts; aux[b] = block sum.
__global__ __launch_bounds__(1024)
void scan1_all_kernel()
{
    const int b = blockIdx.x;
    const int* cnt; int* rp; int* aux; int n; int lb;
    if (b < NB_N)              { cnt = g_cnt_hht; rp = g_rp_hht; aux = g_aux_hht; n = NROWS; lb = b; }
    else if (b < 2 * NB_N)     { cnt = g_cnt_h;   rp = g_rp_h;   aux = g_aux_h;   n = NROWS; lb = b - NB_N; }
    else if (b < 2*NB_N+NB_M)  { cnt = g_cnt_ht;  rp = g_rp_ht;  aux = g_aux_ht;  n = MROWS; lb = b - 2*NB_N; }
    else                       { cnt = g_cnt_hth; rp = g_rp_hth; aux = g_aux_hth; n = MROWS; lb = b - 2*NB_N - NB_M; }

    __shared__ int s[1024];
    const int tid = threadIdx.x;
    const int i = lb * 1024 + tid;
    const int v = (i < n) ? cnt[i] : 0;
    s[tid] = v;
    __syncthreads();
    for (int off = 1; off < 1024; off <<= 1) {
        int t = (tid >= off) ? s[tid - off] : 0;
        __syncthreads();
        s[tid] += t;
        __syncthreads();
    }
    if (i < n) rp[i] = s[tid] - v;
    if (tid == 1023) aux[lb] = s[1023];
}

// pass 2 (all four aux arrays, block per array)
__global__ __launch_bounds__(64)
void scan2_all_kernel()
{
    int* aux; int naux;
    switch (blockIdx.x) {
        case 0:  aux = g_aux_hht; naux = NB_N; break;
        case 1:  aux = g_aux_h;   naux = NB_N; break;
        case 2:  aux = g_aux_ht;  naux = NB_M; break;
        default: aux = g_aux_hth; naux = NB_M; break;
    }
    __shared__ int s[64];
    const int tid = threadIdx.x;
    const int v = (tid < naux) ? aux[tid] : 0;
    s[tid] = v;
    __syncthreads();
    for (int off = 1; off < 64; off <<= 1) {
        int t = (tid >= off) ? s[tid - off] : 0;
        __syncthreads();
        s[tid] += t;
        __syncthreads();
    }
    if (tid < naux) aux[tid] = s[tid] - v;
}

// pass 3: add block offsets; copy into cursor; one thread writes rp[n] = nnz.
__global__ __launch_bounds__(1024)
void scan3_all_kernel(int n0, int n1, int n2, int n3)
{
    const int b = blockIdx.x;
    int* rp; int* cur; const int* aux; int n; int lb; int nnz;
    if (b < NB_N)              { rp = g_rp_hht; cur = g_cur_hht; aux = g_aux_hht; n = NROWS; lb = b;                  nnz = n0; }
    else if (b < 2 * NB_N)     { rp = g_rp_h;   cur = g_cur_h;   aux = g_aux_h;   n = NROWS; lb = b - NB_N;           nnz = n1; }
    else if (b < 2*NB_N+NB_M)  { rp = g_rp_ht;  cur = g_cur_ht;  aux = g_aux_ht;  n = MROWS; lb = b - 2*NB_N;         nnz = n2; }
    else                       { rp = g_rp_hth; cur = g_cur_hth; aux = g_aux_hth; n = MROWS; lb = b - 2*NB_N - NB_M;  nnz = n3; }

    const int tid = threadIdx.x;
    const int i = lb * 1024 + tid;
    if (i < n) {
        const int r = rp[i] + aux[lb];
        rp[i] = r;
        cur[i] = r;
    }
    if (lb == 0 && tid == 0) rp[n] = nnz;
}

// K6: gemm_y interleaved 1:3 with scatter.
// b % 4 == 0 && b < K6_INTERLEAVE  -> gemm block  g = b/4   (exactly GY_BLOCKS)
// otherwise                        -> scatter block, compact id.
__global__ __launch_bounds__(256)
void fused_gemmy_scatter_kernel(const float* __restrict__ y, const float* __restrict__ W0,
                                float* __restrict__ yw0,
                                const int* __restrict__ r0, const int* __restrict__ c0,
                                const float* __restrict__ v0, int n0,
                                const int* __restrict__ r1, const int* __restrict__ c1,
                                const float* __restrict__ v1, int n1,
                                const int* __restrict__ r2, const int* __restrict__ c2,
                                const float* __restrict__ v2, int n2,
                                const int* __restrict__ r3, const int* __restrict__ c3,
                                const float* __restrict__ v3, int n3)
{
    const int b = blockIdx.x;
    if (b < K6_INTERLEAVE && (b & 3) == 0) {
        const int g = b >> 2;                       // 0..GY_BLOCKS-1
        gemm_body<128, 8>(y, W0, yw0, MROWS, HIDC, HIDC, g & 1, g >> 1);
        return;
    }
    int sid;
    if (b < K6_INTERLEAVE) sid = b - (b >> 2) - 1;                 // compact over b%4!=0
    else                   sid = (K6_INTERLEAVE - GY_BLOCKS) + (b - K6_INTERLEAVE);

    const int total = n0 + n1 + n2 + n3;
    const int stride = SCAT_BLOCKS * 256;
    for (int e = sid * 256 + threadIdx.x; e < total; e += stride) {
        const int* rows; const int* cols; const float* vals;
        int* cur; int2* pe; int el;
        if (e < n0)                { rows = r0; cols = c0; vals = v0; cur = g_cur_hht; pe = g_pe_hht; el = e; }
        else if (e < n0 + n1)      { rows = r1; cols = c1; vals = v1; cur = g_cur_h;   pe = g_pe_h;   el = e - n0; }
        else if (e < n0 + n1 + n2) { rows = r2; cols = c2; vals = v2; cur = g_cur_ht;  pe = g_pe_ht;  el = e - n0 - n1; }
        else                       { rows = r3; cols = c3; vals = v3; cur = g_cur_hth; pe = g_pe_hth; el = e - n0 - n1 - n2; }
        const int r = __ldcs(rows + el);
        const int pos = atomicAdd(cur + r, 1);
        __stcs(pe + pos, make_int2(__ldcs(cols + el), __float_as_int(__ldcs(vals + el))));
    }
}

// ===========================================================================
// Merged CSR SpMM row bodies
// ===========================================================================
__device__ __forceinline__
void spmm256_row(const int* __restrict__ rp, const int2* __restrict__ pe,
                 const float* __restrict__ src, int row, int lane,
                 float4& acc0, float4& acc1)
{
    const int s0 = __ldg(rp + row);
    const int s1 = __ldg(rp + row + 1);
    for (int j0 = s0; j0 < s1; j0 += 32) {
        int2 e = make_int2(0, 0);
        if (j0 + lane < s1) e = __ldcs(pe + j0 + lane);
        const int cnt = min(32, s1 - j0);
        for (int t = 0; t < cnt; ++t) {
            const int   ct = __shfl_sync(0xffffffffu, e.x, t);
            const float vt = __int_as_float(__shfl_sync(0xffffffffu, e.y, t));
            const float4* sp = (const float4*)(src + (size_t)ct * HIDC);
            const float4 x0 = __ldg(sp + lane);
            const float4 x1 = __ldg(sp + 32 + lane);
            acc0.x += vt * x0.x; acc0.y += vt * x0.y; acc0.z += vt * x0.z; acc0.w += vt * x0.w;
            acc1.x += vt * x1.x; acc1.y += vt * x1.y; acc1.z += vt * x1.z; acc1.w += vt * x1.w;
        }
    }
}

// K=256 merged SpMM over BOTH row spaces: blocks [0, NROWS/8) -> x1,
// blocks [NROWS/8, NROWS/8 + MROWS/8) -> y1. One warp per row.
__global__ __launch_bounds__(256)
void spmm256_dual_kernel(const float* __restrict__ xw0, const float* __restrict__ yw0,
                         float* __restrict__ x1, float* __restrict__ y1)
{
    const int lane = threadIdx.x & 31;
    const int wb   = blockIdx.x * 8 + (threadIdx.x >> 5);

    float4 a0 = make_float4(0.f,0.f,0.f,0.f), a1 = make_float4(0.f,0.f,0.f,0.f);
    float4 b0 = make_float4(0.f,0.f,0.f,0.f), b1 = make_float4(0.f,0.f,0.f,0.f);
    float* dst;
    int row;
    if (wb < NROWS) {
        row = wb;
        spmm256_row(g_rp_hht, g_pe_hht, xw0, row, lane, a0, a1);
        spmm256_row(g_rp_h,   g_pe_h,   yw0, row, lane, b0, b1);
        dst = x1;
    } else {
        row = wb - NROWS;
        spmm256_row(g_rp_ht,  g_pe_ht,  xw0, row, lane, a0, a1);
        spmm256_row(g_rp_hth, g_pe_hth, yw0, row, lane, b0, b1);
        dst = y1;
    }

    const float4 la0 = leaky4(a0), la1 = leaky4(a1);
    const float4 lb0 = leaky4(b0), lb1 = leaky4(b1);
    float4* dp = (float4*)(dst + (size_t)row * HIDC);
    __stcs(dp + lane,      make_float4(la0.x + lb0.x, la0.y + lb0.y, la0.z + lb0.z, la0.w + lb0.w));
    __stcs(dp + 32 + lane, make_float4(la1.x + lb1.x, la1.y + lb1.y, la1.z + lb1.z, la1.w + lb1.w));
}

__device__ __forceinline__
void spmm64_row(const int* __restrict__ rp, const int2* __restrict__ pe,
                const float* __restrict__ src, int row, int lane16, unsigned gmask,
                float4& acc)
{
    const int s0 = __ldg(rp + row);
    const int s1 = __ldg(rp + row + 1);
    for (int j0 = s0; j0 < s1; j0 += 16) {
        int2 e = make_int2(0, 0);
        if (j0 + lane16 < s1) e = __ldcs(pe + j0 + lane16);
        const int cnt = min(16, s1 - j0);
        for (int t = 0; t < cnt; ++t) {
            const int   ct = __shfl_sync(gmask, e.x, t, 16);
            const float vt = __int_as_float(__shfl_sync(gmask, e.y, t, 16));
            const float4 x = __ldg((const float4*)(src + (size_t)ct * OUTC) + lane16);
            acc.x += vt * x.x; acc.y += vt * x.y; acc.z += vt * x.z; acc.w += vt * x.w;
        }
    }
}

// K=64 merged SpMM over both row spaces; writes final output.
__global__ __launch_bounds__(256)
void spmm64_dual_kernel(const float* __restrict__ xw1, const float* __restrict__ yw1,
                        float* __restrict__ out)
{
    const int lane32 = threadIdx.x & 31;
    const int lane16 = threadIdx.x & 15;
    const unsigned gmask = 0xFFFFu << (lane32 & 16);
    const int wb = blockIdx.x * 16 + (threadIdx.x >> 4);

    float4 a = make_float4(0.f,0.f,0.f,0.f), b = make_float4(0.f,0.f,0.f,0.f);
    float* dst;
    int row;
    if (wb < NROWS) {
        row = wb;
        spmm64_row(g_rp_hht, g_pe_hht, xw1, row, lane16, gmask, a);
        spmm64_row(g_rp_h,   g_pe_h,   yw1, row, lane16, gmask, b);
        dst = out;
    } else {
        row = wb - NROWS;
        spmm64_row(g_rp_ht,  g_pe_ht,  xw1, row, lane16, gmask, a);
        spmm64_row(g_rp_hth, g_pe_hth, yw1, row, lane16, gmask, b);
        dst = out + (size_t)NROWS * OUTC;
    }

    const float4 la = leaky4(a), lb = leaky4(b);
    __stcs((float4*)(dst + (size_t)row * OUTC) + lane16,
           make_float4(la.x + lb.x, la.y + lb.y, la.z + lb.z, la.w + lb.w));
}

// Merged layer-1 GEMM: blocks [0,391) -> x1@W1, [391,548) -> y1@W1.
#define G1X_BLOCKS 391
__global__ __launch_bounds__(256)
void gemm1_dual_kernel(const float* __restrict__ x1, const float* __restrict__ y1,
                       const float* __restrict__ W1,
                       float* __restrict__ xw1, float* __restrict__ yw1)
{
    const int b = blockIdx.x;
    if (b < G1X_BLOCKS)
        gemm_body<64, 4>(x1, W1, xw1, NROWS, HIDC, OUTC, 0, b);
    else
        gemm_body<64, 4>(y1, W1, yw1, MROWS, HIDC, OUTC, 0, b - G1X_BLOCKS);
}

// ---------------------------------------------------------------------------
// Launch
// ---------------------------------------------------------------------------
extern "C" void kernel_launch(void* const* d_in, const int* in_sizes, int n_in,
                              void* d_out, int out_size)
{
    const float* x   = (const float*)d_in[0];
    const float* y   = (const float*)d_in[1];
    const float* W0  = (const float*)d_in[2];
    const float* W1  = (const float*)d_in[3];
    const int*   hht_r = (const int*)d_in[4];
    const int*   hht_c = (const int*)d_in[5];
    const float* hht_v = (const float*)d_in[6];
    const int*   h_r   = (const int*)d_in[7];
    const int*   h_c   = (const int*)d_in[8];
    const float* h_v   = (const float*)d_in[9];
    const int*   ht_r  = (const int*)d_in[10];
    const int*   ht_c  = (const int*)d_in[11];
    const float* ht_v  = (const float*)d_in[12];
    const int*   hth_r = (const int*)d_in[13];
    const int*   hth_c = (const int*)d_in[14];
    const float* hth_v = (const float*)d_in[15];

    const int nnz_hht = in_sizes[4];
    const int nnz_h   = in_sizes[7];
    const int nnz_ht  = in_sizes[10];
    const int nnz_hth = in_sizes[13];

    float *xw0, *yw0, *x1, *y1, *xw1, *yw1;
    cudaGetSymbolAddress((void**)&xw0, g_xw0);
    cudaGetSymbolAddress((void**)&yw0, g_yw0);
    cudaGetSymbolAddress((void**)&x1,  g_x1);
    cudaGetSymbolAddress((void**)&y1,  g_y1);
    cudaGetSymbolAddress((void**)&xw1, g_xw1);
    cudaGetSymbolAddress((void**)&yw1, g_yw1);

    float* out = (float*)d_out;

    const int SCAN_BLOCKS = 2 * NB_N + 2 * NB_M;   // 138

    // K1: zero histogram counters
    zero_counts_kernel<<<(NROWS + 255) / 256, 256>>>();

    // K2: x@W0 GEMM co-scheduled with the 4-matrix histogram
    fused_gemmx_hist_kernel<<<GX_BLOCKS + HIST_BLOCKS, 256>>>(
        x, W0, xw0,
        hht_r, nnz_hht, h_r, nnz_h, ht_r, nnz_ht, hth_r, nnz_hth);

    // K3..K5: rowptr scans
    scan1_all_kernel<<<SCAN_BLOCKS, 1024>>>();
    scan2_all_kernel<<<4, 64>>>();
    scan3_all_kernel<<<SCAN_BLOCKS, 1024>>>(nnz_hht, nnz_h, nnz_ht, nnz_hth);

    // K6: y@W0 GEMM interleaved with the COO->CSR scatter
    fused_gemmy_scatter_kernel<<<K6_BLOCKS, 256>>>(
        y, W0, yw0,
        hht_r, hht_c, hht_v, nnz_hht,
        h_r,   h_c,   h_v,   nnz_h,
        ht_r,  ht_c,  ht_v,  nnz_ht,
        hth_r, hth_c, hth_v, nnz_hth);

    // K7: layer-0 SpMM over both row spaces (combine + leaky fused into store)
    spmm256_dual_kernel<<<NROWS / 8 + MROWS / 8, 256>>>(xw0, yw0, x1, y1);

    // K8: layer-1 GEMM (both inputs in one launch)
    gemm1_dual_kernel<<<G1X_BLOCKS + 157, 256>>>(x1, y1, W1, xw1, yw1);

    // K9: layer-1 SpMM, writes final output directly
    spmm64_dual_kernel<<<NROWS / 16 + MROWS / 16, 256>>>(xw1, yw1, out);
}

// round 12
// speedup vs baseline: 2.4150x; 1.1550x over previous
#include <cuda_runtime.h>
#include <cuda_fp16.h>
#include <cstdint>
#include <cstddef>

// Problem constants (match reference)
#define NROWS 50000
#define MROWS 20000
#define HIDC  256
#define OUTC  64
#define NNZ_HHT 1600000
#define NNZ_H   1000000
#define NNZ_HT  1000000
#define NNZ_HTH  640000

#define NB_N 49   // ceil(NROWS/1024)
#define NB_M 20   // ceil(MROWS/1024)

// block partitioning for fused kernels
#define GX_BLOCKS   782    // (HIDC/128) * ceil(NROWS/128) = 2*391
#define HIST_BLOCKS 1024
#define GY_BLOCKS   314    // 2*157
#define SCAT_BLOCKS 1024
#define K6_INTERLEAVE (GY_BLOCKS * 4)          // 1256
#define K6_BLOCKS  (K6_INTERLEAVE + (SCAT_BLOCKS - (K6_INTERLEAVE - GY_BLOCKS)))  // 1338

// ---------------------------------------------------------------------------
// Static device scratch (allocation-free rule: __device__ globals)
// Gather tables (xw0/yw0/xw1/yw1) are fp16: consumed ONLY by SpMM gathers.
// x1/y1 stay fp32 (layer-1 GEMM inputs).
// ---------------------------------------------------------------------------
__device__ __align__(16) __half g_xw0[(size_t)NROWS * HIDC];
__device__ __align__(16) __half g_yw0[(size_t)MROWS * HIDC];
__device__ __align__(16) float  g_x1 [(size_t)NROWS * HIDC];
__device__ __align__(16) float  g_y1 [(size_t)MROWS * HIDC];
__device__ __align__(16) __half g_xw1[(size_t)NROWS * OUTC];
__device__ __align__(16) __half g_yw1[(size_t)MROWS * OUTC];

// CSR structures (built on device each launch)
__device__ int  g_cnt_hht[NROWS],  g_rp_hht[NROWS + 1],  g_cur_hht[NROWS];
__device__ int  g_cnt_h  [NROWS],  g_rp_h  [NROWS + 1],  g_cur_h  [NROWS];
__device__ int  g_cnt_ht [MROWS],  g_rp_ht [MROWS + 1],  g_cur_ht [MROWS];
__device__ int  g_cnt_hth[MROWS],  g_rp_hth[MROWS + 1],  g_cur_hth[MROWS];
__device__ int  g_aux_hht[64], g_aux_h[64], g_aux_ht[64], g_aux_hth[64];
// packed (col, float_as_int(val)) per edge
__device__ int2 g_pe_hht[NNZ_HHT];
__device__ int2 g_pe_h  [NNZ_H];
__device__ int2 g_pe_ht [NNZ_HT];
__device__ int2 g_pe_hth[NNZ_HTH];

__device__ __forceinline__ float leaky(float v) {
    return v >= 0.0f ? v : 0.2f * v;
}

// ---- packed fp32x2 helpers (Blackwell FFMA2 path) ----
__device__ __forceinline__ unsigned long long pack_dup_f32(float x) {
#if defined(__CUDA_ARCH__) && (__CUDA_ARCH__ >= 1000)
    unsigned long long r;
    asm("mov.b64 %0, {%1, %1};" : "=l"(r) : "r"(__float_as_uint(x)));
    return r;
#else
    union { unsigned long long u; float f[2]; } t;
    t.f[0] = x; t.f[1] = x;
    return t.u;
#endif
}

__device__ __forceinline__ void ffma2(unsigned long long& acc,
                                      unsigned long long a, unsigned long long b) {
#if defined(__CUDA_ARCH__) && (__CUDA_ARCH__ >= 1000)
    asm("fma.rn.f32x2 %0, %1, %2, %0;" : "+l"(acc) : "l"(a), "l"(b));
#else
    union U { unsigned long long u; float f[2]; };
    U ua, ub, uc; ua.u = a; ub.u = b; uc.u = acc;
    uc.f[0] = fmaf(ua.f[0], ub.f[0], uc.f[0]);
    uc.f[1] = fmaf(ua.f[1], ub.f[1], uc.f[1]);
    acc = uc.u;
#endif
}

__device__ __forceinline__ __half2 ull_to_half2(unsigned long long u) {
    union { unsigned long long u; float f[2]; } t; t.u = u;
    return __floats2half2_rn(t.f[0], t.f[1]);
}

// ===========================================================================
// GEMM body: C tile (bx, by) of C[Mr,Nc] = A[Mr,K] @ B[K,Nc], fp32 inputs,
// FFMA2 inner product, fp16 output (gather tables).
// BM=128, BK=16, 256 threads, TM=8 x TN micro-tile.
// ===========================================================================
template<int BN, int TN>
__device__ __forceinline__
void gemm_body_h(const float* __restrict__ A, const float* __restrict__ B,
                 __half* __restrict__ C, int Mr, int K, int Nc, int bx, int by)
{
    constexpr int BM = 128, BK = 16, TM = 8;
    constexpr int TNP = TN / 2;
    constexpr int NT4 = BN / 4;
    constexpr int BSLOTS = BK * NT4;

    __shared__ float As[BK][BM];
    __shared__ float Bs[BK][BN];

    const int tid  = threadIdx.x;
    const int tx   = tid & 15;
    const int ty   = tid >> 4;
    const int row0 = by * BM;
    const int col0 = bx * BN;

    unsigned long long acc2[TM][TNP] = {};

    for (int k0 = 0; k0 < K; k0 += BK) {
        #pragma unroll
        for (int t = 0; t < 2; ++t) {
            const int li = tid + t * 256;
            const int r  = li >> 2;
            const int kc = (li & 3) * 4;
            float4 v = make_float4(0.f, 0.f, 0.f, 0.f);
            if (row0 + r < Mr)
                v = *(const float4*)(A + (size_t)(row0 + r) * K + k0 + kc);
            As[kc + 0][r] = v.x; As[kc + 1][r] = v.y;
            As[kc + 2][r] = v.z; As[kc + 3][r] = v.w;
        }
        #pragma unroll
        for (int t = 0; t < BSLOTS / 256; ++t) {
            const int li = tid + t * 256;
            const int r  = li / NT4;
            const int c  = (li % NT4) * 4;
            *(float4*)&Bs[r][c] =
                *(const float4*)(B + (size_t)(k0 + r) * Nc + col0 + c);
        }
        __syncthreads();

        #pragma unroll
        for (int k = 0; k < BK; ++k) {
            float a[TM];
            *(float4*)&a[0] = *(const float4*)&As[k][ty * TM];
            *(float4*)&a[4] = *(const float4*)&As[k][ty * TM + 4];

            unsigned long long a2[TM];
            #pragma unroll
            for (int i = 0; i < TM; ++i) a2[i] = pack_dup_f32(a[i]);

            unsigned long long b2[TNP];
            #pragma unroll
            for (int j = 0; j < TNP; j += 2) {
                const ulonglong2 t2 = *(const ulonglong2*)&Bs[k][tx * TN + j * 2];
                b2[j]     = t2.x;
                b2[j + 1] = t2.y;
            }

            #pragma unroll
            for (int i = 0; i < TM; ++i)
                #pragma unroll
                for (int j = 0; j < TNP; ++j)
                    ffma2(acc2[i][j], a2[i], b2[j]);
        }
        __syncthreads();
    }

    #pragma unroll
    for (int i = 0; i < TM; ++i) {
        const int r = row0 + ty * TM + i;
        if (r < Mr) {
            __half2 h[TNP];
            #pragma unroll
            for (int j = 0; j < TNP; ++j) h[j] = ull_to_half2(acc2[i][j]);
            __half* cp = C + (size_t)r * Nc + col0 + tx * TN;
            if (TNP == 4)      *(uint4*)cp = *(uint4*)h;   // TN=8: 16B store
            else               *(uint2*)cp = *(uint2*)h;   // TN=4: 8B store
        }
    }
}

// ===========================================================================
// CSR build kernels
// ===========================================================================
__global__ __launch_bounds__(256)
void zero_counts_kernel()
{
    const int i = blockIdx.x * blockDim.x + threadIdx.x;
    if (i < NROWS) { g_cnt_hht[i] = 0; g_cnt_h[i] = 0; }
    if (i < MROWS) { g_cnt_ht[i]  = 0; g_cnt_hth[i] = 0; }
}

// K2: blocks [0, GX_BLOCKS) compute x@W0 (fp16 out); rest run the histogram.
__global__ __launch_bounds__(256)
void fused_gemmx_hist_kernel(const float* __restrict__ x, const float* __restrict__ W0,
                             __half* __restrict__ xw0,
                             const int* __restrict__ r0, int n0,
                             const int* __restrict__ r1, int n1,
                             const int* __restrict__ r2, int n2,
                             const int* __restrict__ r3, int n3)
{
    const int b = blockIdx.x;
    if (b < GX_BLOCKS) {
        gemm_body_h<128, 8>(x, W0, xw0, NROWS, HIDC, HIDC, b & 1, b >> 1);
    } else {
        const int hb = b - GX_BLOCKS;
        const int total = n0 + n1 + n2 + n3;
        const int stride = HIST_BLOCKS * 256;
        for (int e = hb * 256 + threadIdx.x; e < total; e += stride) {
            if (e < n0)                atomicAdd(g_cnt_hht + __ldcs(r0 + e), 1);
            else if (e < n0 + n1)      atomicAdd(g_cnt_h   + __ldcs(r1 + e - n0), 1);
            else if (e < n0 + n1 + n2) atomicAdd(g_cnt_ht  + __ldcs(r2 + e - n0 - n1), 1);
            else                       atomicAdd(g_cnt_hth + __ldcs(r3 + e - n0 - n1 - n2), 1);
        }
    }
}

// pass 1: per-block exclusive scan of counts; aux[b] = block sum.
__global__ __launch_bounds__(1024)
void scan1_all_kernel()
{
    const int b = blockIdx.x;
    const int* cnt; int* rp; int* aux; int n; int lb;
    if (b < NB_N)              { cnt = g_cnt_hht; rp = g_rp_hht; aux = g_aux_hht; n = NROWS; lb = b; }
    else if (b < 2 * NB_N)     { cnt = g_cnt_h;   rp = g_rp_h;   aux = g_aux_h;   n = NROWS; lb = b - NB_N; }
    else if (b < 2*NB_N+NB_M)  { cnt = g_cnt_ht;  rp = g_rp_ht;  aux = g_aux_ht;  n = MROWS; lb = b - 2*NB_N; }
    else                       { cnt = g_cnt_hth; rp = g_rp_hth; aux = g_aux_hth; n = MROWS; lb = b - 2*NB_N - NB_M; }

    __shared__ int s[1024];
    const int tid = threadIdx.x;
    const int i = lb * 1024 + tid;
    const int v = (i < n) ? cnt[i] : 0;
    s[tid] = v;
    __syncthreads();
    for (int off = 1; off < 1024; off <<= 1) {
        int t = (tid >= off) ? s[tid - off] : 0;
        __syncthreads();
        s[tid] += t;
        __syncthreads();
    }
    if (i < n) rp[i] = s[tid] - v;
    if (tid == 1023) aux[lb] = s[1023];
}

// pass 2 (all four aux arrays, block per array)
__global__ __launch_bounds__(64)
void scan2_all_kernel()
{
    int* aux; int naux;
    switch (blockIdx.x) {
        case 0:  aux = g_aux_hht; naux = NB_N; break;
        case 1:  aux = g_aux_h;   naux = NB_N; break;
        case 2:  aux = g_aux_ht;  naux = NB_M; break;
        default: aux = g_aux_hth; naux = NB_M; break;
    }
    __shared__ int s[64];
    const int tid = threadIdx.x;
    const int v = (tid < naux) ? aux[tid] : 0;
    s[tid] = v;
    __syncthreads();
    for (int off = 1; off < 64; off <<= 1) {
        int t = (tid >= off) ? s[tid - off] : 0;
        __syncthreads();
        s[tid] += t;
        __syncthreads();
    }
    if (tid < naux) aux[tid] = s[tid] - v;
}

// pass 3: add block offsets; copy into cursor; one thread writes rp[n] = nnz.
__global__ __launch_bounds__(1024)
void scan3_all_kernel(int n0, int n1, int n2, int n3)
{
    const int b = blockIdx.x;
    int* rp; int* cur; const int* aux; int n; int lb; int nnz;
    if (b < NB_N)              { rp = g_rp_hht; cur = g_cur_hht; aux = g_aux_hht; n = NROWS; lb = b;                  nnz = n0; }
    else if (b < 2 * NB_N)     { rp = g_rp_h;   cur = g_cur_h;   aux = g_aux_h;   n = NROWS; lb = b - NB_N;           nnz = n1; }
    else if (b < 2*NB_N+NB_M)  { rp = g_rp_ht;  cur = g_cur_ht;  aux = g_aux_ht;  n = MROWS; lb = b - 2*NB_N;         nnz = n2; }
    else                       { rp = g_rp_hth; cur = g_cur_hth; aux = g_aux_hth; n = MROWS; lb = b - 2*NB_N - NB_M;  nnz = n3; }

    const int tid = threadIdx.x;
    const int i = lb * 1024 + tid;
    if (i < n) {
        const int r = rp[i] + aux[lb];
        rp[i] = r;
        cur[i] = r;
    }
    if (lb == 0 && tid == 0) rp[n] = nnz;
}

// K6: gemm_y (fp16 out) interleaved 1:3 with scatter.
__global__ __launch_bounds__(256)
void fused_gemmy_scatter_kernel(const float* __restrict__ y, const float* __restrict__ W0,
                                __half* __restrict__ yw0,
                                const int* __restrict__ r0, const int* __restrict__ c0,
                                const float* __restrict__ v0, int n0,
                                const int* __restrict__ r1, const int* __restrict__ c1,
                                const float* __restrict__ v1, int n1,
                                const int* __restrict__ r2, const int* __restrict__ c2,
                                const float* __restrict__ v2, int n2,
                                const int* __restrict__ r3, const int* __restrict__ c3,
                                const float* __restrict__ v3, int n3)
{
    const int b = blockIdx.x;
    if (b < K6_INTERLEAVE && (b & 3) == 0) {
        const int g = b >> 2;
        gemm_body_h<128, 8>(y, W0, yw0, MROWS, HIDC, HIDC, g & 1, g >> 1);
        return;
    }
    int sid;
    if (b < K6_INTERLEAVE) sid = b - (b >> 2) - 1;
    else                   sid = (K6_INTERLEAVE - GY_BLOCKS) + (b - K6_INTERLEAVE);

    const int total = n0 + n1 + n2 + n3;
    const int stride = SCAT_BLOCKS * 256;
    for (int e = sid * 256 + threadIdx.x; e < total; e += stride) {
        const int* rows; const int* cols; const float* vals;
        int* cur; int2* pe; int el;
        if (e < n0)                { rows = r0; cols = c0; vals = v0; cur = g_cur_hht; pe = g_pe_hht; el = e; }
        else if (e < n0 + n1)      { rows = r1; cols = c1; vals = v1; cur = g_cur_h;   pe = g_pe_h;   el = e - n0; }
        else if (e < n0 + n1 + n2) { rows = r2; cols = c2; vals = v2; cur = g_cur_ht;  pe = g_pe_ht;  el = e - n0 - n1; }
        else                       { rows = r3; cols = c3; vals = v3; cur = g_cur_hth; pe = g_pe_hth; el = e - n0 - n1 - n2; }
        const int r = __ldcs(rows + el);
        const int pos = atomicAdd(cur + r, 1);
        __stcs(pe + pos, make_int2(__ldcs(cols + el), __float_as_int(__ldcs(vals + el))));
    }
}

// ===========================================================================
// Merged CSR SpMM row bodies, fp16 gather sources, fp32 accumulation.
// ===========================================================================
__device__ __forceinline__
void spmm256_row_h(const int* __restrict__ rp, const int2* __restrict__ pe,
                   const __half* __restrict__ src, int row, int lane, float acc[8])
{
    const int s0 = __ldg(rp + row);
    const int s1 = __ldg(rp + row + 1);
    for (int j0 = s0; j0 < s1; j0 += 32) {
        int2 e = make_int2(0, 0);
        if (j0 + lane < s1) e = __ldcs(pe + j0 + lane);
        const int cnt = min(32, s1 - j0);
        for (int t = 0; t < cnt; ++t) {
            const int   ct = __shfl_sync(0xffffffffu, e.x, t);
            const float vt = __int_as_float(__shfl_sync(0xffffffffu, e.y, t));
            // lane covers 8 contiguous halves: cols [lane*8 .. lane*8+7]
            const uint4 u = __ldg((const uint4*)(src + (size_t)ct * HIDC) + lane);
            const __half2* h2 = (const __half2*)&u;
            float2 f;
            f = __half22float2(h2[0]); acc[0] += vt * f.x; acc[1] += vt * f.y;
            f = __half22float2(h2[1]); acc[2] += vt * f.x; acc[3] += vt * f.y;
            f = __half22float2(h2[2]); acc[4] += vt * f.x; acc[5] += vt * f.y;
            f = __half22float2(h2[3]); acc[6] += vt * f.x; acc[7] += vt * f.y;
        }
    }
}

// K=256 merged SpMM over BOTH row spaces; writes leaky(sumA)+leaky(sumB) fp32.
__global__ __launch_bounds__(256)
void spmm256_dual_kernel(const __half* __restrict__ xw0, const __half* __restrict__ yw0,
                         float* __restrict__ x1, float* __restrict__ y1)
{
    const int lane = threadIdx.x & 31;
    const int wb   = blockIdx.x * 8 + (threadIdx.x >> 5);

    float a[8] = {}, b[8] = {};
    float* dst;
    int row;
    if (wb < NROWS) {
        row = wb;
        spmm256_row_h(g_rp_hht, g_pe_hht, xw0, row, lane, a);
        spmm256_row_h(g_rp_h,   g_pe_h,   yw0, row, lane, b);
        dst = x1;
    } else {
        row = wb - NROWS;
        spmm256_row_h(g_rp_ht,  g_pe_ht,  xw0, row, lane, a);
        spmm256_row_h(g_rp_hth, g_pe_hth, yw0, row, lane, b);
        dst = y1;
    }

    float o[8];
    #pragma unroll
    for (int i = 0; i < 8; ++i) o[i] = leaky(a[i]) + leaky(b[i]);
    // lane writes cols [lane*8 .. lane*8+7]
    float4* dp = (float4*)(dst + (size_t)row * HIDC + lane * 8);
    __stcs(dp,     *(float4*)&o[0]);
    __stcs(dp + 1, *(float4*)&o[4]);
}

__device__ __forceinline__
void spmm64_row_h(const int* __restrict__ rp, const int2* __restrict__ pe,
                  const __half* __restrict__ src, int row, int lane16, unsigned gmask,
                  float acc[4])
{
    const int s0 = __ldg(rp + row);
    const int s1 = __ldg(rp + row + 1);
    for (int j0 = s0; j0 < s1; j0 += 16) {
        int2 e = make_int2(0, 0);
        if (j0 + lane16 < s1) e = __ldcs(pe + j0 + lane16);
        const int cnt = min(16, s1 - j0);
        for (int t = 0; t < cnt; ++t) {
            const int   ct = __shfl_sync(gmask, e.x, t, 16);
            const float vt = __int_as_float(__shfl_sync(gmask, e.y, t, 16));
            // lane covers 4 halves: cols [lane16*4 .. lane16*4+3]
            const uint2 u = __ldg((const uint2*)(src + (size_t)ct * OUTC) + lane16);
            const __half2* h2 = (const __half2*)&u;
            float2 f;
            f = __half22float2(h2[0]); acc[0] += vt * f.x; acc[1] += vt * f.y;
            f = __half22float2(h2[1]); acc[2] += vt * f.x; acc[3] += vt * f.y;
        }
    }
}

// K=64 merged SpMM over both row spaces; writes final fp32 output.
__global__ __launch_bounds__(256)
void spmm64_dual_kernel(const __half* __restrict__ xw1, const __half* __restrict__ yw1,
                        float* __restrict__ out)
{
    const int lane32 = threadIdx.x & 31;
    const int lane16 = threadIdx.x & 15;
    const unsigned gmask = 0xFFFFu << (lane32 & 16);
    const int wb = blockIdx.x * 16 + (threadIdx.x >> 4);

    float a[4] = {}, b[4] = {};
    float* dst;
    int row;
    if (wb < NROWS) {
        row = wb;
        spmm64_row_h(g_rp_hht, g_pe_hht, xw1, row, lane16, gmask, a);
        spmm64_row_h(g_rp_h,   g_pe_h,   yw1, row, lane16, gmask, b);
        dst = out;
    } else {
        row = wb - NROWS;
        spmm64_row_h(g_rp_ht,  g_pe_ht,  xw1, row, lane16, gmask, a);
        spmm64_row_h(g_rp_hth, g_pe_hth, yw1, row, lane16, gmask, b);
        dst = out + (size_t)NROWS * OUTC;
    }

    float o[4];
    #pragma unroll
    for (int i = 0; i < 4; ++i) o[i] = leaky(a[i]) + leaky(b[i]);
    __stcs((float4*)(dst + (size_t)row * OUTC + lane16 * 4), *(float4*)&o[0]);
}

// Merged layer-1 GEMM (fp32 in, fp16 out): [0,391) -> x1@W1, rest -> y1@W1.
#define G1X_BLOCKS 391
__global__ __launch_bounds__(256)
void gemm1_dual_kernel(const float* __restrict__ x1, const float* __restrict__ y1,
                       const float* __restrict__ W1,
                       __half* __restrict__ xw1, __half* __restrict__ yw1)
{
    const int b = blockIdx.x;
    if (b < G1X_BLOCKS)
        gemm_body_h<64, 4>(x1, W1, xw1, NROWS, HIDC, OUTC, 0, b);
    else
        gemm_body_h<64, 4>(y1, W1, yw1, MROWS, HIDC, OUTC, 0, b - G1X_BLOCKS);
}

// ---------------------------------------------------------------------------
// Launch
// ---------------------------------------------------------------------------
extern "C" void kernel_launch(void* const* d_in, const int* in_sizes, int n_in,
                              void* d_out, int out_size)
{
    const float* x   = (const float*)d_in[0];
    const float* y   = (const float*)d_in[1];
    const float* W0  = (const float*)d_in[2];
    const float* W1  = (const float*)d_in[3];
    const int*   hht_r = (const int*)d_in[4];
    const int*   hht_c = (const int*)d_in[5];
    const float* hht_v = (const float*)d_in[6];
    const int*   h_r   = (const int*)d_in[7];
    const int*   h_c   = (const int*)d_in[8];
    const float* h_v   = (const float*)d_in[9];
    const int*   ht_r  = (const int*)d_in[10];
    const int*   ht_c  = (const int*)d_in[11];
    const float* ht_v  = (const float*)d_in[12];
    const int*   hth_r = (const int*)d_in[13];
    const int*   hth_c = (const int*)d_in[14];
    const float* hth_v = (const float*)d_in[15];

    const int nnz_hht = in_sizes[4];
    const int nnz_h   = in_sizes[7];
    const int nnz_ht  = in_sizes[10];
    const int nnz_hth = in_sizes[13];

    __half *xw0, *yw0, *xw1, *yw1;
    float  *x1, *y1;
    cudaGetSymbolAddress((void**)&xw0, g_xw0);
    cudaGetSymbolAddress((void**)&yw0, g_yw0);
    cudaGetSymbolAddress((void**)&x1,  g_x1);
    cudaGetSymbolAddress((void**)&y1,  g_y1);
    cudaGetSymbolAddress((void**)&xw1, g_xw1);
    cudaGetSymbolAddress((void**)&yw1, g_yw1);

    float* out = (float*)d_out;

    const int SCAN_BLOCKS = 2 * NB_N + 2 * NB_M;   // 138

    // K1: zero histogram counters
    zero_counts_kernel<<<(NROWS + 255) / 256, 256>>>();

    // K2: x@W0 GEMM (fp16 out) co-scheduled with the 4-matrix histogram
    fused_gemmx_hist_kernel<<<GX_BLOCKS + HIST_BLOCKS, 256>>>(
        x, W0, xw0,
        hht_r, nnz_hht, h_r, nnz_h, ht_r, nnz_ht, hth_r, nnz_hth);

    // K3..K5: rowptr scans
    scan1_all_kernel<<<SCAN_BLOCKS, 1024>>>();
    scan2_all_kernel<<<4, 64>>>();
    scan3_all_kernel<<<SCAN_BLOCKS, 1024>>>(nnz_hht, nnz_h, nnz_ht, nnz_hth);

    // K6: y@W0 GEMM (fp16 out) interleaved with the COO->CSR scatter
    fused_gemmy_scatter_kernel<<<K6_BLOCKS, 256>>>(
        y, W0, yw0,
        hht_r, hht_c, hht_v, nnz_hht,
        h_r,   h_c,   h_v,   nnz_h,
        ht_r,  ht_c,  ht_v,  nnz_ht,
        hth_r, hth_c, hth_v, nnz_hth);

    // K7: layer-0 SpMM over both row spaces (fp16 gathers, fp32 accum)
    spmm256_dual_kernel<<<NROWS / 8 + MROWS / 8, 256>>>(xw0, yw0, x1, y1);

    // K8: layer-1 GEMM (fp32 in, fp16 out)
    gemm1_dual_kernel<<<G1X_BLOCKS + 157, 256>>>(x1, y1, W1, xw1, yw1);

    // K9: layer-1 SpMM (fp16 gathers), writes final fp32 output
    spmm64_dual_kernel<<<NROWS / 16 + MROWS / 16, 256>>>(xw1, yw1, out);
}

// round 13
// speedup vs baseline: 3.5336x; 1.4632x over previous
#include <cuda_runtime.h>
#include <cuda_fp16.h>
#include <cstdint>
#include <cstddef>

// Problem constants (match reference)
#define NROWS 50000
#define MROWS 20000
#define HIDC  256
#define OUTC  64
#define NNZ_HHT 1600000
#define NNZ_H   1000000
#define NNZ_HT  1000000
#define NNZ_HTH  640000

#define NB_N 49   // ceil(NROWS/1024)
#define NB_M 20   // ceil(MROWS/1024)

// GEMM tiling: BM=128, BN=64 -> tiles per GEMM
#define GXT 1564   // 4 col-tiles * 391 row-tiles (x@W0, Nc=256)
#define GYT 628    // 4 * 157                     (y@W0)
#define HIST_BLOCKS 1024
#define SCAT_BLOCKS 1024
#define K2_BLOCKS (GXT + HIST_BLOCKS)             // 2588, interleaved below
#define K6_BLOCKS (2 * GYT + (SCAT_BLOCKS - GYT)) // 1652

// ---------------------------------------------------------------------------
// Static device scratch. Gather tables AND x1/y1 are fp16.
// ---------------------------------------------------------------------------
__device__ __align__(16) __half g_xw0[(size_t)NROWS * HIDC];
__device__ __align__(16) __half g_yw0[(size_t)MROWS * HIDC];
__device__ __align__(16) __half g_x1 [(size_t)NROWS * HIDC];
__device__ __align__(16) __half g_y1 [(size_t)MROWS * HIDC];
__device__ __align__(16) __half g_xw1[(size_t)NROWS * OUTC];
__device__ __align__(16) __half g_yw1[(size_t)MROWS * OUTC];

// CSR structures (built on device each launch)
__device__ int  g_cnt_hht[NROWS],  g_rp_hht[NROWS + 1],  g_cur_hht[NROWS];
__device__ int  g_cnt_h  [NROWS],  g_rp_h  [NROWS + 1],  g_cur_h  [NROWS];
__device__ int  g_cnt_ht [MROWS],  g_rp_ht [MROWS + 1],  g_cur_ht [MROWS];
__device__ int  g_cnt_hth[MROWS],  g_rp_hth[MROWS + 1],  g_cur_hth[MROWS];
__device__ int  g_aux_hht[64], g_aux_h[64], g_aux_ht[64], g_aux_hth[64];
__device__ int2 g_pe_hht[NNZ_HHT];
__device__ int2 g_pe_h  [NNZ_H];
__device__ int2 g_pe_ht [NNZ_HT];
__device__ int2 g_pe_hth[NNZ_HTH];

__device__ __forceinline__ float leaky(float v) {
    return v >= 0.0f ? v : 0.2f * v;
}
__device__ __forceinline__ uint32_t smem_u32(const void* p) {
    return (uint32_t)__cvta_generic_to_shared(p);
}

// ===========================================================================
// Tensor-core GEMM body: C[Mr,Nc](fp16) = A[Mr,K] @ B[K,Nc](fp32)
// A source fp32 (layer 0) or fp16 (layer 1), converted/copied into fp16 smem.
// BM=128, BN=64, BK=32; 8 warps (4m x 2n), warp tile 32x32 via m16n8k16 mma.
// ===========================================================================
template<typename AT>
__device__ __forceinline__
void gemm_mma_body(const AT* __restrict__ A, const float* __restrict__ B,
                   __half* __restrict__ C, int Mr, int K, int Nc, int bx, int by)
{
    constexpr int BM = 128, BN = 64, BK = 32;
    __shared__ __half As[BM][BK + 8];   // pitch 40 halves = 80B (16B multiple)
    __shared__ __half Bs[BK][BN + 8];   // pitch 72 halves = 144B

    const int tid  = threadIdx.x;
    const int lane = tid & 31;
    const int wid  = tid >> 5;
    const int wm   = wid >> 1;          // 0..3
    const int wn   = wid & 1;           // 0..1
    const int row0 = by * BM;
    const int col0 = bx * BN;

    float acc[2][4][4];
    #pragma unroll
    for (int i = 0; i < 2; ++i)
        #pragma unroll
        for (int j = 0; j < 4; ++j)
            #pragma unroll
            for (int e = 0; e < 4; ++e) acc[i][j][e] = 0.f;

    for (int k0 = 0; k0 < K; k0 += BK) {
        // ---- A tile 128x32 -> fp16 smem ----
        if (sizeof(AT) == 4) {
            #pragma unroll
            for (int t = 0; t < 4; ++t) {
                const int li = tid + t * 256;        // 0..1023 float4 slots
                const int r  = li >> 3;
                const int kc = (li & 7) * 4;
                float4 v = make_float4(0.f, 0.f, 0.f, 0.f);
                if (row0 + r < Mr)
                    v = *(const float4*)((const float*)A + (size_t)(row0 + r) * K + k0 + kc);
                *(__half2*)&As[r][kc]     = __floats2half2_rn(v.x, v.y);
                *(__half2*)&As[r][kc + 2] = __floats2half2_rn(v.z, v.w);
            }
        } else {
            #pragma unroll
            for (int t = 0; t < 2; ++t) {
                const int li = tid + t * 256;        // 0..511 uint4 slots
                const int r  = li >> 2;
                const int kc = (li & 3) * 8;
                uint4 v = make_uint4(0, 0, 0, 0);
                if (row0 + r < Mr)
                    v = *(const uint4*)((const __half*)A + (size_t)(row0 + r) * K + k0 + kc);
                *(uint4*)&As[r][kc] = v;
            }
        }
        // ---- B tile 32x64 fp32 -> fp16 smem ----
        #pragma unroll
        for (int t = 0; t < 2; ++t) {
            const int li = tid + t * 256;            // 0..511 float4 slots
            const int r  = li >> 4;                  // 16 float4 per row
            const int c  = (li & 15) * 4;
            const float4 v = *(const float4*)(B + (size_t)(k0 + r) * Nc + col0 + c);
            *(__half2*)&Bs[r][c]     = __floats2half2_rn(v.x, v.y);
            *(__half2*)&Bs[r][c + 2] = __floats2half2_rn(v.z, v.w);
        }
        __syncthreads();

        #pragma unroll
        for (int kk = 0; kk < BK; kk += 16) {
            uint32_t a[2][4];
            #pragma unroll
            for (int mi = 0; mi < 2; ++mi) {
                const int rsel = wm * 32 + mi * 16 + (lane & 15);
                const int csel = kk + (lane >> 4) * 8;
                const uint32_t addr = smem_u32(&As[rsel][csel]);
                asm volatile("ldmatrix.sync.aligned.m8n8.x4.shared.b16 {%0,%1,%2,%3}, [%4];"
                    : "=r"(a[mi][0]), "=r"(a[mi][1]), "=r"(a[mi][2]), "=r"(a[mi][3])
                    : "r"(addr));
            }
            uint32_t bf[4][2];
            #pragma unroll
            for (int nb = 0; nb < 2; ++nb) {
                const int ksel = kk + (lane & 15);
                const int nsel = wn * 32 + nb * 16 + (lane >> 4) * 8;
                const uint32_t addr = smem_u32(&Bs[ksel][nsel]);
                uint32_t r0, r1, r2, r3;
                asm volatile("ldmatrix.sync.aligned.m8n8.x4.trans.shared.b16 {%0,%1,%2,%3}, [%4];"
                    : "=r"(r0), "=r"(r1), "=r"(r2), "=r"(r3) : "r"(addr));
                bf[nb * 2 + 0][0] = r0; bf[nb * 2 + 0][1] = r1;
                bf[nb * 2 + 1][0] = r2; bf[nb * 2 + 1][1] = r3;
            }
            #pragma unroll
            for (int mi = 0; mi < 2; ++mi)
                #pragma unroll
                for (int nj = 0; nj < 4; ++nj)
                    asm volatile("mma.sync.aligned.m16n8k16.row.col.f32.f16.f16.f32 "
                        "{%0,%1,%2,%3}, {%4,%5,%6,%7}, {%8,%9}, {%0,%1,%2,%3};"
                        : "+f"(acc[mi][nj][0]), "+f"(acc[mi][nj][1]),
                          "+f"(acc[mi][nj][2]), "+f"(acc[mi][nj][3])
                        : "r"(a[mi][0]), "r"(a[mi][1]), "r"(a[mi][2]), "r"(a[mi][3]),
                          "r"(bf[nj][0]), "r"(bf[nj][1]));
        }
        __syncthreads();
    }

    // epilogue: c-fragment layout row=(lane>>2)[+8], col=(lane&3)*2
    const int g  = lane >> 2;
    const int t4 = lane & 3;
    #pragma unroll
    for (int mi = 0; mi < 2; ++mi) {
        #pragma unroll
        for (int nj = 0; nj < 4; ++nj) {
            const int col = col0 + wn * 32 + nj * 8 + t4 * 2;
            const int ra = row0 + wm * 32 + mi * 16 + g;
            const int rb = ra + 8;
            if (ra < Mr)
                *(__half2*)(C + (size_t)ra * Nc + col) =
                    __floats2half2_rn(acc[mi][nj][0], acc[mi][nj][1]);
            if (rb < Mr)
                *(__half2*)(C + (size_t)rb * Nc + col) =
                    __floats2half2_rn(acc[mi][nj][2], acc[mi][nj][3]);
        }
    }
}

// ===========================================================================
// CSR build kernels
// ===========================================================================
__global__ __launch_bounds__(256)
void zero_counts_kernel()
{
    const int i = blockIdx.x * blockDim.x + threadIdx.x;
    if (i < NROWS) { g_cnt_hht[i] = 0; g_cnt_h[i] = 0; }
    if (i < MROWS) { g_cnt_ht[i]  = 0; g_cnt_hth[i] = 0; }
}

// K2: x@W0 (mma, fp16 out) interleaved with the 4-matrix histogram.
// b in [0,2048): even -> gemm (b>>1), odd -> hist (b>>1); b>=2048 -> gemm (b-1024).
__global__ __launch_bounds__(256)
void fused_gemmx_hist_kernel(const float* __restrict__ x, const float* __restrict__ W0,
                             __half* __restrict__ xw0,
                             const int* __restrict__ r0, int n0,
                             const int* __restrict__ r1, int n1,
                             const int* __restrict__ r2, int n2,
                             const int* __restrict__ r3, int n3)
{
    const int b = blockIdx.x;
    int gid = -1, hb = -1;
    if (b < 2 * HIST_BLOCKS) { if ((b & 1) == 0) gid = b >> 1; else hb = b >> 1; }
    else                     gid = b - HIST_BLOCKS;

    if (gid >= 0) {
        gemm_mma_body<float>(x, W0, xw0, NROWS, HIDC, HIDC, gid & 3, gid >> 2);
    } else {
        const int total = n0 + n1 + n2 + n3;
        const int stride = HIST_BLOCKS * 256;
        for (int e = hb * 256 + threadIdx.x; e < total; e += stride) {
            if (e < n0)                atomicAdd(g_cnt_hht + __ldcs(r0 + e), 1);
            else if (e < n0 + n1)      atomicAdd(g_cnt_h   + __ldcs(r1 + e - n0), 1);
            else if (e < n0 + n1 + n2) atomicAdd(g_cnt_ht  + __ldcs(r2 + e - n0 - n1), 1);
            else                       atomicAdd(g_cnt_hth + __ldcs(r3 + e - n0 - n1 - n2), 1);
        }
    }
}

// pass 1: per-block exclusive scan of counts; aux[b] = block sum.
__global__ __launch_bounds__(1024)
void scan1_all_kernel()
{
    const int b = blockIdx.x;
    const int* cnt; int* rp; int* aux; int n; int lb;
    if (b < NB_N)              { cnt = g_cnt_hht; rp = g_rp_hht; aux = g_aux_hht; n = NROWS; lb = b; }
    else if (b < 2 * NB_N)     { cnt = g_cnt_h;   rp = g_rp_h;   aux = g_aux_h;   n = NROWS; lb = b - NB_N; }
    else if (b < 2*NB_N+NB_M)  { cnt = g_cnt_ht;  rp = g_rp_ht;  aux = g_aux_ht;  n = MROWS; lb = b - 2*NB_N; }
    else                       { cnt = g_cnt_hth; rp = g_rp_hth; aux = g_aux_hth; n = MROWS; lb = b - 2*NB_N - NB_M; }

    __shared__ int s[1024];
    const int tid = threadIdx.x;
    const int i = lb * 1024 + tid;
    const int v = (i < n) ? cnt[i] : 0;
    s[tid] = v;
    __syncthreads();
    for (int off = 1; off < 1024; off <<= 1) {
        int t = (tid >= off) ? s[tid - off] : 0;
        __syncthreads();
        s[tid] += t;
        __syncthreads();
    }
    if (i < n) rp[i] = s[tid] - v;
    if (tid == 1023) aux[lb] = s[1023];
}

// pass 2 (all four aux arrays, block per array)
__global__ __launch_bounds__(64)
void scan2_all_kernel()
{
    int* aux; int naux;
    switch (blockIdx.x) {
        case 0:  aux = g_aux_hht; naux = NB_N; break;
        case 1:  aux = g_aux_h;   naux = NB_N; break;
        case 2:  aux = g_aux_ht;  naux = NB_M; break;
        default: aux = g_aux_hth; naux = NB_M; break;
    }
    __shared__ int s[64];
    const int tid = threadIdx.x;
    const int v = (tid < naux) ? aux[tid] : 0;
    s[tid] = v;
    __syncthreads();
    for (int off = 1; off < 64; off <<= 1) {
        int t = (tid >= off) ? s[tid - off] : 0;
        __syncthreads();
        s[tid] += t;
        __syncthreads();
    }
    if (tid < naux) aux[tid] = s[tid] - v;
}

// pass 3: add block offsets; copy into cursor; one thread writes rp[n] = nnz.
__global__ __launch_bounds__(1024)
void scan3_all_kernel(int n0, int n1, int n2, int n3)
{
    const int b = blockIdx.x;
    int* rp; int* cur; const int* aux; int n; int lb; int nnz;
    if (b < NB_N)              { rp = g_rp_hht; cur = g_cur_hht; aux = g_aux_hht; n = NROWS; lb = b;                  nnz = n0; }
    else if (b < 2 * NB_N)     { rp = g_rp_h;   cur = g_cur_h;   aux = g_aux_h;   n = NROWS; lb = b - NB_N;           nnz = n1; }
    else if (b < 2*NB_N+NB_M)  { rp = g_rp_ht;  cur = g_cur_ht;  aux = g_aux_ht;  n = MROWS; lb = b - 2*NB_N;         nnz = n2; }
    else                       { rp = g_rp_hth; cur = g_cur_hth; aux = g_aux_hth; n = MROWS; lb = b - 2*NB_N - NB_M;  nnz = n3; }

    const int tid = threadIdx.x;
    const int i = lb * 1024 + tid;
    if (i < n) {
        const int r = rp[i] + aux[lb];
        rp[i] = r;
        cur[i] = r;
    }
    if (lb == 0 && tid == 0) rp[n] = nnz;
}

// K6: y@W0 (mma) interleaved 1:1 with scatter.
// b in [0, 2*GYT): even -> gemm (b>>1), odd -> scatter (b>>1); b>=2*GYT -> scatter.
__global__ __launch_bounds__(256)
void fused_gemmy_scatter_kernel(const float* __restrict__ y, const float* __restrict__ W0,
                                __half* __restrict__ yw0,
                                const int* __restrict__ r0, const int* __restrict__ c0,
                                const float* __restrict__ v0, int n0,
                                const int* __restrict__ r1, const int* __restrict__ c1,
                                const float* __restrict__ v1, int n1,
                                const int* __restrict__ r2, const int* __restrict__ c2,
                                const float* __restrict__ v2, int n2,
                                const int* __restrict__ r3, const int* __restrict__ c3,
                                const float* __restrict__ v3, int n3)
{
    const int b = blockIdx.x;
    int sid;
    if (b < 2 * GYT) {
        if ((b & 1) == 0) {
            const int g = b >> 1;
            gemm_mma_body<float>(y, W0, yw0, MROWS, HIDC, HIDC, g & 3, g >> 2);
            return;
        }
        sid = b >> 1;                       // 0..GYT-1
    } else {
        sid = GYT + (b - 2 * GYT);          // GYT..SCAT_BLOCKS-1
    }

    const int total = n0 + n1 + n2 + n3;
    const int stride = SCAT_BLOCKS * 256;
    for (int e = sid * 256 + threadIdx.x; e < total; e += stride) {
        const int* rows; const int* cols; const float* vals;
        int* cur; int2* pe; int el;
        if (e < n0)                { rows = r0; cols = c0; vals = v0; cur = g_cur_hht; pe = g_pe_hht; el = e; }
        else if (e < n0 + n1)      { rows = r1; cols = c1; vals = v1; cur = g_cur_h;   pe = g_pe_h;   el = e - n0; }
        else if (e < n0 + n1 + n2) { rows = r2; cols = c2; vals = v2; cur = g_cur_ht;  pe = g_pe_ht;  el = e - n0 - n1; }
        else                       { rows = r3; cols = c3; vals = v3; cur = g_cur_hth; pe = g_pe_hth; el = e - n0 - n1 - n2; }
        const int r = __ldcs(rows + el);
        const int pos = atomicAdd(cur + r, 1);
        __stcs(pe + pos, make_int2(__ldcs(cols + el), __float_as_int(__ldcs(vals + el))));
    }
}

// ===========================================================================
// Merged CSR SpMM row bodies, fp16 gather sources, fp32 accumulation.
// ===========================================================================
__device__ __forceinline__
void spmm256_row_h(const int* __restrict__ rp, const int2* __restrict__ pe,
                   const __half* __restrict__ src, int row, int lane, float acc[8])
{
    const int s0 = __ldg(rp + row);
    const int s1 = __ldg(rp + row + 1);
    for (int j0 = s0; j0 < s1; j0 += 32) {
        int2 e = make_int2(0, 0);
        if (j0 + lane < s1) e = __ldcs(pe + j0 + lane);
        const int cnt = min(32, s1 - j0);
        for (int t = 0; t < cnt; ++t) {
            const int   ct = __shfl_sync(0xffffffffu, e.x, t);
            const float vt = __int_as_float(__shfl_sync(0xffffffffu, e.y, t));
            const uint4 u = __ldg((const uint4*)(src + (size_t)ct * HIDC) + lane);
            const __half2* h2 = (const __half2*)&u;
            float2 f;
            f = __half22float2(h2[0]); acc[0] += vt * f.x; acc[1] += vt * f.y;
            f = __half22float2(h2[1]); acc[2] += vt * f.x; acc[3] += vt * f.y;
            f = __half22float2(h2[2]); acc[4] += vt * f.x; acc[5] += vt * f.y;
            f = __half22float2(h2[3]); acc[6] += vt * f.x; acc[7] += vt * f.y;
        }
    }
}

// K=256 merged SpMM over BOTH row spaces; writes leaky(sumA)+leaky(sumB) fp16.
__global__ __launch_bounds__(256)
void spmm256_dual_kernel(const __half* __restrict__ xw0, const __half* __restrict__ yw0,
                         __half* __restrict__ x1, __half* __restrict__ y1)
{
    const int lane = threadIdx.x & 31;
    const int wb   = blockIdx.x * 8 + (threadIdx.x >> 5);

    float a[8] = {}, b[8] = {};
    __half* dst;
    int row;
    if (wb < NROWS) {
        row = wb;
        spmm256_row_h(g_rp_hht, g_pe_hht, xw0, row, lane, a);
        spmm256_row_h(g_rp_h,   g_pe_h,   yw0, row, lane, b);
        dst = x1;
    } else {
        row = wb - NROWS;
        spmm256_row_h(g_rp_ht,  g_pe_ht,  xw0, row, lane, a);
        spmm256_row_h(g_rp_hth, g_pe_hth, yw0, row, lane, b);
        dst = y1;
    }

    __half2 o[4];
    #pragma unroll
    for (int i = 0; i < 4; ++i)
        o[i] = __floats2half2_rn(leaky(a[2*i]) + leaky(b[2*i]),
                                 leaky(a[2*i+1]) + leaky(b[2*i+1]));
    __stcs((uint4*)(dst + (size_t)row * HIDC + lane * 8), *(uint4*)o);
}

__device__ __forceinline__
void spmm64_row_h(const int* __restrict__ rp, const int2* __restrict__ pe,
                  const __half* __restrict__ src, int row, int lane16, unsigned gmask,
                  float acc[4])
{
    const int s0 = __ldg(rp + row);
    const int s1 = __ldg(rp + row + 1);
    for (int j0 = s0; j0 < s1; j0 += 16) {
        int2 e = make_int2(0, 0);
        if (j0 + lane16 < s1) e = __ldcs(pe + j0 + lane16);
        const int cnt = min(16, s1 - j0);
        for (int t = 0; t < cnt; ++t) {
            const int   ct = __shfl_sync(gmask, e.x, t, 16);
            const float vt = __int_as_float(__shfl_sync(gmask, e.y, t, 16));
            const uint2 u = __ldg((const uint2*)(src + (size_t)ct * OUTC) + lane16);
            const __half2* h2 = (const __half2*)&u;
            float2 f;
            f = __half22float2(h2[0]); acc[0] += vt * f.x; acc[1] += vt * f.y;
            f = __half22float2(h2[1]); acc[2] += vt * f.x; acc[3] += vt * f.y;
        }
    }
}

// K=64 merged SpMM over both row spaces; writes final fp32 output.
__global__ __launch_bounds__(256)
void spmm64_dual_kernel(const __half* __restrict__ xw1, const __half* __restrict__ yw1,
                        float* __restrict__ out)
{
    const int lane32 = threadIdx.x & 31;
    const int lane16 = threadIdx.x & 15;
    const unsigned gmask = 0xFFFFu << (lane32 & 16);
    const int wb = blockIdx.x * 16 + (threadIdx.x >> 4);

    float a[4] = {}, b[4] = {};
    float* dst;
    int row;
    if (wb < NROWS) {
        row = wb;
        spmm64_row_h(g_rp_hht, g_pe_hht, xw1, row, lane16, gmask, a);
        spmm64_row_h(g_rp_h,   g_pe_h,   yw1, row, lane16, gmask, b);
        dst = out;
    } else {
        row = wb - NROWS;
        spmm64_row_h(g_rp_ht,  g_pe_ht,  xw1, row, lane16, gmask, a);
        spmm64_row_h(g_rp_hth, g_pe_hth, yw1, row, lane16, gmask, b);
        dst = out + (size_t)NROWS * OUTC;
    }

    float o[4];
    #pragma unroll
    for (int i = 0; i < 4; ++i) o[i] = leaky(a[i]) + leaky(b[i]);
    __stcs((float4*)(dst + (size_t)row * OUTC + lane16 * 4), *(float4*)&o[0]);
}

// K8: merged layer-1 GEMM (fp16 A, fp32 W1, fp16 out): [0,391) x1, rest y1.
#define G1X_BLOCKS 391
__global__ __launch_bounds__(256)
void gemm1_dual_kernel(const __half* __restrict__ x1, const __half* __restrict__ y1,
                       const float* __restrict__ W1,
                       __half* __restrict__ xw1, __half* __restrict__ yw1)
{
    const int b = blockIdx.x;
    if (b < G1X_BLOCKS)
        gemm_mma_body<__half>(x1, W1, xw1, NROWS, HIDC, OUTC, 0, b);
    else
        gemm_mma_body<__half>(y1, W1, yw1, MROWS, HIDC, OUTC, 0, b - G1X_BLOCKS);
}

// ---------------------------------------------------------------------------
// Launch
// ---------------------------------------------------------------------------
extern "C" void kernel_launch(void* const* d_in, const int* in_sizes, int n_in,
                              void* d_out, int out_size)
{
    const float* x   = (const float*)d_in[0];
    const float* y   = (const float*)d_in[1];
    const float* W0  = (const float*)d_in[2];
    const float* W1  = (const float*)d_in[3];
    const int*   hht_r = (const int*)d_in[4];
    const int*   hht_c = (const int*)d_in[5];
    const float* hht_v = (const float*)d_in[6];
    const int*   h_r   = (const int*)d_in[7];
    const int*   h_c   = (const int*)d_in[8];
    const float* h_v   = (const float*)d_in[9];
    const int*   ht_r  = (const int*)d_in[10];
    const int*   ht_c  = (const int*)d_in[11];
    const float* ht_v  = (const float*)d_in[12];
    const int*   hth_r = (const int*)d_in[13];
    const int*   hth_c = (const int*)d_in[14];
    const float* hth_v = (const float*)d_in[15];

    const int nnz_hht = in_sizes[4];
    const int nnz_h   = in_sizes[7];
    const int nnz_ht  = in_sizes[10];
    const int nnz_hth = in_sizes[13];

    __half *xw0, *yw0, *x1, *y1, *xw1, *yw1;
    cudaGetSymbolAddress((void**)&xw0, g_xw0);
    cudaGetSymbolAddress((void**)&yw0, g_yw0);
    cudaGetSymbolAddress((void**)&x1,  g_x1);
    cudaGetSymbolAddress((void**)&y1,  g_y1);
    cudaGetSymbolAddress((void**)&xw1, g_xw1);
    cudaGetSymbolAddress((void**)&yw1, g_yw1);

    float* out = (float*)d_out;

    const int SCAN_BLOCKS = 2 * NB_N + 2 * NB_M;   // 138

    // K1: zero histogram counters
    zero_counts_kernel<<<(NROWS + 255) / 256, 256>>>();

    // K2: x@W0 tensor-core GEMM interleaved with the 4-matrix histogram
    fused_gemmx_hist_kernel<<<K2_BLOCKS, 256>>>(
        x, W0, xw0,
        hht_r, nnz_hht, h_r, nnz_h, ht_r, nnz_ht, hth_r, nnz_hth);

    // K3..K5: rowptr scans
    scan1_all_kernel<<<SCAN_BLOCKS, 1024>>>();
    scan2_all_kernel<<<4, 64>>>();
    scan3_all_kernel<<<SCAN_BLOCKS, 1024>>>(nnz_hht, nnz_h, nnz_ht, nnz_hth);

    // K6: y@W0 tensor-core GEMM interleaved with the COO->CSR scatter
    fused_gemmy_scatter_kernel<<<K6_BLOCKS, 256>>>(
        y, W0, yw0,
        hht_r, hht_c, hht_v, nnz_hht,
        h_r,   h_c,   h_v,   nnz_h,
        ht_r,  ht_c,  ht_v,  nnz_ht,
        hth_r, hth_c, hth_v, nnz_hth);

    // K7: layer-0 SpMM over both row spaces (fp16 gathers/out, fp32 accum)
    spmm256_dual_kernel<<<NROWS / 8 + MROWS / 8, 256>>>(xw0, yw0, x1, y1);

    // K8: layer-1 tensor-core GEMM (fp16 in, fp16 out)
    gemm1_dual_kernel<<<G1X_BLOCKS + 157, 256>>>(x1, y1, W1, xw1, yw1);

    // K9: layer-1 SpMM (fp16 gathers), writes final fp32 output
    spmm64_dual_kernel<<<NROWS / 16 + MROWS / 16, 256>>>(xw1, yw1, out);
}

// round 14
// speedup vs baseline: 3.6996x; 1.0470x over previous
#include <cuda_runtime.h>
#include <cuda_fp16.h>
#include <cstdint>
#include <cstddef>

// Problem constants (match reference)
#define NROWS 50000
#define MROWS 20000
#define HIDC  256
#define OUTC  64
#define NNZ_HHT 1600000
#define NNZ_H   1000000
#define NNZ_HT  1000000
#define NNZ_HTH  640000

#define NB_N 49   // ceil(NROWS/1024)
#define NB_M 20   // ceil(MROWS/1024)
#define SCAN_BLOCKS (2 * NB_N + 2 * NB_M)   // 138 (all co-resident on 148 SMs)

// GEMM tiling: BM=128, BN=64 -> tiles per GEMM
#define GXT 1564   // 4 col-tiles * 391 row-tiles (x@W0, Nc=256)
#define GYT 628    // 4 * 157                     (y@W0)
#define HIST_BLOCKS 1024
#define SCAT_BLOCKS 1024
#define K2_BLOCKS (GXT + HIST_BLOCKS)             // 2588
#define K6_BLOCKS (2 * GYT + (SCAT_BLOCKS - GYT)) // 1652

// ---------------------------------------------------------------------------
// Static device scratch. Gather tables AND x1/y1 are fp16.
// ---------------------------------------------------------------------------
__device__ __align__(16) __half g_xw0[(size_t)NROWS * HIDC];
__device__ __align__(16) __half g_yw0[(size_t)MROWS * HIDC];
__device__ __align__(16) __half g_x1 [(size_t)NROWS * HIDC];
__device__ __align__(16) __half g_y1 [(size_t)MROWS * HIDC];
__device__ __align__(16) __half g_xw1[(size_t)NROWS * OUTC];
__device__ __align__(16) __half g_yw1[(size_t)MROWS * OUTC];

// CSR structures (built on device each launch).
// cnt arrays are zeroed at the END of scan_fused (static zero-init covers run 1).
__device__ int  g_cnt_hht[NROWS],  g_rp_hht[NROWS + 1],  g_cur_hht[NROWS];
__device__ int  g_cnt_h  [NROWS],  g_rp_h  [NROWS + 1],  g_cur_h  [NROWS];
__device__ int  g_cnt_ht [MROWS],  g_rp_ht [MROWS + 1],  g_cur_ht [MROWS];
__device__ int  g_cnt_hth[MROWS],  g_rp_hth[MROWS + 1],  g_cur_hth[MROWS];
__device__ int  g_aux_hht[64], g_aux_h[64], g_aux_ht[64], g_aux_hth[64];
__device__ unsigned g_bar;   // monotonic grid-barrier ticket counter
__device__ int2 g_pe_hht[NNZ_HHT];
__device__ int2 g_pe_h  [NNZ_H];
__device__ int2 g_pe_ht [NNZ_HT];
__device__ int2 g_pe_hth[NNZ_HTH];

__device__ __forceinline__ float leaky(float v) {
    return v >= 0.0f ? v : 0.2f * v;
}
__device__ __forceinline__ uint32_t smem_u32(const void* p) {
    return (uint32_t)__cvta_generic_to_shared(p);
}

// ===========================================================================
// Tensor-core GEMM body: C[Mr,Nc](fp16) = A[Mr,K] @ B[K,Nc](fp32)
// A source fp32 (layer 0) or fp16 (layer 1), converted/copied into fp16 smem.
// BM=128, BN=64, BK=32; 8 warps (4m x 2n), warp tile 32x32 via m16n8k16 mma.
// ===========================================================================
template<typename AT>
__device__ __forceinline__
void gemm_mma_body(const AT* __restrict__ A, const float* __restrict__ B,
                   __half* __restrict__ C, int Mr, int K, int Nc, int bx, int by)
{
    constexpr int BM = 128, BN = 64, BK = 32;
    __shared__ __half As[BM][BK + 8];
    __shared__ __half Bs[BK][BN + 8];

    const int tid  = threadIdx.x;
    const int lane = tid & 31;
    const int wid  = tid >> 5;
    const int wm   = wid >> 1;
    const int wn   = wid & 1;
    const int row0 = by * BM;
    const int col0 = bx * BN;

    float acc[2][4][4];
    #pragma unroll
    for (int i = 0; i < 2; ++i)
        #pragma unroll
        for (int j = 0; j < 4; ++j)
            #pragma unroll
            for (int e = 0; e < 4; ++e) acc[i][j][e] = 0.f;

    for (int k0 = 0; k0 < K; k0 += BK) {
        if (sizeof(AT) == 4) {
            #pragma unroll
            for (int t = 0; t < 4; ++t) {
                const int li = tid + t * 256;
                const int r  = li >> 3;
                const int kc = (li & 7) * 4;
                float4 v = make_float4(0.f, 0.f, 0.f, 0.f);
                if (row0 + r < Mr)
                    v = *(const float4*)((const float*)A + (size_t)(row0 + r) * K + k0 + kc);
                *(__half2*)&As[r][kc]     = __floats2half2_rn(v.x, v.y);
                *(__half2*)&As[r][kc + 2] = __floats2half2_rn(v.z, v.w);
            }
        } else {
            #pragma unroll
            for (int t = 0; t < 2; ++t) {
                const int li = tid + t * 256;
                const int r  = li >> 2;
                const int kc = (li & 3) * 8;
                uint4 v = make_uint4(0, 0, 0, 0);
                if (row0 + r < Mr)
                    v = *(const uint4*)((const __half*)A + (size_t)(row0 + r) * K + k0 + kc);
                *(uint4*)&As[r][kc] = v;
            }
        }
        #pragma unroll
        for (int t = 0; t < 2; ++t) {
            const int li = tid + t * 256;
            const int r  = li >> 4;
            const int c  = (li & 15) * 4;
            const float4 v = *(const float4*)(B + (size_t)(k0 + r) * Nc + col0 + c);
            *(__half2*)&Bs[r][c]     = __floats2half2_rn(v.x, v.y);
            *(__half2*)&Bs[r][c + 2] = __floats2half2_rn(v.z, v.w);
        }
        __syncthreads();

        #pragma unroll
        for (int kk = 0; kk < BK; kk += 16) {
            uint32_t a[2][4];
            #pragma unroll
            for (int mi = 0; mi < 2; ++mi) {
                const int rsel = wm * 32 + mi * 16 + (lane & 15);
                const int csel = kk + (lane >> 4) * 8;
                const uint32_t addr = smem_u32(&As[rsel][csel]);
                asm volatile("ldmatrix.sync.aligned.m8n8.x4.shared.b16 {%0,%1,%2,%3}, [%4];"
                    : "=r"(a[mi][0]), "=r"(a[mi][1]), "=r"(a[mi][2]), "=r"(a[mi][3])
                    : "r"(addr));
            }
            uint32_t bf[4][2];
            #pragma unroll
            for (int nb = 0; nb < 2; ++nb) {
                const int ksel = kk + (lane & 15);
                const int nsel = wn * 32 + nb * 16 + (lane >> 4) * 8;
                const uint32_t addr = smem_u32(&Bs[ksel][nsel]);
                uint32_t r0, r1, r2, r3;
                asm volatile("ldmatrix.sync.aligned.m8n8.x4.trans.shared.b16 {%0,%1,%2,%3}, [%4];"
                    : "=r"(r0), "=r"(r1), "=r"(r2), "=r"(r3) : "r"(addr));
                bf[nb * 2 + 0][0] = r0; bf[nb * 2 + 0][1] = r1;
                bf[nb * 2 + 1][0] = r2; bf[nb * 2 + 1][1] = r3;
            }
            #pragma unroll
            for (int mi = 0; mi < 2; ++mi)
                #pragma unroll
                for (int nj = 0; nj < 4; ++nj)
                    asm volatile("mma.sync.aligned.m16n8k16.row.col.f32.f16.f16.f32 "
                        "{%0,%1,%2,%3}, {%4,%5,%6,%7}, {%8,%9}, {%0,%1,%2,%3};"
                        : "+f"(acc[mi][nj][0]), "+f"(acc[mi][nj][1]),
                          "+f"(acc[mi][nj][2]), "+f"(acc[mi][nj][3])
                        : "r"(a[mi][0]), "r"(a[mi][1]), "r"(a[mi][2]), "r"(a[mi][3]),
                          "r"(bf[nj][0]), "r"(bf[nj][1]));
        }
        __syncthreads();
    }

    const int g  = lane >> 2;
    const int t4 = lane & 3;
    #pragma unroll
    for (int mi = 0; mi < 2; ++mi) {
        #pragma unroll
        for (int nj = 0; nj < 4; ++nj) {
            const int col = col0 + wn * 32 + nj * 8 + t4 * 2;
            const int ra = row0 + wm * 32 + mi * 16 + g;
            const int rb = ra + 8;
            if (ra < Mr)
                *(__half2*)(C + (size_t)ra * Nc + col) =
                    __floats2half2_rn(acc[mi][nj][0], acc[mi][nj][1]);
            if (rb < Mr)
                *(__half2*)(C + (size_t)rb * Nc + col) =
                    __floats2half2_rn(acc[mi][nj][2], acc[mi][nj][3]);
        }
    }
}

// ===========================================================================
// K2: x@W0 (mma) interleaved with the 4-matrix histogram.
// ===========================================================================
__global__ __launch_bounds__(256)
void fused_gemmx_hist_kernel(const float* __restrict__ x, const float* __restrict__ W0,
                             __half* __restrict__ xw0,
                             const int* __restrict__ r0, int n0,
                             const int* __restrict__ r1, int n1,
                             const int* __restrict__ r2, int n2,
                             const int* __restrict__ r3, int n3)
{
    const int b = blockIdx.x;
    int gid = -1, hb = -1;
    if (b < 2 * HIST_BLOCKS) { if ((b & 1) == 0) gid = b >> 1; else hb = b >> 1; }
    else                     gid = b - HIST_BLOCKS;

    if (gid >= 0) {
        gemm_mma_body<float>(x, W0, xw0, NROWS, HIDC, HIDC, gid & 3, gid >> 2);
    } else {
        const int total = n0 + n1 + n2 + n3;
        const int stride = HIST_BLOCKS * 256;
        for (int e = hb * 256 + threadIdx.x; e < total; e += stride) {
            if (e < n0)                atomicAdd(g_cnt_hht + __ldcs(r0 + e), 1);
            else if (e < n0 + n1)      atomicAdd(g_cnt_h   + __ldcs(r1 + e - n0), 1);
            else if (e < n0 + n1 + n2) atomicAdd(g_cnt_ht  + __ldcs(r2 + e - n0 - n1), 1);
            else                       atomicAdd(g_cnt_hth + __ldcs(r3 + e - n0 - n1 - n2), 1);
        }
    }
}

// ===========================================================================
// Fused rowptr build: per-block scan -> grid barrier -> aux prefix -> apply.
// Zeroes cnt after consumption (resets state for the next graph replay).
// 138 blocks x 1024 threads: all co-resident -> spin barrier is safe.
// ===========================================================================
__global__ __launch_bounds__(1024)
void scan_fused_kernel(int n0, int n1, int n2, int n3)
{
    const int b = blockIdx.x;
    int* cnt; int* rp; int* cur; int* aux; int n; int lb; int nnz;
    if (b < NB_N)              { cnt = g_cnt_hht; rp = g_rp_hht; cur = g_cur_hht; aux = g_aux_hht; n = NROWS; lb = b;                 nnz = n0; }
    else if (b < 2 * NB_N)     { cnt = g_cnt_h;   rp = g_rp_h;   cur = g_cur_h;   aux = g_aux_h;   n = NROWS; lb = b - NB_N;          nnz = n1; }
    else if (b < 2*NB_N+NB_M)  { cnt = g_cnt_ht;  rp = g_rp_ht;  cur = g_cur_ht;  aux = g_aux_ht;  n = MROWS; lb = b - 2*NB_N;        nnz = n2; }
    else                       { cnt = g_cnt_hth; rp = g_rp_hth; cur = g_cur_hth; aux = g_aux_hth; n = MROWS; lb = b - 2*NB_N - NB_M; nnz = n3; }

    __shared__ int s[1024];
    __shared__ int s_off;
    const int tid = threadIdx.x;
    const int i = lb * 1024 + tid;
    const int v = (i < n) ? cnt[i] : 0;
    s[tid] = v;
    __syncthreads();
    for (int off = 1; off < 1024; off <<= 1) {
        int t = (tid >= off) ? s[tid - off] : 0;
        __syncthreads();
        s[tid] += t;
        __syncthreads();
    }
    const int excl = s[tid] - v;           // exclusive within block
    if (tid == 1023) aux[lb] = s[1023];    // block total
    __syncthreads();                       // aux write done before arrival

    // ---- grid-wide barrier (monotonic ticket; no reset needed) ----
    if (tid == 0) {
        __threadfence();
        const unsigned ticket = atomicAdd(&g_bar, 1u);
        const unsigned target = ticket - (ticket % SCAN_BLOCKS) + SCAN_BLOCKS;
        while (*(volatile unsigned*)&g_bar < target) {}
        __threadfence();
        // exclusive prefix of this matrix's aux up to lb
        int off = 0;
        for (int k = 0; k < lb; ++k) off += aux[k];
        s_off = off;
    }
    __syncthreads();

    if (i < n) {
        const int r = excl + s_off;
        rp[i]  = r;
        cur[i] = r;
        cnt[i] = 0;                        // reset for next replay
    }
    if (lb == 0 && tid == 0) rp[n] = nnz;
}

// ===========================================================================
// K6: y@W0 (mma) interleaved 1:1 with scatter.
// ===========================================================================
__global__ __launch_bounds__(256)
void fused_gemmy_scatter_kernel(const float* __restrict__ y, const float* __restrict__ W0,
                                __half* __restrict__ yw0,
                                const int* __restrict__ r0, const int* __restrict__ c0,
                                const float* __restrict__ v0, int n0,
                                const int* __restrict__ r1, const int* __restrict__ c1,
                                const float* __restrict__ v1, int n1,
                                const int* __restrict__ r2, const int* __restrict__ c2,
                                const float* __restrict__ v2, int n2,
                                const int* __restrict__ r3, const int* __restrict__ c3,
                                const float* __restrict__ v3, int n3)
{
    const int b = blockIdx.x;
    int sid;
    if (b < 2 * GYT) {
        if ((b & 1) == 0) {
            const int g = b >> 1;
            gemm_mma_body<float>(y, W0, yw0, MROWS, HIDC, HIDC, g & 3, g >> 2);
            return;
        }
        sid = b >> 1;
    } else {
        sid = GYT + (b - 2 * GYT);
    }

    const int total = n0 + n1 + n2 + n3;
    const int stride = SCAT_BLOCKS * 256;
    for (int e = sid * 256 + threadIdx.x; e < total; e += stride) {
        const int* rows; const int* cols; const float* vals;
        int* cur; int2* pe; int el;
        if (e < n0)                { rows = r0; cols = c0; vals = v0; cur = g_cur_hht; pe = g_pe_hht; el = e; }
        else if (e < n0 + n1)      { rows = r1; cols = c1; vals = v1; cur = g_cur_h;   pe = g_pe_h;   el = e - n0; }
        else if (e < n0 + n1 + n2) { rows = r2; cols = c2; vals = v2; cur = g_cur_ht;  pe = g_pe_ht;  el = e - n0 - n1; }
        else                       { rows = r3; cols = c3; vals = v3; cur = g_cur_hth; pe = g_pe_hth; el = e - n0 - n1 - n2; }
        const int r = __ldcs(rows + el);
        const int pos = atomicAdd(cur + r, 1);
        __stcs(pe + pos, make_int2(__ldcs(cols + el), __float_as_int(__ldcs(vals + el))));
    }
}

// ===========================================================================
// Merged CSR SpMM row bodies, fp16 gather sources, fp32 accumulation.
// Edge stream double-buffered (load batch j0+32 before processing batch j0).
// ===========================================================================
__device__ __forceinline__
void spmm256_row_h(const int* __restrict__ rp, const int2* __restrict__ pe,
                   const __half* __restrict__ src, int row, int lane, float acc[8])
{
    const int s0 = __ldg(rp + row);
    const int s1 = __ldg(rp + row + 1);
    if (s0 >= s1) return;

    int2 e = (s0 + lane < s1) ? __ldcs(pe + s0 + lane) : make_int2(0, 0);
    for (int j0 = s0; j0 < s1; j0 += 32) {
        const int2 ecur = e;
        const int jn = j0 + 32;
        if (jn < s1)
            e = (jn + lane < s1) ? __ldcs(pe + jn + lane) : make_int2(0, 0);
        const int cnt = min(32, s1 - j0);
        for (int t = 0; t < cnt; ++t) {
            const int   ct = __shfl_sync(0xffffffffu, ecur.x, t);
            const float vt = __int_as_float(__shfl_sync(0xffffffffu, ecur.y, t));
            const uint4 u = __ldg((const uint4*)(src + (size_t)ct * HIDC) + lane);
            const __half2* h2 = (const __half2*)&u;
            float2 f;
            f = __half22float2(h2[0]); acc[0] += vt * f.x; acc[1] += vt * f.y;
            f = __half22float2(h2[1]); acc[2] += vt * f.x; acc[3] += vt * f.y;
            f = __half22float2(h2[2]); acc[4] += vt * f.x; acc[5] += vt * f.y;
            f = __half22float2(h2[3]); acc[6] += vt * f.x; acc[7] += vt * f.y;
        }
    }
}

// K=256 merged SpMM over BOTH row spaces; writes leaky(sumA)+leaky(sumB) fp16.
__global__ __launch_bounds__(256)
void spmm256_dual_kernel(const __half* __restrict__ xw0, const __half* __restrict__ yw0,
                         __half* __restrict__ x1, __half* __restrict__ y1)
{
    const int lane = threadIdx.x & 31;
    const int wb   = blockIdx.x * 8 + (threadIdx.x >> 5);

    float a[8] = {}, b[8] = {};
    __half* dst;
    int row;
    if (wb < NROWS) {
        row = wb;
        spmm256_row_h(g_rp_hht, g_pe_hht, xw0, row, lane, a);
        spmm256_row_h(g_rp_h,   g_pe_h,   yw0, row, lane, b);
        dst = x1;
    } else {
        row = wb - NROWS;
        spmm256_row_h(g_rp_ht,  g_pe_ht,  xw0, row, lane, a);
        spmm256_row_h(g_rp_hth, g_pe_hth, yw0, row, lane, b);
        dst = y1;
    }

    __half2 o[4];
    #pragma unroll
    for (int i = 0; i < 4; ++i)
        o[i] = __floats2half2_rn(leaky(a[2*i]) + leaky(b[2*i]),
                                 leaky(a[2*i+1]) + leaky(b[2*i+1]));
    __stcs((uint4*)(dst + (size_t)row * HIDC + lane * 8), *(uint4*)o);
}

__device__ __forceinline__
void spmm64_row_h(const int* __restrict__ rp, const int2* __restrict__ pe,
                  const __half* __restrict__ src, int row, int lane16, unsigned gmask,
                  float acc[4])
{
    const int s0 = __ldg(rp + row);
    const int s1 = __ldg(rp + row + 1);
    for (int j0 = s0; j0 < s1; j0 += 16) {
        int2 e = make_int2(0, 0);
        if (j0 + lane16 < s1) e = __ldcs(pe + j0 + lane16);
        const int cnt = min(16, s1 - j0);
        for (int t = 0; t < cnt; ++t) {
            const int   ct = __shfl_sync(gmask, e.x, t, 16);
            const float vt = __int_as_float(__shfl_sync(gmask, e.y, t, 16));
            const uint2 u = __ldg((const uint2*)(src + (size_t)ct * OUTC) + lane16);
            const __half2* h2 = (const __half2*)&u;
            float2 f;
            f = __half22float2(h2[0]); acc[0] += vt * f.x; acc[1] += vt * f.y;
            f = __half22float2(h2[1]); acc[2] += vt * f.x; acc[3] += vt * f.y;
        }
    }
}

// K=64 merged SpMM over both row spaces; writes final fp32 output.
__global__ __launch_bounds__(256)
void spmm64_dual_kernel(const __half* __restrict__ xw1, const __half* __restrict__ yw1,
                        float* __restrict__ out)
{
    const int lane32 = threadIdx.x & 31;
    const int lane16 = threadIdx.x & 15;
    const unsigned gmask = 0xFFFFu << (lane32 & 16);
    const int wb = blockIdx.x * 16 + (threadIdx.x >> 4);

    float a[4] = {}, b[4] = {};
    float* dst;
    int row;
    if (wb < NROWS) {
        row = wb;
        spmm64_row_h(g_rp_hht, g_pe_hht, xw1, row, lane16, gmask, a);
        spmm64_row_h(g_rp_h,   g_pe_h,   yw1, row, lane16, gmask, b);
        dst = out;
    } else {
        row = wb - NROWS;
        spmm64_row_h(g_rp_ht,  g_pe_ht,  xw1, row, lane16, gmask, a);
        spmm64_row_h(g_rp_hth, g_pe_hth, yw1, row, lane16, gmask, b);
        dst = out + (size_t)NROWS * OUTC;
    }

    float o[4];
    #pragma unroll
    for (int i = 0; i < 4; ++i) o[i] = leaky(a[i]) + leaky(b[i]);
    __stcs((float4*)(dst + (size_t)row * OUTC + lane16 * 4), *(float4*)&o[0]);
}

// K8: merged layer-1 GEMM (fp16 A, fp32 W1, fp16 out): [0,391) x1, rest y1.
#define G1X_BLOCKS 391
__global__ __launch_bounds__(256)
void gemm1_dual_kernel(const __half* __restrict__ x1, const __half* __restrict__ y1,
                       const float* __restrict__ W1,
                       __half* __restrict__ xw1, __half* __restrict__ yw1)
{
    const int b = blockIdx.x;
    if (b < G1X_BLOCKS)
        gemm_mma_body<__half>(x1, W1, xw1, NROWS, HIDC, OUTC, 0, b);
    else
        gemm_mma_body<__half>(y1, W1, yw1, MROWS, HIDC, OUTC, 0, b - G1X_BLOCKS);
}

// ---------------------------------------------------------------------------
// Launch
// ---------------------------------------------------------------------------
extern "C" void kernel_launch(void* const* d_in, const int* in_sizes, int n_in,
                              void* d_out, int out_size)
{
    const float* x   = (const float*)d_in[0];
    const float* y   = (const float*)d_in[1];
    const float* W0  = (const float*)d_in[2];
    const float* W1  = (const float*)d_in[3];
    const int*   hht_r = (const int*)d_in[4];
    const int*   hht_c = (const int*)d_in[5];
    const float* hht_v = (const float*)d_in[6];
    const int*   h_r   = (const int*)d_in[7];
    const int*   h_c   = (const int*)d_in[8];
    const float* h_v   = (const float*)d_in[9];
    const int*   ht_r  = (const int*)d_in[10];
    const int*   ht_c  = (const int*)d_in[11];
    const float* ht_v  = (const float*)d_in[12];
    const int*   hth_r = (const int*)d_in[13];
    const int*   hth_c = (const int*)d_in[14];
    const float* hth_v = (const float*)d_in[15];

    const int nnz_hht = in_sizes[4];
    const int nnz_h   = in_sizes[7];
    const int nnz_ht  = in_sizes[10];
    const int nnz_hth = in_sizes[13];

    __half *xw0, *yw0, *x1, *y1, *xw1, *yw1;
    cudaGetSymbolAddress((void**)&xw0, g_xw0);
    cudaGetSymbolAddress((void**)&yw0, g_yw0);
    cudaGetSymbolAddress((void**)&x1,  g_x1);
    cudaGetSymbolAddress((void**)&y1,  g_y1);
    cudaGetSymbolAddress((void**)&xw1, g_xw1);
    cudaGetSymbolAddress((void**)&yw1, g_yw1);

    float* out = (float*)d_out;

    // K1: x@W0 tensor-core GEMM interleaved with the 4-matrix histogram
    //     (cnt zeroed by the previous run's scan_fused; static init covers run 1)
    fused_gemmx_hist_kernel<<<K2_BLOCKS, 256>>>(
        x, W0, xw0,
        hht_r, nnz_hht, h_r, nnz_h, ht_r, nnz_ht, hth_r, nnz_hth);

    // K2: fused rowptr build (scan + grid barrier + apply + cnt reset)
    scan_fused_kernel<<<SCAN_BLOCKS, 1024>>>(nnz_hht, nnz_h, nnz_ht, nnz_hth);

    // K3: y@W0 tensor-core GEMM interleaved with the COO->CSR scatter
    fused_gemmy_scatter_kernel<<<K6_BLOCKS, 256>>>(
        y, W0, yw0,
        hht_r, hht_c, hht_v, nnz_hht,
        h_r,   h_c,   h_v,   nnz_h,
        ht_r,  ht_c,  ht_v,  nnz_ht,
        hth_r, hth_c, hth_v, nnz_hth);

    // K4: layer-0 SpMM over both row spaces (fp16 gathers/out, fp32 accum)
    spmm256_dual_kernel<<<NROWS / 8 + MROWS / 8, 256>>>(xw0, yw0, x1, y1);

    // K5: layer-1 tensor-core GEMM (fp16 in, fp16 out)
    gemm1_dual_kernel<<<G1X_BLOCKS + 157, 256>>>(x1, y1, W1, xw1, yw1);

    // K6: layer-1 SpMM (fp16 gathers), writes final fp32 output
    spmm64_dual_kernel<<<NROWS / 16 + MROWS / 16, 256>>>(xw1, yw1, out);
}